// round 4
// baseline (speedup 1.0000x reference)
#include <cuda_runtime.h>
#include <math.h>

#define TT   2048
#define NH   32
#define NKV  8
#define HS   128
#define FD   64
#define NB   32          // 64-token blocks
#define NC   8           // chunks of 4 blocks
#define EPSF 1e-12f
#define SCALE 0.08838834764831845f  // 1/sqrt(128)

// scratch (device globals: no runtime allocation allowed)
__device__ float g_fq[NH*TT*HS];          // 33.5 MB
__device__ float g_fk[NH*TT*HS];          // 33.5 MB
__device__ float g_S [NH*NB*HS*HS];       // 67 MB  per-block KV states
__device__ float g_z [NH*NB*HS];          // 0.5 MB per-block key sums
__device__ float g_Sb[NH*NC*HS*HS];       // 17 MB  chunk-boundary prefix states

// ---------------------------------------------------------------------------
// Kernel 1: feature map  f = clip(concat(softmax(W^T x), softmax(-W^T x)), EPS)
// grid (32 tiles, 32 heads), 256 thr. which=0 -> g_fq, which=1 -> g_fk
// ---------------------------------------------------------------------------
__global__ void __launch_bounds__(256) featmap_kernel(
    const float* __restrict__ x, int xstride, int rep,
    const float* __restrict__ w, int which)
{
  extern __shared__ float sm[];
  float* sW = sm;                 // [128][65]
  float* sX = sW + 128*65;        // [64][129]
  float* sZ = sX + 64*129;        // [64][65]
  float* sF = sX;                 // reuse after Z computed

  int tile = blockIdx.x, h = blockIdx.y;
  int tid = threadIdx.x;
  int hoff = (h / rep) * HS;
  const float* wh = w + (size_t)h * HS * FD;
  float* outp = which ? g_fk : g_fq;

  for (int i = tid; i < HS*FD; i += 256) {
    int d = i / FD, f = i % FD;
    sW[d*65+f] = wh[i];
  }
  for (int i = tid; i < 64*HS; i += 256) {
    int t = i / HS, d = i % HS;
    sX[t*129+d] = x[(size_t)(tile*64+t)*xstride + hoff + d];
  }
  __syncthreads();

  int ty = tid/16, tx = tid%16;
  int r0 = ty*4, f0 = tx*4;
  float acc[16];
  #pragma unroll
  for (int i=0;i<16;i++) acc[i]=0.f;
  for (int d=0; d<HS; ++d) {
    float a[4], bv[4];
    #pragma unroll
    for (int i=0;i<4;i++) a[i]=sX[(r0+i)*129+d];
    #pragma unroll
    for (int j=0;j<4;j++) bv[j]=sW[d*65+f0+j];
    #pragma unroll
    for (int i=0;i<4;i++)
      #pragma unroll
      for (int j=0;j<4;j++) acc[i*4+j] += a[i]*bv[j];
  }
  #pragma unroll
  for (int i=0;i<4;i++)
    #pragma unroll
    for (int j=0;j<4;j++) sZ[(r0+i)*65+f0+j] = acc[i*4+j];
  __syncthreads();

  if (tid < 64) {
    int r = tid;
    float mx=-1e30f, mn=1e30f;
    for (int f=0; f<FD; ++f) { float z=sZ[r*65+f]; mx=fmaxf(mx,z); mn=fminf(mn,z); }
    float sp=0.f, sn=0.f;
    for (int f=0; f<FD; ++f) { float z=sZ[r*65+f]; sp+=__expf(z-mx); sn+=__expf(mn-z); }
    float rp=1.f/sp, rn=1.f/sn;
    for (int f=0; f<FD; ++f) {
      float z=sZ[r*65+f];
      sF[r*129+f]    = fmaxf(__expf(z-mx)*rp, EPSF);
      sF[r*129+FD+f] = fmaxf(__expf(mn-z)*rn, EPSF);
    }
  }
  __syncthreads();

  for (int i = tid; i < 64*HS; i += 256) {
    int t=i/HS, f=i%HS;
    outp[((size_t)h*TT + tile*64 + t)*HS + f] = sF[t*129+f];
  }
}

// ---------------------------------------------------------------------------
// Kernel 2: per key-block state  S_b[f][d] = sum_t f_k[t][f]*v[t][d],  z_b[f]
// grid (32 blocks, 32 heads), 256 thr
// ---------------------------------------------------------------------------
__global__ void __launch_bounds__(256) blockstate_kernel(const float* __restrict__ value)
{
  extern __shared__ float sm[];
  float* sFK = sm;            // [64][129]
  float* sV  = sm + 64*129;   // [64][129]
  int b = blockIdx.x, h = blockIdx.y;
  int tid = threadIdx.x;
  int kvh = h >> 2;

  for (int i = tid; i < 64*HS; i += 256) {
    int t=i/HS, f=i%HS;
    sFK[t*129+f] = g_fk[((size_t)h*TT + b*64 + t)*HS + f];
    sV [t*129+f] = value[(size_t)(b*64+t)*(NKV*HS) + kvh*HS + f];
  }
  __syncthreads();

  int ty=tid/16, tx=tid%16;
  int f0=ty*8, d0=tx*8;
  float acc[64];
  #pragma unroll
  for (int i=0;i<64;i++) acc[i]=0.f;
  for (int t=0;t<64;++t) {
    float fv[8], vv[8];
    #pragma unroll
    for (int i=0;i<8;i++) fv[i]=sFK[t*129+f0+i];
    #pragma unroll
    for (int j=0;j<8;j++) vv[j]=sV[t*129+d0+j];
    #pragma unroll
    for (int i=0;i<8;i++)
      #pragma unroll
      for (int j=0;j<8;j++) acc[i*8+j]+=fv[i]*vv[j];
  }
  float* Sout = g_S + ((size_t)h*NB + b)*HS*HS;
  #pragma unroll
  for (int i=0;i<8;i++)
    #pragma unroll
    for (int j=0;j<8;j++) Sout[(f0+i)*HS + d0+j] = acc[i*8+j];

  if (tid < HS) {
    float z=0.f;
    for (int t=0;t<64;++t) z += sFK[t*129+tid];
    g_z[((size_t)h*NB+b)*HS + tid] = z;
  }
}

// ---------------------------------------------------------------------------
// Kernel 3: chunk-boundary prefix  g_Sb[h][c] = sum_{j<=4c-2} S_j  (c=1..7)
// grid (64, 32), 256 thr; element-parallel scan
// ---------------------------------------------------------------------------
__global__ void __launch_bounds__(256) prefix_kernel()
{
  int h = blockIdx.y;
  int e = blockIdx.x*256 + threadIdx.x;  // 0..16383
  float acc = 0.f;
  for (int j = 0; j <= 26; ++j) {
    acc += g_S[((size_t)h*NB + j)*HS*HS + e];
    if (((j+2) & 3) == 0) {
      int c = (j+2) >> 2;
      g_Sb[((size_t)h*NC + c)*HS*HS + e] = acc;
    }
  }
}

// ---------------------------------------------------------------------------
// Kernel 4: main attention. grid (8 chunks, 32 heads), 256 thr, ~194 KB smem
// Per chunk keeps running Scum in smem, iterates 4 query blocks.
// ---------------------------------------------------------------------------
__global__ void __launch_bounds__(256) attn_kernel(
    const float* __restrict__ query, const float* __restrict__ key,
    const float* __restrict__ value, const float* __restrict__ wfraw,
    float* __restrict__ out)
{
  extern __shared__ float sm[];
  float* sScum = sm;            // [128][128] running linear state
  float* sA    = sScum + 16384; // [64][129]  Q then f_q
  float* sKV   = sA + 8256;     // [128][129] K^T then V
  float* sSC   = sKV + 16512;   // [64][129]  scores/probs
  float* sZc   = sSC + 8256;    // [128]      running z
  float* sSums = sZc + 128;     // [128]      sum_sm | sum_ln

  int c = blockIdx.x, h = blockIdx.y;
  int tid = threadIdx.x;
  int kvh = h >> 2;
  float wf = 1.f / (1.f + __expf(-wfraw[h]));

  if (c == 0) {
    for (int i=tid;i<16384;i+=256) sScum[i]=0.f;
    if (tid<HS) sZc[tid]=0.f;
  } else {
    const float* Sb = g_Sb + ((size_t)h*NC + c)*HS*HS;
    for (int i=tid;i<16384;i+=256) sScum[i]=Sb[i];
    if (tid<HS) {
      float z=0.f;
      for (int j=0;j<=4*c-2;++j) z += g_z[((size_t)h*NB+j)*HS+tid];
      sZc[tid]=z;
    }
  }
  __syncthreads();

  int ty=tid/16, tx=tid%16;
  int r0=ty*4, c0=tx*8;

  for (int b=c*4; b<c*4+4; ++b) {
    // phase 1: load K window transposed + Q tile
    for (int i=tid;i<HS*HS;i+=256) {
      int col=i/HS, d=i%HS;
      float kv;
      if (col<64) kv = (b==0)?0.f : key[(size_t)((b-1)*64+col)*(NKV*HS) + kvh*HS + d];
      else        kv = key[(size_t)(b*64+col-64)*(NKV*HS) + kvh*HS + d];
      sKV[d*129+col]=kv;   // transposed: [d][col]
    }
    for (int i=tid;i<64*HS;i+=256) {
      int r=i/HS, d=i%HS;
      sA[r*129+d]=query[(size_t)(b*64+r)*(NH*HS) + h*HS + d];
    }
    __syncthreads();

    // phase 2: scores  s[r][col] = q.k * scale
    float acc[32];
    #pragma unroll
    for (int i=0;i<32;i++) acc[i]=0.f;
    for (int d=0; d<HS; ++d) {
      float a[4], kk[8];
      #pragma unroll
      for (int i=0;i<4;i++) a[i]=sA[(r0+i)*129+d];
      #pragma unroll
      for (int j=0;j<8;j++) kk[j]=sKV[d*129+c0+j];
      #pragma unroll
      for (int i=0;i<4;i++)
        #pragma unroll
        for (int j=0;j<8;j++) acc[i*8+j]+=a[i]*kk[j];
    }
    #pragma unroll
    for (int i=0;i<4;i++)
      #pragma unroll
      for (int j=0;j<8;j++) sSC[(r0+i)*129+c0+j]=acc[i*8+j]*SCALE;
    __syncthreads();

    // phase 3: load V (natural layout) + f_q; row threads do masked max/exp
    for (int i=tid;i<HS*HS;i+=256) {
      int row=i/HS, d=i%HS;
      float vv;
      if (row<64) vv = (b==0)?0.f : value[(size_t)((b-1)*64+row)*(NKV*HS)+kvh*HS+d];
      else        vv = value[(size_t)(b*64+row-64)*(NKV*HS)+kvh*HS+d];
      sKV[row*129+d]=vv;
    }
    for (int i=tid;i<64*HS;i+=256) {
      int r=i/HS, f=i%HS;
      sA[r*129+f]=g_fq[((size_t)h*TT + b*64 + r)*HS + f];
    }
    if (tid<64) {
      int r=tid;
      int kstart = (b==0)?64:0;
      int kmax = 64 + r;                 // causal within block b
      float mx=-1e30f;
      for (int k=kstart;k<=kmax;++k) mx=fmaxf(mx,sSC[r*129+k]);
      float s=0.f;
      for (int k=0;k<HS;++k) {
        float p=0.f;
        if (k>=kstart && k<=kmax) p = wf*__expf(sSC[r*129+k]-mx);
        sSC[r*129+k]=p;
        s+=p;
      }
      sSums[r]=s;
    }
    __syncthreads();

    // phase 4: y = p@V + f_q@Scum ; sum_ln = f_q . z_cum
    #pragma unroll
    for (int i=0;i<32;i++) acc[i]=0.f;
    for (int k=0;k<HS;++k) {
      float p[4], vv[8];
      #pragma unroll
      for (int i=0;i<4;i++) p[i]=sSC[(r0+i)*129+k];
      #pragma unroll
      for (int j=0;j<8;j++) vv[j]=sKV[k*129+c0+j];
      #pragma unroll
      for (int i=0;i<4;i++)
        #pragma unroll
        for (int j=0;j<8;j++) acc[i*8+j]+=p[i]*vv[j];
    }
    for (int f=0;f<HS;++f) {
      float fq[4], sv[8];
      #pragma unroll
      for (int i=0;i<4;i++) fq[i]=sA[(r0+i)*129+f];
      #pragma unroll
      for (int j=0;j<8;j++) sv[j]=sScum[f*HS+c0+j];
      #pragma unroll
      for (int i=0;i<4;i++)
        #pragma unroll
        for (int j=0;j<8;j++) acc[i*8+j]+=fq[i]*sv[j];
    }
    if (tid<64) {
      int r=tid;
      float s=0.f;
      for (int f=0;f<HS;++f) s+=sA[r*129+f]*sZc[f];
      sSums[64+r]=s;
    }
    __syncthreads();

    // phase 5: write output + advance running state by S_{b-1}
    #pragma unroll
    for (int i=0;i<4;i++) {
      int r=r0+i;
      float inv = 1.f/(sSums[r]+sSums[64+r]);
      #pragma unroll
      for (int j=0;j<8;j++)
        out[((size_t)h*TT + b*64 + r)*HS + c0 + j] = acc[i*8+j]*inv;
    }
    if (b>=1) {
      const float* Sb = g_S + ((size_t)h*NB + (b-1))*HS*HS;
      for (int i=tid;i<16384;i+=256) sScum[i]+=Sb[i];
      if (tid<HS) sZc[tid]+=g_z[((size_t)h*NB+(b-1))*HS+tid];
    }
    __syncthreads();
  }
}

// ---------------------------------------------------------------------------
extern "C" void kernel_launch(void* const* d_in, const int* in_sizes, int n_in,
                              void* d_out, int out_size)
{
  const float* q   = (const float*)d_in[0];
  const float* k   = (const float*)d_in[1];
  const float* v   = (const float*)d_in[2];
  const float* fqw = (const float*)d_in[3];
  const float* fkw = (const float*)d_in[4];
  const float* wfr = (const float*)d_in[5];
  float* out = (float*)d_out;

  cudaFuncSetAttribute(featmap_kernel,   cudaFuncAttributeMaxDynamicSharedMemorySize, 82944);
  cudaFuncSetAttribute(blockstate_kernel,cudaFuncAttributeMaxDynamicSharedMemorySize, 66048);
  cudaFuncSetAttribute(attn_kernel,      cudaFuncAttributeMaxDynamicSharedMemorySize, 198656);

  featmap_kernel<<<dim3(32,32),256,82944>>>(q, NH*HS, 1, fqw, 0);
  featmap_kernel<<<dim3(32,32),256,82944>>>(k, NKV*HS, 4, fkw, 1);
  blockstate_kernel<<<dim3(32,32),256,66048>>>(v);
  prefix_kernel<<<dim3(64,32),256>>>();
  attn_kernel<<<dim3(8,32),256,198656>>>(q, k, v, wfr, out);
}

// round 5
// speedup vs baseline: 1.5490x; 1.5490x over previous
#include <cuda_runtime.h>
#include <math.h>

#define TT   2048
#define NH   32
#define NKV  8
#define HS   128
#define FD   64
#define NB   32          // 64-token blocks
#define EPSF 1e-12f
#define SCALE 0.08838834764831845f  // 1/sqrt(128)

// scratch (device globals: no runtime allocation allowed)
__device__ float g_fq[NH*TT*HS];          // 33.5 MB
__device__ float g_S [NH*NB*HS*HS];       // 67 MB  per-block KV states
__device__ float g_z [NH*NB*HS];          // 0.5 MB per-block key sums
__device__ float g_P [NH*NB*HS*HS];       // 67 MB  per-block prefix states (blocks <= b-2)
__device__ float g_zp[NH*NB*HS];          // 0.5 MB per-block prefix key sums

// ---------------------------------------------------------------------------
// Kernel 1: feature map for Q.  f = clip(concat(softmax(Wx), softmax(-Wx)), EPS)
// grid (32 tiles, 32 heads), 256 thr.
// ---------------------------------------------------------------------------
__global__ void __launch_bounds__(256) featmap_q_kernel(
    const float* __restrict__ x, const float* __restrict__ w)
{
  extern __shared__ float sm[];
  float* sW = sm;                 // [128][65]
  float* sX = sW + 128*65;        // [64][129]
  float* sZ = sX + 64*129;        // [64][65]
  float* sF = sX;                 // reuse after Z computed

  int tile = blockIdx.x, h = blockIdx.y;
  int tid = threadIdx.x;
  const float* wh = w + (size_t)h * HS * FD;

  for (int i = tid; i < HS*FD; i += 256) {
    int d = i / FD, f = i % FD;
    sW[d*65+f] = wh[i];
  }
  for (int i = tid; i < 64*HS; i += 256) {
    int t = i / HS, d = i % HS;
    sX[t*129+d] = x[(size_t)(tile*64+t)*(NH*HS) + h*HS + d];
  }
  __syncthreads();

  {
    int ty = tid/16, tx = tid%16;
    int r0 = ty*4, f0 = tx*4;
    float acc[16];
    #pragma unroll
    for (int i=0;i<16;i++) acc[i]=0.f;
    #pragma unroll 4
    for (int d=0; d<HS; ++d) {
      float a[4], bv[4];
      #pragma unroll
      for (int i=0;i<4;i++) a[i]=sX[(r0+i)*129+d];
      #pragma unroll
      for (int j=0;j<4;j++) bv[j]=sW[d*65+f0+j];
      #pragma unroll
      for (int i=0;i<4;i++)
        #pragma unroll
        for (int j=0;j<4;j++) acc[i*4+j] += a[i]*bv[j];
    }
    #pragma unroll
    for (int i=0;i<4;i++)
      #pragma unroll
      for (int j=0;j<4;j++) sZ[(r0+i)*65+f0+j] = acc[i*4+j];
  }
  __syncthreads();

  // softmax: 4 threads per row, 16 features each; exps computed ONCE
  {
    int r = tid >> 2, qq = tid & 3, fb = qq*16;
    float mx=-1e30f, mn=1e30f;
    #pragma unroll
    for (int f=fb; f<fb+16; ++f) { float z=sZ[r*65+f]; mx=fmaxf(mx,z); mn=fminf(mn,z); }
    mx = fmaxf(mx, __shfl_xor_sync(0xffffffffu, mx, 1, 4));
    mx = fmaxf(mx, __shfl_xor_sync(0xffffffffu, mx, 2, 4));
    mn = fminf(mn, __shfl_xor_sync(0xffffffffu, mn, 1, 4));
    mn = fminf(mn, __shfl_xor_sync(0xffffffffu, mn, 2, 4));
    float sp=0.f, sn=0.f;
    #pragma unroll
    for (int f=fb; f<fb+16; ++f) {
      float z=sZ[r*65+f];
      float ep=__expf(z-mx), en=__expf(mn-z);
      sF[r*129+f]=ep; sF[r*129+FD+f]=en;
      sp+=ep; sn+=en;
    }
    sp += __shfl_xor_sync(0xffffffffu, sp, 1, 4);
    sp += __shfl_xor_sync(0xffffffffu, sp, 2, 4);
    sn += __shfl_xor_sync(0xffffffffu, sn, 1, 4);
    sn += __shfl_xor_sync(0xffffffffu, sn, 2, 4);
    float rp=1.f/sp, rn=1.f/sn;
    #pragma unroll
    for (int f=fb; f<fb+16; ++f) {
      sF[r*129+f]    = fmaxf(sF[r*129+f]*rp, EPSF);
      sF[r*129+FD+f] = fmaxf(sF[r*129+FD+f]*rn, EPSF);
    }
  }
  __syncthreads();

  for (int i = tid; i < 64*HS; i += 256) {
    int t=i/HS, f=i%HS;
    g_fq[((size_t)h*TT + tile*64 + t)*HS + f] = sF[t*129+f];
  }
}

// ---------------------------------------------------------------------------
// Kernel 2: FUSED feature map for K + block state. One CTA per (block, head).
// Computes f_k in smem, then S_b = f_k^T V_b and z_b, never writing f_k to DRAM.
// ---------------------------------------------------------------------------
__global__ void __launch_bounds__(256) fkstate_kernel(
    const float* __restrict__ key, const float* __restrict__ value,
    const float* __restrict__ w)
{
  extern __shared__ float sm[];
  float* sW = sm;                 // [128][65] = 8320, reused as V [64][129]=8256
  float* sX = sW + 128*65;        // [64][129] k tile, then f_k
  float* sZ = sX + 64*129;        // [64][65]
  float* sV = sW;

  int b = blockIdx.x, h = blockIdx.y;
  int tid = threadIdx.x;
  int kvh = h >> 2;
  const float* wh = w + (size_t)h * HS * FD;

  for (int i = tid; i < HS*FD; i += 256) {
    int d = i / FD, f = i % FD;
    sW[d*65+f] = wh[i];
  }
  for (int i = tid; i < 64*HS; i += 256) {
    int t = i / HS, d = i % HS;
    sX[t*129+d] = key[(size_t)(b*64+t)*(NKV*HS) + kvh*HS + d];
  }
  __syncthreads();

  {
    int ty = tid/16, tx = tid%16;
    int r0 = ty*4, f0 = tx*4;
    float acc[16];
    #pragma unroll
    for (int i=0;i<16;i++) acc[i]=0.f;
    #pragma unroll 4
    for (int d=0; d<HS; ++d) {
      float a[4], bv[4];
      #pragma unroll
      for (int i=0;i<4;i++) a[i]=sX[(r0+i)*129+d];
      #pragma unroll
      for (int j=0;j<4;j++) bv[j]=sW[d*65+f0+j];
      #pragma unroll
      for (int i=0;i<4;i++)
        #pragma unroll
        for (int j=0;j<4;j++) acc[i*4+j] += a[i]*bv[j];
    }
    #pragma unroll
    for (int i=0;i<4;i++)
      #pragma unroll
      for (int j=0;j<4;j++) sZ[(r0+i)*65+f0+j] = acc[i*4+j];
  }
  __syncthreads();   // sW (weights) dead after this point

  // softmax (4 thr/row, single exp pass) + V load in same barrier interval
  {
    int r = tid >> 2, qq = tid & 3, fb = qq*16;
    float mx=-1e30f, mn=1e30f;
    #pragma unroll
    for (int f=fb; f<fb+16; ++f) { float z=sZ[r*65+f]; mx=fmaxf(mx,z); mn=fminf(mn,z); }
    mx = fmaxf(mx, __shfl_xor_sync(0xffffffffu, mx, 1, 4));
    mx = fmaxf(mx, __shfl_xor_sync(0xffffffffu, mx, 2, 4));
    mn = fminf(mn, __shfl_xor_sync(0xffffffffu, mn, 1, 4));
    mn = fminf(mn, __shfl_xor_sync(0xffffffffu, mn, 2, 4));
    float sp=0.f, sn=0.f;
    #pragma unroll
    for (int f=fb; f<fb+16; ++f) {
      float z=sZ[r*65+f];
      float ep=__expf(z-mx), en=__expf(mn-z);
      sX[r*129+f]=ep; sX[r*129+FD+f]=en;
      sp+=ep; sn+=en;
    }
    sp += __shfl_xor_sync(0xffffffffu, sp, 1, 4);
    sp += __shfl_xor_sync(0xffffffffu, sp, 2, 4);
    sn += __shfl_xor_sync(0xffffffffu, sn, 1, 4);
    sn += __shfl_xor_sync(0xffffffffu, sn, 2, 4);
    float rp=1.f/sp, rn=1.f/sn;
    #pragma unroll
    for (int f=fb; f<fb+16; ++f) {
      sX[r*129+f]    = fmaxf(sX[r*129+f]*rp, EPSF);
      sX[r*129+FD+f] = fmaxf(sX[r*129+FD+f]*rn, EPSF);
    }
  }
  for (int i = tid; i < 64*HS; i += 256) {
    int t=i/HS, d=i%HS;
    sV[t*129+d] = value[(size_t)(b*64+t)*(NKV*HS) + kvh*HS + d];
  }
  __syncthreads();

  // S_b[f][d] = sum_t f_k[t][f] * V[t][d]   (8x8 per-thread tile)
  {
    int ty=tid/16, tx=tid%16;
    int f0=ty*8, d0=tx*8;
    float acc[64];
    #pragma unroll
    for (int i=0;i<64;i++) acc[i]=0.f;
    #pragma unroll 4
    for (int t=0;t<64;++t) {
      float fv[8], vv[8];
      #pragma unroll
      for (int i=0;i<8;i++) fv[i]=sX[t*129+f0+i];
      #pragma unroll
      for (int j=0;j<8;j++) vv[j]=sV[t*129+d0+j];
      #pragma unroll
      for (int i=0;i<8;i++)
        #pragma unroll
        for (int j=0;j<8;j++) acc[i*8+j]+=fv[i]*vv[j];
    }
    float* Sout = g_S + ((size_t)h*NB + b)*HS*HS;
    #pragma unroll
    for (int i=0;i<8;i++)
      #pragma unroll
      for (int j=0;j<8;j++) Sout[(f0+i)*HS + d0+j] = acc[i*8+j];
  }
  if (tid < HS) {
    float z=0.f;
    #pragma unroll 4
    for (int t=0;t<64;++t) z += sX[t*129+tid];
    g_z[((size_t)h*NB+b)*HS + tid] = z;
  }
}

// ---------------------------------------------------------------------------
// Kernel 3: per-block prefix states  g_P[h][b] = sum_{j<=b-2} S_j  (b=2..31)
// and g_zp likewise. grid (64, 32), 256 thr; element-parallel scan.
// ---------------------------------------------------------------------------
__global__ void __launch_bounds__(256) prefix_kernel()
{
  int h = blockIdx.y;
  int e = blockIdx.x*256 + threadIdx.x;  // 0..16383
  float acc = 0.f;
  for (int j = 0; j <= NB-3; ++j) {
    acc += g_S[((size_t)h*NB + j)*HS*HS + e];
    g_P[((size_t)h*NB + j+2)*HS*HS + e] = acc;
  }
  if (blockIdx.x == 0 && threadIdx.x < HS) {
    float az = 0.f;
    for (int j = 0; j <= NB-3; ++j) {
      az += g_z[((size_t)h*NB + j)*HS + threadIdx.x];
      g_zp[((size_t)h*NB + j+2)*HS + threadIdx.x] = az;
    }
  }
}

// ---------------------------------------------------------------------------
// Kernel 4: main attention. One CTA per (block, head): grid (32,32)=1024 CTAs,
// 256 thr, ~100 KB smem -> 2 CTAs/SM. Register softmax via width-16 shuffles.
// ---------------------------------------------------------------------------
__global__ void __launch_bounds__(256,2) attn_kernel(
    const float* __restrict__ query, const float* __restrict__ key,
    const float* __restrict__ value, const float* __restrict__ wfraw,
    float* __restrict__ out)
{
  extern __shared__ float sm[];
  float* sBig  = sm;            // [128][129]  P, then K^T, then V
  float* sA    = sBig + 16512;  // [64][129]   f_q, then Q, then probs
  float* sZp   = sA + 8256;     // [128]
  float* sSums = sZp + 128;     // [128]  sum_sm | sum_ln

  int b = blockIdx.x, h = blockIdx.y;
  int tid = threadIdx.x;
  int kvh = h >> 2;
  float wf = 1.f / (1.f + __expf(-wfraw[h]));

  int ty=tid/16, tx=tid%16;
  int r0=ty*4, c0=tx*8;

  float acc[32];
  #pragma unroll
  for (int i=0;i<32;i++) acc[i]=0.f;

  // ---- linear prefix phase: y_lin = f_q @ P_b, sum_ln = f_q . zp_b ----
  if (b >= 2) {
    const float* P = g_P + ((size_t)h*NB + b)*HS*HS;
    for (int i=tid;i<HS*HS;i+=256) sBig[(i/HS)*129 + (i%HS)] = P[i];
    for (int i=tid;i<64*HS;i+=256) {
      int r=i/HS, f=i%HS;
      sA[r*129+f] = g_fq[((size_t)h*TT + b*64 + r)*HS + f];
    }
    if (tid < HS) sZp[tid] = g_zp[((size_t)h*NB + b)*HS + tid];
    __syncthreads();

    #pragma unroll 4
    for (int f=0; f<HS; ++f) {
      float a[4], pv[8];
      #pragma unroll
      for (int i=0;i<4;i++) a[i]=sA[(r0+i)*129+f];
      #pragma unroll
      for (int j=0;j<8;j++) pv[j]=sBig[f*129+c0+j];
      #pragma unroll
      for (int i=0;i<4;i++)
        #pragma unroll
        for (int j=0;j<8;j++) acc[i*8+j]+=a[i]*pv[j];
    }
    if (tid < 64) {
      float s=0.f;
      #pragma unroll 4
      for (int f=0;f<HS;++f) s += sA[tid*129+f]*sZp[f];
      sSums[64+tid]=s;
    }
    __syncthreads();
  } else {
    if (tid < 64) sSums[64+tid]=0.f;
  }

  // ---- load Q and K^T (cols 0..63 = block b-1, 64..127 = block b) ----
  for (int i=tid;i<HS*HS;i+=256) {
    int col=i/HS, d=i%HS;
    float kv;
    if (col<64) kv = (b==0)?0.f : key[(size_t)((b-1)*64+col)*(NKV*HS) + kvh*HS + d];
    else        kv = key[(size_t)(b*64+col-64)*(NKV*HS) + kvh*HS + d];
    sBig[d*129+col]=kv;
  }
  for (int i=tid;i<64*HS;i+=256) {
    int r=i/HS, d=i%HS;
    sA[r*129+d]=query[(size_t)(b*64+r)*(NH*HS) + h*HS + d];
  }
  __syncthreads();

  // ---- scores into registers ----
  float sc[32];
  #pragma unroll
  for (int i=0;i<32;i++) sc[i]=0.f;
  #pragma unroll 4
  for (int d=0; d<HS; ++d) {
    float a[4], kk[8];
    #pragma unroll
    for (int i=0;i<4;i++) a[i]=sA[(r0+i)*129+d];
    #pragma unroll
    for (int j=0;j<8;j++) kk[j]=sBig[d*129+c0+j];
    #pragma unroll
    for (int i=0;i<4;i++)
      #pragma unroll
      for (int j=0;j<8;j++) sc[i*8+j]+=a[i]*kk[j];
  }
  __syncthreads();   // Q and K^T fully consumed

  // ---- register softmax: each row spread over 16 lanes (width-16 shuffles) ----
  #pragma unroll
  for (int i=0;i<4;i++) {
    int r = r0 + i;
    float mx = -1e30f;
    #pragma unroll
    for (int j=0;j<8;j++) {
      int col = c0 + j;
      bool ok = (col < 64) ? (b > 0) : ((col - 64) <= r);
      float s = sc[i*8+j]*SCALE;
      sc[i*8+j] = s;
      if (ok) mx = fmaxf(mx, s);
    }
    mx = fmaxf(mx, __shfl_xor_sync(0xffffffffu, mx, 8, 16));
    mx = fmaxf(mx, __shfl_xor_sync(0xffffffffu, mx, 4, 16));
    mx = fmaxf(mx, __shfl_xor_sync(0xffffffffu, mx, 2, 16));
    mx = fmaxf(mx, __shfl_xor_sync(0xffffffffu, mx, 1, 16));
    float sum = 0.f;
    #pragma unroll
    for (int j=0;j<8;j++) {
      int col = c0 + j;
      bool ok = (col < 64) ? (b > 0) : ((col - 64) <= r);
      float p = ok ? wf*__expf(sc[i*8+j]-mx) : 0.f;
      sc[i*8+j] = p;
      sum += p;
    }
    sum += __shfl_xor_sync(0xffffffffu, sum, 8, 16);
    sum += __shfl_xor_sync(0xffffffffu, sum, 4, 16);
    sum += __shfl_xor_sync(0xffffffffu, sum, 2, 16);
    sum += __shfl_xor_sync(0xffffffffu, sum, 1, 16);
    if (tx == 0) sSums[r] = sum;
  }

  // ---- probs -> smem (overwrite Q), V -> sBig (overwrite K^T) ----
  #pragma unroll
  for (int i=0;i<4;i++)
    #pragma unroll
    for (int j=0;j<8;j++) sA[(r0+i)*129+c0+j]=sc[i*8+j];
  for (int i=tid;i<HS*HS;i+=256) {
    int row=i/HS, d=i%HS;
    float vv;
    if (row<64) vv = (b==0)?0.f : value[(size_t)((b-1)*64+row)*(NKV*HS)+kvh*HS+d];
    else        vv = value[(size_t)(b*64+row-64)*(NKV*HS)+kvh*HS+d];
    sBig[row*129+d]=vv;
  }
  __syncthreads();

  // ---- y += p @ V ----
  #pragma unroll 4
  for (int k=0;k<HS;++k) {
    float p[4], vv[8];
    #pragma unroll
    for (int i=0;i<4;i++) p[i]=sA[(r0+i)*129+k];
    #pragma unroll
    for (int j=0;j<8;j++) vv[j]=sBig[k*129+c0+j];
    #pragma unroll
    for (int i=0;i<4;i++)
      #pragma unroll
      for (int j=0;j<8;j++) acc[i*8+j]+=p[i]*vv[j];
  }

  // ---- epilogue ----
  #pragma unroll
  for (int i=0;i<4;i++) {
    int r=r0+i;
    float inv = 1.f/(sSums[r]+sSums[64+r]);
    #pragma unroll
    for (int j=0;j<8;j++)
      out[((size_t)h*TT + b*64 + r)*HS + c0 + j] = acc[i*8+j]*inv;
  }
}

// ---------------------------------------------------------------------------
extern "C" void kernel_launch(void* const* d_in, const int* in_sizes, int n_in,
                              void* d_out, int out_size)
{
  const float* q   = (const float*)d_in[0];
  const float* k   = (const float*)d_in[1];
  const float* v   = (const float*)d_in[2];
  const float* fqw = (const float*)d_in[3];
  const float* fkw = (const float*)d_in[4];
  const float* wfr = (const float*)d_in[5];
  float* out = (float*)d_out;

  cudaFuncSetAttribute(featmap_q_kernel, cudaFuncAttributeMaxDynamicSharedMemorySize, 82944);
  cudaFuncSetAttribute(fkstate_kernel,   cudaFuncAttributeMaxDynamicSharedMemorySize, 82944);
  cudaFuncSetAttribute(attn_kernel,      cudaFuncAttributeMaxDynamicSharedMemorySize, 100096);

  featmap_q_kernel<<<dim3(32,32),256,82944>>>(q, fqw);
  fkstate_kernel  <<<dim3(32,32),256,82944>>>(k, v, fkw);
  prefix_kernel   <<<dim3(64,32),256>>>();
  attn_kernel     <<<dim3(32,32),256,100096>>>(q, k, v, wfr, out);
}

// round 6
// speedup vs baseline: 1.8696x; 1.2070x over previous
#include <cuda_runtime.h>
#include <math.h>

#define TT   2048
#define NH   32
#define NKV  8
#define HS   128
#define FD   64
#define NB   32          // 64-token blocks
#define EPSF 1e-12f
#define SCALE 0.08838834764831845f  // 1/sqrt(128)

#define PA 68    // pad for transposed A tiles [128][68]
#define PBV 132  // pad for B tiles (K^T, P, V, f_k, probs)

// scratch (device globals: no runtime allocation allowed)
__device__ float g_fq[NH*TT*HS];          // 33.5 MB
__device__ float g_S [NH*NB*HS*HS];       // 67 MB  per-block KV states
__device__ float g_z [NH*NB*HS];          // 0.5 MB per-block key sums
__device__ float g_P [NH*NB*HS*HS];       // 67 MB  per-block prefix states
__device__ float g_zp[NH*NB*HS];          // 0.5 MB per-block prefix key sums

// ---------------------------------------------------------------------------
// Kernel 1: feature map for Q.  f = clip(concat(softmax(Wx), softmax(-Wx)), EPS)
// grid (32 tiles, 32 heads), 256 thr.
// ---------------------------------------------------------------------------
__global__ void __launch_bounds__(256) featmap_q_kernel(
    const float* __restrict__ x, const float* __restrict__ w)
{
  extern __shared__ float sm[];
  float* sW  = sm;             // [128][68]
  float* sXT = sW + 128*PA;    // [128][68] x transposed; later sF [64][129]
  float* sZ  = sXT + 128*PA;   // [64][65]
  float* sF  = sXT;

  int tile = blockIdx.x, h = blockIdx.y;
  int tid = threadIdx.x;
  const float* wh = w + (size_t)h * HS * FD;

  for (int i = tid; i < HS*FD; i += 256) {
    int d = i / FD, f = i % FD;
    sW[d*PA+f] = wh[i];
  }
  for (int i = tid; i < 64*HS; i += 256) {
    int t = i >> 7, d = i & 127;
    sXT[d*PA+t] = x[(size_t)(tile*64+t)*(NH*HS) + h*HS + d];
  }
  __syncthreads();

  {
    int ty = tid/16, tx = tid%16;
    int r0 = ty*4, f0 = tx*4;
    float acc[16];
    #pragma unroll
    for (int i=0;i<16;i++) acc[i]=0.f;
    #pragma unroll 4
    for (int d=0; d<HS; ++d) {
      float4 a  = *(const float4*)&sXT[d*PA+r0];
      float4 bv = *(const float4*)&sW [d*PA+f0];
      float av[4] = {a.x,a.y,a.z,a.w};
      float bb[4] = {bv.x,bv.y,bv.z,bv.w};
      #pragma unroll
      for (int i=0;i<4;i++)
        #pragma unroll
        for (int j=0;j<4;j++) acc[i*4+j] += av[i]*bb[j];
    }
    #pragma unroll
    for (int i=0;i<4;i++)
      #pragma unroll
      for (int j=0;j<4;j++) sZ[(r0+i)*65+f0+j] = acc[i*4+j];
  }
  __syncthreads();

  // softmax: 4 threads per row, 16 features each; exps computed once
  {
    int r = tid >> 2, qq = tid & 3, fb = qq*16;
    float mx=-1e30f, mn=1e30f;
    #pragma unroll
    for (int f=fb; f<fb+16; ++f) { float z=sZ[r*65+f]; mx=fmaxf(mx,z); mn=fminf(mn,z); }
    mx = fmaxf(mx, __shfl_xor_sync(0xffffffffu, mx, 1, 4));
    mx = fmaxf(mx, __shfl_xor_sync(0xffffffffu, mx, 2, 4));
    mn = fminf(mn, __shfl_xor_sync(0xffffffffu, mn, 1, 4));
    mn = fminf(mn, __shfl_xor_sync(0xffffffffu, mn, 2, 4));
    float sp=0.f, sn=0.f;
    #pragma unroll
    for (int f=fb; f<fb+16; ++f) {
      float z=sZ[r*65+f];
      float ep=__expf(z-mx), en=__expf(mn-z);
      sF[r*129+f]=ep; sF[r*129+FD+f]=en;
      sp+=ep; sn+=en;
    }
    sp += __shfl_xor_sync(0xffffffffu, sp, 1, 4);
    sp += __shfl_xor_sync(0xffffffffu, sp, 2, 4);
    sn += __shfl_xor_sync(0xffffffffu, sn, 1, 4);
    sn += __shfl_xor_sync(0xffffffffu, sn, 2, 4);
    float rp=1.f/sp, rn=1.f/sn;
    #pragma unroll
    for (int f=fb; f<fb+16; ++f) {
      sF[r*129+f]    = fmaxf(sF[r*129+f]*rp, EPSF);
      sF[r*129+FD+f] = fmaxf(sF[r*129+FD+f]*rn, EPSF);
    }
  }
  __syncthreads();

  for (int i = tid; i < 64*HS; i += 256) {
    int t=i>>7, f=i&127;
    g_fq[((size_t)h*TT + tile*64 + t)*HS + f] = sF[t*129+f];
  }
}

// ---------------------------------------------------------------------------
// Kernel 2: FUSED feature map for K + block state. One CTA per (block, head).
// ---------------------------------------------------------------------------
__global__ void __launch_bounds__(256) fkstate_kernel(
    const float* __restrict__ key, const float* __restrict__ value,
    const float* __restrict__ w)
{
  extern __shared__ float sm[];
  float* sW  = sm;             // [128][68]; later sV [64][132]
  float* sXT = sW + 128*PA;    // [128][68] k transposed; later f_k [64][132]
  float* sZ  = sXT + 128*PA;   // [64][65]
  float* sFK = sXT;
  float* sV  = sW;

  int b = blockIdx.x, h = blockIdx.y;
  int tid = threadIdx.x;
  int kvh = h >> 2;
  const float* wh = w + (size_t)h * HS * FD;

  for (int i = tid; i < HS*FD; i += 256) {
    int d = i / FD, f = i % FD;
    sW[d*PA+f] = wh[i];
  }
  for (int i = tid; i < 64*HS; i += 256) {
    int t = i >> 7, d = i & 127;
    sXT[d*PA+t] = key[(size_t)(b*64+t)*(NKV*HS) + kvh*HS + d];
  }
  __syncthreads();

  {
    int ty = tid/16, tx = tid%16;
    int r0 = ty*4, f0 = tx*4;
    float acc[16];
    #pragma unroll
    for (int i=0;i<16;i++) acc[i]=0.f;
    #pragma unroll 4
    for (int d=0; d<HS; ++d) {
      float4 a  = *(const float4*)&sXT[d*PA+r0];
      float4 bv = *(const float4*)&sW [d*PA+f0];
      float av[4] = {a.x,a.y,a.z,a.w};
      float bb[4] = {bv.x,bv.y,bv.z,bv.w};
      #pragma unroll
      for (int i=0;i<4;i++)
        #pragma unroll
        for (int j=0;j<4;j++) acc[i*4+j] += av[i]*bb[j];
    }
    #pragma unroll
    for (int i=0;i<4;i++)
      #pragma unroll
      for (int j=0;j<4;j++) sZ[(r0+i)*65+f0+j] = acc[i*4+j];
  }
  __syncthreads();   // sW, sXT dead after this point

  // softmax (4 thr/row) writes f_k row-major [64][132]; V load same interval
  {
    int r = tid >> 2, qq = tid & 3, fb = qq*16;
    float mx=-1e30f, mn=1e30f;
    #pragma unroll
    for (int f=fb; f<fb+16; ++f) { float z=sZ[r*65+f]; mx=fmaxf(mx,z); mn=fminf(mn,z); }
    mx = fmaxf(mx, __shfl_xor_sync(0xffffffffu, mx, 1, 4));
    mx = fmaxf(mx, __shfl_xor_sync(0xffffffffu, mx, 2, 4));
    mn = fminf(mn, __shfl_xor_sync(0xffffffffu, mn, 1, 4));
    mn = fminf(mn, __shfl_xor_sync(0xffffffffu, mn, 2, 4));
    float sp=0.f, sn=0.f;
    #pragma unroll
    for (int f=fb; f<fb+16; ++f) {
      float z=sZ[r*65+f];
      float ep=__expf(z-mx), en=__expf(mn-z);
      sFK[r*PBV+f]=ep; sFK[r*PBV+FD+f]=en;
      sp+=ep; sn+=en;
    }
    sp += __shfl_xor_sync(0xffffffffu, sp, 1, 4);
    sp += __shfl_xor_sync(0xffffffffu, sp, 2, 4);
    sn += __shfl_xor_sync(0xffffffffu, sn, 1, 4);
    sn += __shfl_xor_sync(0xffffffffu, sn, 2, 4);
    float rp=1.f/sp, rn=1.f/sn;
    #pragma unroll
    for (int f=fb; f<fb+16; ++f) {
      sFK[r*PBV+f]    = fmaxf(sFK[r*PBV+f]*rp, EPSF);
      sFK[r*PBV+FD+f] = fmaxf(sFK[r*PBV+FD+f]*rn, EPSF);
    }
  }
  for (int i = tid; i < 64*32; i += 256) {
    int t = i >> 5, dg = (i & 31) * 4;
    float4 vv = *(const float4*)&value[(size_t)(b*64+t)*(NKV*HS) + kvh*HS + dg];
    *(float4*)&sV[t*PBV+dg] = vv;
  }
  __syncthreads();

  // S_b[f][d] = sum_t f_k[t][f] * V[t][d]   (8x8 per-thread tile)
  {
    int ty=tid/16, tx=tid%16;
    int f0=ty*8, d0=tx*8;
    float acc[64];
    #pragma unroll
    for (int i=0;i<64;i++) acc[i]=0.f;
    #pragma unroll 4
    for (int t=0;t<64;++t) {
      float4 f0v = *(const float4*)&sFK[t*PBV+f0];
      float4 f1v = *(const float4*)&sFK[t*PBV+f0+4];
      float4 v0v = *(const float4*)&sV [t*PBV+d0];
      float4 v1v = *(const float4*)&sV [t*PBV+d0+4];
      float fv[8] = {f0v.x,f0v.y,f0v.z,f0v.w,f1v.x,f1v.y,f1v.z,f1v.w};
      float vv[8] = {v0v.x,v0v.y,v0v.z,v0v.w,v1v.x,v1v.y,v1v.z,v1v.w};
      #pragma unroll
      for (int i=0;i<8;i++)
        #pragma unroll
        for (int j=0;j<8;j++) acc[i*8+j]+=fv[i]*vv[j];
    }
    float* Sout = g_S + ((size_t)h*NB + b)*HS*HS;
    #pragma unroll
    for (int i=0;i<8;i++) {
      float4 o0 = make_float4(acc[i*8+0],acc[i*8+1],acc[i*8+2],acc[i*8+3]);
      float4 o1 = make_float4(acc[i*8+4],acc[i*8+5],acc[i*8+6],acc[i*8+7]);
      *(float4*)&Sout[(f0+i)*HS + d0]     = o0;
      *(float4*)&Sout[(f0+i)*HS + d0 + 4] = o1;
    }
  }
  if (tid < HS) {
    float z=0.f;
    #pragma unroll 4
    for (int t=0;t<64;++t) z += sFK[t*PBV+tid];
    g_z[((size_t)h*NB+b)*HS + tid] = z;
  }
}

// ---------------------------------------------------------------------------
// Kernel 3: per-block prefix states  g_P[h][b] = sum_{j<=b-2} S_j  (b=2..31)
// ---------------------------------------------------------------------------
__global__ void __launch_bounds__(256) prefix_kernel()
{
  int h = blockIdx.y;
  int e = blockIdx.x*256 + threadIdx.x;  // 0..16383
  float acc = 0.f;
  for (int j = 0; j <= NB-3; ++j) {
    acc += g_S[((size_t)h*NB + j)*HS*HS + e];
    g_P[((size_t)h*NB + j+2)*HS*HS + e] = acc;
  }
  if (blockIdx.x == 0 && threadIdx.x < HS) {
    float az = 0.f;
    for (int j = 0; j <= NB-3; ++j) {
      az += g_z[((size_t)h*NB + j)*HS + threadIdx.x];
      g_zp[((size_t)h*NB + j+2)*HS + threadIdx.x] = az;
    }
  }
}

// ---------------------------------------------------------------------------
// Kernel 4: main attention. One CTA per (block, head): grid (32,32)=1024 CTAs,
// 256 thr, ~101 KB smem -> 2 CTAs/SM. All GEMM operands vectorized LDS.128.
// ---------------------------------------------------------------------------
__global__ void __launch_bounds__(256,2) attn_kernel(
    const float* __restrict__ query, const float* __restrict__ key,
    const float* __restrict__ value, const float* __restrict__ wfraw,
    float* __restrict__ out)
{
  extern __shared__ float sm[];
  float* sBig  = sm;              // [128][132]  P, then K^T, then V
  float* sAT   = sBig + 128*PBV;  // [128][68]   fq^T / Q^T ; later probs [64][132]
  float* sZp   = sAT + 128*PA;    // [128]
  float* sSums = sZp + 128;       // [128]  sum_sm | sum_ln
  float* sP    = sAT;             // probs alias

  int b = blockIdx.x, h = blockIdx.y;
  int tid = threadIdx.x;
  int kvh = h >> 2;
  float wf = 1.f / (1.f + __expf(-wfraw[h]));

  int ty=tid/16, tx=tid%16;
  int r0=ty*4, c0=tx*8;

  float acc[32];
  #pragma unroll
  for (int i=0;i<32;i++) acc[i]=0.f;

  // ---- linear prefix phase: y_lin = f_q @ P_b, sum_ln = f_q . zp_b ----
  if (b >= 2) {
    const float* P = g_P + ((size_t)h*NB + b)*HS*HS;
    for (int i=tid;i<HS*32;i+=256) {
      int e = i*4;
      int row = e >> 7, col = e & 127;
      *(float4*)&sBig[row*PBV+col] = *(const float4*)&P[e];
    }
    for (int i=tid;i<64*HS;i+=256) {
      int r=i>>7, f=i&127;
      sAT[f*PA+r] = g_fq[((size_t)h*TT + b*64)*HS + i];
    }
    if (tid < HS) sZp[tid] = g_zp[((size_t)h*NB + b)*HS + tid];
    __syncthreads();

    #pragma unroll 4
    for (int f=0; f<HS; ++f) {
      float4 a  = *(const float4*)&sAT [f*PA+r0];
      float4 p0 = *(const float4*)&sBig[f*PBV+c0];
      float4 p1 = *(const float4*)&sBig[f*PBV+c0+4];
      float av[4] = {a.x,a.y,a.z,a.w};
      float pv[8] = {p0.x,p0.y,p0.z,p0.w,p1.x,p1.y,p1.z,p1.w};
      #pragma unroll
      for (int i=0;i<4;i++)
        #pragma unroll
        for (int j=0;j<8;j++) acc[i*8+j]+=av[i]*pv[j];
    }
    if (tid < 64) {
      float s=0.f;
      #pragma unroll 4
      for (int f=0;f<HS;++f) s += sAT[f*PA+tid]*sZp[f];
      sSums[64+tid]=s;
    }
    __syncthreads();
  } else {
    if (tid < 64) sSums[64+tid]=0.f;
  }

  // ---- load K^T (cols 0..63 = block b-1, 64..127 = block b) and Q^T ----
  for (int i=tid;i<HS*HS;i+=256) {
    int col=i>>7, d=i&127;
    float kv;
    if (col<64) kv = (b==0)?0.f : key[(size_t)((b-1)*64+col)*(NKV*HS) + kvh*HS + d];
    else        kv = key[(size_t)(b*64+col-64)*(NKV*HS) + kvh*HS + d];
    sBig[d*PBV+col]=kv;
  }
  for (int i=tid;i<64*HS;i+=256) {
    int r=i>>7, d=i&127;
    sAT[d*PA+r]=query[(size_t)(b*64+r)*(NH*HS) + h*HS + d];
  }
  __syncthreads();

  // ---- scores into registers ----
  float sc[32];
  #pragma unroll
  for (int i=0;i<32;i++) sc[i]=0.f;
  #pragma unroll 4
  for (int d=0; d<HS; ++d) {
    float4 a  = *(const float4*)&sAT [d*PA+r0];
    float4 k0 = *(const float4*)&sBig[d*PBV+c0];
    float4 k1 = *(const float4*)&sBig[d*PBV+c0+4];
    float av[4] = {a.x,a.y,a.z,a.w};
    float kk[8] = {k0.x,k0.y,k0.z,k0.w,k1.x,k1.y,k1.z,k1.w};
    #pragma unroll
    for (int i=0;i<4;i++)
      #pragma unroll
      for (int j=0;j<8;j++) sc[i*8+j]+=av[i]*kk[j];
  }
  __syncthreads();   // Q^T and K^T fully consumed

  // ---- register softmax: each row spread over 16 lanes ----
  #pragma unroll
  for (int i=0;i<4;i++) {
    int r = r0 + i;
    float mx = -1e30f;
    #pragma unroll
    for (int j=0;j<8;j++) {
      int col = c0 + j;
      bool ok = (col < 64) ? (b > 0) : ((col - 64) <= r);
      float s = sc[i*8+j]*SCALE;
      sc[i*8+j] = s;
      if (ok) mx = fmaxf(mx, s);
    }
    mx = fmaxf(mx, __shfl_xor_sync(0xffffffffu, mx, 8, 16));
    mx = fmaxf(mx, __shfl_xor_sync(0xffffffffu, mx, 4, 16));
    mx = fmaxf(mx, __shfl_xor_sync(0xffffffffu, mx, 2, 16));
    mx = fmaxf(mx, __shfl_xor_sync(0xffffffffu, mx, 1, 16));
    float sum = 0.f;
    #pragma unroll
    for (int j=0;j<8;j++) {
      int col = c0 + j;
      bool ok = (col < 64) ? (b > 0) : ((col - 64) <= r);
      float p = ok ? wf*__expf(sc[i*8+j]-mx) : 0.f;
      sc[i*8+j] = p;
      sum += p;
    }
    sum += __shfl_xor_sync(0xffffffffu, sum, 8, 16);
    sum += __shfl_xor_sync(0xffffffffu, sum, 4, 16);
    sum += __shfl_xor_sync(0xffffffffu, sum, 2, 16);
    sum += __shfl_xor_sync(0xffffffffu, sum, 1, 16);
    if (tx == 0) sSums[r] = sum;
  }

  // ---- probs -> smem (STS.128), V -> sBig (float4) ----
  #pragma unroll
  for (int i=0;i<4;i++) {
    float4 o0 = make_float4(sc[i*8+0],sc[i*8+1],sc[i*8+2],sc[i*8+3]);
    float4 o1 = make_float4(sc[i*8+4],sc[i*8+5],sc[i*8+6],sc[i*8+7]);
    *(float4*)&sP[(r0+i)*PBV+c0]   = o0;
    *(float4*)&sP[(r0+i)*PBV+c0+4] = o1;
  }
  for (int i=tid;i<HS*32;i+=256) {
    int e = i*4;
    int row=e>>7, dg=e&127;
    float4 vv;
    if (row<64) {
      if (b==0) vv = make_float4(0.f,0.f,0.f,0.f);
      else vv = *(const float4*)&value[(size_t)((b-1)*64+row)*(NKV*HS)+kvh*HS+dg];
    } else {
      vv = *(const float4*)&value[(size_t)(b*64+row-64)*(NKV*HS)+kvh*HS+dg];
    }
    *(float4*)&sBig[row*PBV+dg]=vv;
  }
  __syncthreads();

  // ---- y += p @ V ----
  #pragma unroll 4
  for (int k=0;k<HS;++k) {
    float4 v0 = *(const float4*)&sBig[k*PBV+c0];
    float4 v1 = *(const float4*)&sBig[k*PBV+c0+4];
    float vv[8] = {v0.x,v0.y,v0.z,v0.w,v1.x,v1.y,v1.z,v1.w};
    float p[4];
    #pragma unroll
    for (int i=0;i<4;i++) p[i]=sP[(r0+i)*PBV+k];
    #pragma unroll
    for (int i=0;i<4;i++)
      #pragma unroll
      for (int j=0;j<8;j++) acc[i*8+j]+=p[i]*vv[j];
  }

  // ---- epilogue ----
  #pragma unroll
  for (int i=0;i<4;i++) {
    int r=r0+i;
    float inv = 1.f/(sSums[r]+sSums[64+r]);
    float4 o0 = make_float4(acc[i*8+0]*inv,acc[i*8+1]*inv,acc[i*8+2]*inv,acc[i*8+3]*inv);
    float4 o1 = make_float4(acc[i*8+4]*inv,acc[i*8+5]*inv,acc[i*8+6]*inv,acc[i*8+7]*inv);
    *(float4*)&out[((size_t)h*TT + b*64 + r)*HS + c0]     = o0;
    *(float4*)&out[((size_t)h*TT + b*64 + r)*HS + c0 + 4] = o1;
  }
}

// ---------------------------------------------------------------------------
extern "C" void kernel_launch(void* const* d_in, const int* in_sizes, int n_in,
                              void* d_out, int out_size)
{
  const float* q   = (const float*)d_in[0];
  const float* k   = (const float*)d_in[1];
  const float* v   = (const float*)d_in[2];
  const float* fqw = (const float*)d_in[3];
  const float* fkw = (const float*)d_in[4];
  const float* wfr = (const float*)d_in[5];
  float* out = (float*)d_out;

  // smem: featmap/fkstate = (128*68 + 128*68 + 64*65)*4 = 86272 B
  // attn = (128*132 + 128*68 + 256)*4 = 103424 B
  cudaFuncSetAttribute(featmap_q_kernel, cudaFuncAttributeMaxDynamicSharedMemorySize, 86272);
  cudaFuncSetAttribute(fkstate_kernel,   cudaFuncAttributeMaxDynamicSharedMemorySize, 86272);
  cudaFuncSetAttribute(attn_kernel,      cudaFuncAttributeMaxDynamicSharedMemorySize, 103424);

  featmap_q_kernel<<<dim3(32,32),256,86272>>>(q, fqw);
  fkstate_kernel  <<<dim3(32,32),256,86272>>>(k, v, fkw);
  prefix_kernel   <<<dim3(64,32),256>>>();
  attn_kernel     <<<dim3(32,32),256,103424>>>(q, k, v, wfr, out);
}

// round 8
// speedup vs baseline: 1.9843x; 1.0614x over previous
#include <cuda_runtime.h>
#include <math.h>

#define TT   2048
#define NH   32
#define NKV  8
#define HS   128
#define FD   64
#define NB   32          // 64-token blocks
#define EPSF 1e-12f
#define SCALE 0.08838834764831845f  // 1/sqrt(128)

#define PA 68    // pad for transposed A tiles [128][68]
#define PBV 132  // pad for B tiles (K^T, P, V, f_k, probs)

// scratch (device globals: no runtime allocation allowed)
__device__ float g_fq[NH*TT*HS];          // 33.5 MB
__device__ float g_S [NH*NB*HS*HS];       // 67 MB  per-block KV states
__device__ float g_z [NH*NB*HS];          // 0.5 MB per-block key sums
__device__ float g_P [NH*NB*HS*HS];       // 67 MB  per-block prefix states
__device__ float g_zp[NH*NB*HS];          // 0.5 MB per-block prefix key sums

// ---------------------------------------------------------------------------
// Kernel 1: feature map for Q. grid (32 tiles, 32 heads), 512 thr.
// ---------------------------------------------------------------------------
__global__ void __launch_bounds__(512,2) featmap_q_kernel(
    const float* __restrict__ x, const float* __restrict__ w)
{
  extern __shared__ float sm[];
  float* sW  = sm;             // [128][68]
  float* sXT = sW + 128*PA;    // [128][68] x transposed; later sF [64][129]
  float* sZ  = sXT + 128*PA;   // [64][65]
  float* sF  = sXT;

  int tile = blockIdx.x, h = blockIdx.y;
  int tid = threadIdx.x;
  const float* wh = w + (size_t)h * HS * FD;

  for (int i = tid; i < HS*FD; i += 512) {
    int d = i / FD, f = i % FD;
    sW[d*PA+f] = wh[i];
  }
  for (int i = tid; i < 64*HS; i += 512) {
    int t = i >> 7, d = i & 127;
    sXT[d*PA+t] = x[(size_t)(tile*64+t)*(NH*HS) + h*HS + d];
  }
  __syncthreads();

  // GEMM Z = X W : 64x64 output, 2x4 per thread
  {
    int r0 = (tid >> 4) * 2, f0 = (tid & 15) * 4;
    float acc[8];
    #pragma unroll
    for (int i=0;i<8;i++) acc[i]=0.f;
    #pragma unroll 4
    for (int d=0; d<HS; ++d) {
      float2 a  = *(const float2*)&sXT[d*PA+r0];
      float4 bv = *(const float4*)&sW [d*PA+f0];
      float av[2] = {a.x,a.y};
      float bb[4] = {bv.x,bv.y,bv.z,bv.w};
      #pragma unroll
      for (int i=0;i<2;i++)
        #pragma unroll
        for (int j=0;j<4;j++) acc[i*4+j] += av[i]*bb[j];
    }
    #pragma unroll
    for (int i=0;i<2;i++)
      #pragma unroll
      for (int j=0;j<4;j++) sZ[(r0+i)*65+f0+j] = acc[i*4+j];
  }
  __syncthreads();

  // softmax: 8 threads per row, 8 features each
  {
    int r = tid >> 3, q8 = tid & 7, fb = q8*8;
    float mx=-1e30f, mn=1e30f;
    #pragma unroll
    for (int f=fb; f<fb+8; ++f) { float z=sZ[r*65+f]; mx=fmaxf(mx,z); mn=fminf(mn,z); }
    mx = fmaxf(mx, __shfl_xor_sync(0xffffffffu, mx, 1, 8));
    mx = fmaxf(mx, __shfl_xor_sync(0xffffffffu, mx, 2, 8));
    mx = fmaxf(mx, __shfl_xor_sync(0xffffffffu, mx, 4, 8));
    mn = fminf(mn, __shfl_xor_sync(0xffffffffu, mn, 1, 8));
    mn = fminf(mn, __shfl_xor_sync(0xffffffffu, mn, 2, 8));
    mn = fminf(mn, __shfl_xor_sync(0xffffffffu, mn, 4, 8));
    float sp=0.f, sn=0.f;
    #pragma unroll
    for (int f=fb; f<fb+8; ++f) {
      float z=sZ[r*65+f];
      float ep=__expf(z-mx), en=__expf(mn-z);
      sF[r*129+f]=ep; sF[r*129+FD+f]=en;
      sp+=ep; sn+=en;
    }
    sp += __shfl_xor_sync(0xffffffffu, sp, 1, 8);
    sp += __shfl_xor_sync(0xffffffffu, sp, 2, 8);
    sp += __shfl_xor_sync(0xffffffffu, sp, 4, 8);
    sn += __shfl_xor_sync(0xffffffffu, sn, 1, 8);
    sn += __shfl_xor_sync(0xffffffffu, sn, 2, 8);
    sn += __shfl_xor_sync(0xffffffffu, sn, 4, 8);
    float rp=1.f/sp, rn=1.f/sn;
    #pragma unroll
    for (int f=fb; f<fb+8; ++f) {
      sF[r*129+f]    = fmaxf(sF[r*129+f]*rp, EPSF);
      sF[r*129+FD+f] = fmaxf(sF[r*129+FD+f]*rn, EPSF);
    }
  }
  __syncthreads();

  for (int i = tid; i < 64*HS; i += 512) {
    int t=i>>7, f=i&127;
    g_fq[((size_t)h*TT + tile*64 + t)*HS + f] = sF[t*129+f];
  }
}

// ---------------------------------------------------------------------------
// Kernel 2: FUSED feature map for K + block state. 512 thr.
// ---------------------------------------------------------------------------
__global__ void __launch_bounds__(512,2) fkstate_kernel(
    const float* __restrict__ key, const float* __restrict__ value,
    const float* __restrict__ w)
{
  extern __shared__ float sm[];
  float* sW  = sm;             // [128][68]; later sV [64][132]
  float* sXT = sW + 128*PA;    // [128][68] k transposed; later f_k [64][132]
  float* sZ  = sXT + 128*PA;   // [64][65]
  float* sFK = sXT;
  float* sV  = sW;

  int b = blockIdx.x, h = blockIdx.y;
  int tid = threadIdx.x;
  int kvh = h >> 2;
  const float* wh = w + (size_t)h * HS * FD;

  for (int i = tid; i < HS*FD; i += 512) {
    int d = i / FD, f = i % FD;
    sW[d*PA+f] = wh[i];
  }
  for (int i = tid; i < 64*HS; i += 512) {
    int t = i >> 7, d = i & 127;
    sXT[d*PA+t] = key[(size_t)(b*64+t)*(NKV*HS) + kvh*HS + d];
  }
  __syncthreads();

  {
    int r0 = (tid >> 4) * 2, f0 = (tid & 15) * 4;
    float acc[8];
    #pragma unroll
    for (int i=0;i<8;i++) acc[i]=0.f;
    #pragma unroll 4
    for (int d=0; d<HS; ++d) {
      float2 a  = *(const float2*)&sXT[d*PA+r0];
      float4 bv = *(const float4*)&sW [d*PA+f0];
      float av[2] = {a.x,a.y};
      float bb[4] = {bv.x,bv.y,bv.z,bv.w};
      #pragma unroll
      for (int i=0;i<2;i++)
        #pragma unroll
        for (int j=0;j<4;j++) acc[i*4+j] += av[i]*bb[j];
    }
    #pragma unroll
    for (int i=0;i<2;i++)
      #pragma unroll
      for (int j=0;j<4;j++) sZ[(r0+i)*65+f0+j] = acc[i*4+j];
  }
  __syncthreads();   // sW, sXT dead after this point

  // softmax (8 thr/row) writes f_k row-major [64][132]; V load same interval
  {
    int r = tid >> 3, q8 = tid & 7, fb = q8*8;
    float mx=-1e30f, mn=1e30f;
    #pragma unroll
    for (int f=fb; f<fb+8; ++f) { float z=sZ[r*65+f]; mx=fmaxf(mx,z); mn=fminf(mn,z); }
    mx = fmaxf(mx, __shfl_xor_sync(0xffffffffu, mx, 1, 8));
    mx = fmaxf(mx, __shfl_xor_sync(0xffffffffu, mx, 2, 8));
    mx = fmaxf(mx, __shfl_xor_sync(0xffffffffu, mx, 4, 8));
    mn = fminf(mn, __shfl_xor_sync(0xffffffffu, mn, 1, 8));
    mn = fminf(mn, __shfl_xor_sync(0xffffffffu, mn, 2, 8));
    mn = fminf(mn, __shfl_xor_sync(0xffffffffu, mn, 4, 8));
    float sp=0.f, sn=0.f;
    #pragma unroll
    for (int f=fb; f<fb+8; ++f) {
      float z=sZ[r*65+f];
      float ep=__expf(z-mx), en=__expf(mn-z);
      sFK[r*PBV+f]=ep; sFK[r*PBV+FD+f]=en;
      sp+=ep; sn+=en;
    }
    sp += __shfl_xor_sync(0xffffffffu, sp, 1, 8);
    sp += __shfl_xor_sync(0xffffffffu, sp, 2, 8);
    sp += __shfl_xor_sync(0xffffffffu, sp, 4, 8);
    sn += __shfl_xor_sync(0xffffffffu, sn, 1, 8);
    sn += __shfl_xor_sync(0xffffffffu, sn, 2, 8);
    sn += __shfl_xor_sync(0xffffffffu, sn, 4, 8);
    float rp=1.f/sp, rn=1.f/sn;
    #pragma unroll
    for (int f=fb; f<fb+8; ++f) {
      sFK[r*PBV+f]    = fmaxf(sFK[r*PBV+f]*rp, EPSF);
      sFK[r*PBV+FD+f] = fmaxf(sFK[r*PBV+FD+f]*rn, EPSF);
    }
  }
  for (int i = tid; i < 64*32; i += 512) {
    int t = i >> 5, dg = (i & 31) * 4;
    float4 vv = *(const float4*)&value[(size_t)(b*64+t)*(NKV*HS) + kvh*HS + dg];
    *(float4*)&sV[t*PBV+dg] = vv;
  }
  __syncthreads();

  // S_b[f][d] = sum_t f_k[t][f] * V[t][d]   (4x8 per-thread tile, 512 thr)
  {
    int f0 = (tid >> 4) * 4, d0 = (tid & 15) * 8;
    float acc[32];
    #pragma unroll
    for (int i=0;i<32;i++) acc[i]=0.f;
    #pragma unroll 4
    for (int t=0;t<64;++t) {
      float4 fv4 = *(const float4*)&sFK[t*PBV+f0];
      float4 v0v = *(const float4*)&sV [t*PBV+d0];
      float4 v1v = *(const float4*)&sV [t*PBV+d0+4];
      float fv[4] = {fv4.x,fv4.y,fv4.z,fv4.w};
      float vv[8] = {v0v.x,v0v.y,v0v.z,v0v.w,v1v.x,v1v.y,v1v.z,v1v.w};
      #pragma unroll
      for (int i=0;i<4;i++)
        #pragma unroll
        for (int j=0;j<8;j++) acc[i*8+j]+=fv[i]*vv[j];
    }
    float* Sout = g_S + ((size_t)h*NB + b)*HS*HS;
    #pragma unroll
    for (int i=0;i<4;i++) {
      float4 o0 = make_float4(acc[i*8+0],acc[i*8+1],acc[i*8+2],acc[i*8+3]);
      float4 o1 = make_float4(acc[i*8+4],acc[i*8+5],acc[i*8+6],acc[i*8+7]);
      *(float4*)&Sout[(f0+i)*HS + d0]     = o0;
      *(float4*)&Sout[(f0+i)*HS + d0 + 4] = o1;
    }
  }
  if (tid < HS) {
    float z=0.f;
    #pragma unroll 4
    for (int t=0;t<64;++t) z += sFK[t*PBV+tid];
    g_z[((size_t)h*NB+b)*HS + tid] = z;
  }
}

// ---------------------------------------------------------------------------
// Kernel 3: per-block prefix states  g_P[h][b] = sum_{j<=b-2} S_j  (b=2..31)
// ---------------------------------------------------------------------------
__global__ void __launch_bounds__(256) prefix_kernel()
{
  int h = blockIdx.y;
  int e = blockIdx.x*256 + threadIdx.x;  // 0..16383
  float acc = 0.f;
  for (int j = 0; j <= NB-3; ++j) {
    acc += g_S[((size_t)h*NB + j)*HS*HS + e];
    g_P[((size_t)h*NB + j+2)*HS*HS + e] = acc;
  }
  if (blockIdx.x == 0 && threadIdx.x < HS) {
    float az = 0.f;
    for (int j = 0; j <= NB-3; ++j) {
      az += g_z[((size_t)h*NB + j)*HS + threadIdx.x];
      g_zp[((size_t)h*NB + j+2)*HS + threadIdx.x] = az;
    }
  }
}

// ---------------------------------------------------------------------------
// Kernel 4: main attention. One CTA per (block, head): grid (32,32)=1024 CTAs,
// 512 thr, 4x4 tiles, ~101 KB smem -> 2 CTAs/SM = 32 warps.
// Window attention FIRST, linear prefix GEMM SECOND (one live accumulator).
// ---------------------------------------------------------------------------
__global__ void __launch_bounds__(512,2) attn_kernel(
    const float* __restrict__ query, const float* __restrict__ key,
    const float* __restrict__ value, const float* __restrict__ wfraw,
    float* __restrict__ out)
{
  extern __shared__ float sm[];
  float* sBig  = sm;              // [128][132]  K^T, then V, then P
  float* sAT   = sBig + 128*PBV;  // [128][68]   Q^T, then probs^T, then fq^T
  float* sZp   = sAT + 128*PA;    // [128]
  float* sSums = sZp + 128;       // [128]  sum_sm | sum_ln

  int b = blockIdx.x, h = blockIdx.y;
  int tid = threadIdx.x;
  int kvh = h >> 2;
  float wf = 1.f / (1.f + __expf(-wfraw[h]));

  // 4x4 thread tile: warp ty owns rows ty*4..ty*4+3 entirely
  int ty = tid >> 5, tx = tid & 31;
  int r0 = ty*4, c0 = tx*4;

  // ---- load K^T (cols 0..63 = block b-1, 64..127 = block b) and Q^T ----
  for (int i=tid;i<HS*HS;i+=512) {
    int col=i>>7, d=i&127;
    float kv;
    if (col<64) kv = (b==0)?0.f : key[(size_t)((b-1)*64+col)*(NKV*HS) + kvh*HS + d];
    else        kv = key[(size_t)(b*64+col-64)*(NKV*HS) + kvh*HS + d];
    sBig[d*PBV+col]=kv;
  }
  for (int i=tid;i<64*HS;i+=512) {
    int r=i>>7, d=i&127;
    sAT[d*PA+r]=query[(size_t)(b*64+r)*(NH*HS) + h*HS + d];
  }
  __syncthreads();

  // ---- scores into registers ----
  float sc[16];
  #pragma unroll
  for (int i=0;i<16;i++) sc[i]=0.f;
  #pragma unroll 4
  for (int d=0; d<HS; ++d) {
    float4 a  = *(const float4*)&sAT [d*PA+r0];
    float4 kk = *(const float4*)&sBig[d*PBV+c0];
    float av[4] = {a.x,a.y,a.z,a.w};
    float kv[4] = {kk.x,kk.y,kk.z,kk.w};
    #pragma unroll
    for (int i=0;i<4;i++)
      #pragma unroll
      for (int j=0;j<4;j++) sc[i*4+j]+=av[i]*kv[j];
  }
  __syncthreads();   // Q^T and K^T fully consumed

  // ---- register softmax: row r fully within warp ty (width-32 shuffles) ----
  #pragma unroll
  for (int i=0;i<4;i++) {
    int r = r0 + i;
    float mx = -1e30f;
    #pragma unroll
    for (int j=0;j<4;j++) {
      int col = c0 + j;
      bool ok = (col < 64) ? (b > 0) : ((col - 64) <= r);
      float s = sc[i*4+j]*SCALE;
      sc[i*4+j] = s;
      if (ok) mx = fmaxf(mx, s);
    }
    #pragma unroll
    for (int m=16;m>=1;m>>=1) mx = fmaxf(mx, __shfl_xor_sync(0xffffffffu, mx, m));
    float sum = 0.f;
    #pragma unroll
    for (int j=0;j<4;j++) {
      int col = c0 + j;
      bool ok = (col < 64) ? (b > 0) : ((col - 64) <= r);
      float p = ok ? wf*__expf(sc[i*4+j]-mx) : 0.f;
      sc[i*4+j] = p;
      sum += p;
    }
    #pragma unroll
    for (int m=16;m>=1;m>>=1) sum += __shfl_xor_sync(0xffffffffu, sum, m);
    if (tx == 0) sSums[r] = sum;
  }

  // ---- probs^T -> sAT [k][r] (scalar stores), V -> sBig ----
  #pragma unroll
  for (int i=0;i<4;i++)
    #pragma unroll
    for (int j=0;j<4;j++) sAT[(c0+j)*PA + r0+i] = sc[i*4+j];
  for (int i=tid;i<HS*32;i+=512) {
    int e = i*4;
    int row=e>>7, dg=e&127;
    float4 vv;
    if (row<64) {
      if (b==0) vv = make_float4(0.f,0.f,0.f,0.f);
      else vv = *(const float4*)&value[(size_t)((b-1)*64+row)*(NKV*HS)+kvh*HS+dg];
    } else {
      vv = *(const float4*)&value[(size_t)(b*64+row-64)*(NKV*HS)+kvh*HS+dg];
    }
    *(float4*)&sBig[row*PBV+dg]=vv;
  }
  __syncthreads();

  // ---- y = p @ V ----
  float acc[16];
  #pragma unroll
  for (int i=0;i<16;i++) acc[i]=0.f;
  #pragma unroll 4
  for (int k=0;k<HS;++k) {
    float4 p4 = *(const float4*)&sAT [k*PA+r0];
    float4 v4 = *(const float4*)&sBig[k*PBV+c0];
    float pv[4] = {p4.x,p4.y,p4.z,p4.w};
    float vv[4] = {v4.x,v4.y,v4.z,v4.w};
    #pragma unroll
    for (int i=0;i<4;i++)
      #pragma unroll
      for (int j=0;j<4;j++) acc[i*4+j]+=pv[i]*vv[j];
  }

  // ---- linear prefix phase: y += f_q @ P_b, sum_ln = f_q . zp_b ----
  if (b >= 2) {
    __syncthreads();   // done with probs^T and V
    const float* P = g_P + ((size_t)h*NB + b)*HS*HS;
    for (int i=tid;i<HS*32;i+=512) {
      int e = i*4;
      int row = e >> 7, col = e & 127;
      *(float4*)&sBig[row*PBV+col] = *(const float4*)&P[e];
    }
    for (int i=tid;i<64*HS;i+=512) {
      int r=i>>7, f=i&127;
      sAT[f*PA+r] = g_fq[((size_t)h*TT + b*64)*HS + i];
    }
    if (tid < HS) sZp[tid] = g_zp[((size_t)h*NB + b)*HS + tid];
    __syncthreads();

    #pragma unroll 4
    for (int f=0; f<HS; ++f) {
      float4 a  = *(const float4*)&sAT [f*PA+r0];
      float4 p4 = *(const float4*)&sBig[f*PBV+c0];
      float av[4] = {a.x,a.y,a.z,a.w};
      float pv[4] = {p4.x,p4.y,p4.z,p4.w};
      #pragma unroll
      for (int i=0;i<4;i++)
        #pragma unroll
        for (int j=0;j<4;j++) acc[i*4+j]+=av[i]*pv[j];
    }
    if (tid < 64) {
      float s=0.f;
      #pragma unroll 4
      for (int f=0;f<HS;++f) s += sAT[f*PA+tid]*sZp[f];
      sSums[64+tid]=s;
    }
  } else {
    if (tid < 64) sSums[64+tid]=0.f;
  }
  __syncthreads();

  // ---- epilogue ----
  #pragma unroll
  for (int i=0;i<4;i++) {
    int r=r0+i;
    float inv = 1.f/(sSums[r]+sSums[64+r]);
    float4 o = make_float4(acc[i*4+0]*inv,acc[i*4+1]*inv,acc[i*4+2]*inv,acc[i*4+3]*inv);
    *(float4*)&out[((size_t)h*TT + b*64 + r)*HS + c0] = o;
  }
}

// ---------------------------------------------------------------------------
extern "C" void kernel_launch(void* const* d_in, const int* in_sizes, int n_in,
                              void* d_out, int out_size)
{
  const float* q   = (const float*)d_in[0];
  const float* k   = (const float*)d_in[1];
  const float* v   = (const float*)d_in[2];
  const float* fqw = (const float*)d_in[3];
  const float* fkw = (const float*)d_in[4];
  const float* wfr = (const float*)d_in[5];
  float* out = (float*)d_out;

  // smem: featmap/fkstate = (128*68 + 128*68 + 64*65)*4 = 86272 B
  // attn = (128*132 + 128*68 + 256)*4 = 103424 B
  cudaFuncSetAttribute(featmap_q_kernel, cudaFuncAttributeMaxDynamicSharedMemorySize, 86272);
  cudaFuncSetAttribute(fkstate_kernel,   cudaFuncAttributeMaxDynamicSharedMemorySize, 86272);
  cudaFuncSetAttribute(attn_kernel,      cudaFuncAttributeMaxDynamicSharedMemorySize, 103424);

  featmap_q_kernel<<<dim3(32,32),512,86272>>>(q, fqw);
  fkstate_kernel  <<<dim3(32,32),512,86272>>>(k, v, fkw);
  prefix_kernel   <<<dim3(64,32),256>>>();
  attn_kernel     <<<dim3(32,32),512,103424>>>(q, k, v, wfr, out);
}

// round 11
// speedup vs baseline: 2.1006x; 1.0586x over previous
#include <cuda_runtime.h>
#include <math.h>

#define TT   2048
#define NH   32
#define NKV  8
#define HS   128
#define FD   64
#define NB   32          // 64-token blocks
#define EPSF 1e-12f
#define SCALE 0.08838834764831845f  // 1/sqrt(128)

#define PA 68    // pad for transposed A tiles [128][68]
#define PBV 132  // pad for B tiles in featmap/fkstate
#define PB 132   // pad for attn B half tiles [64][132]

// scratch (device globals: no runtime allocation allowed)
__device__ float g_fq[NH*TT*HS];          // 33.5 MB
__device__ float g_S [NH*NB*HS*HS];       // 67 MB  per-block KV states
__device__ float g_z [NH*NB*HS];          // 0.5 MB per-block key sums
__device__ float g_P [NH*NB*HS*HS];       // 67 MB  per-block prefix states
__device__ float g_zp[NH*NB*HS];          // 0.5 MB per-block prefix key sums

// ---------------------------------------------------------------------------
// Kernel 1: feature map for Q. grid (32 tiles, 32 heads), 512 thr.
// ---------------------------------------------------------------------------
__global__ void __launch_bounds__(512,2) featmap_q_kernel(
    const float* __restrict__ x, const float* __restrict__ w)
{
  extern __shared__ float sm[];
  float* sW  = sm;             // [128][68]
  float* sXT = sW + 128*PA;    // [128][68] x transposed; later sF [64][129]
  float* sZ  = sXT + 128*PA;   // [64][65]
  float* sF  = sXT;

  int tile = blockIdx.x, h = blockIdx.y;
  int tid = threadIdx.x;
  const float* wh = w + (size_t)h * HS * FD;

  for (int i = tid; i < HS*FD; i += 512) {
    int d = i / FD, f = i % FD;
    sW[d*PA+f] = wh[i];
  }
  for (int i = tid; i < 64*HS; i += 512) {
    int t = i >> 7, d = i & 127;
    sXT[d*PA+t] = x[(size_t)(tile*64+t)*(NH*HS) + h*HS + d];
  }
  __syncthreads();

  // GEMM Z = X W : 64x64 output, 2x4 per thread
  {
    int r0 = (tid >> 4) * 2, f0 = (tid & 15) * 4;
    float acc[8];
    #pragma unroll
    for (int i=0;i<8;i++) acc[i]=0.f;
    #pragma unroll 4
    for (int d=0; d<HS; ++d) {
      float2 a  = *(const float2*)&sXT[d*PA+r0];
      float4 bv = *(const float4*)&sW [d*PA+f0];
      float av[2] = {a.x,a.y};
      float bb[4] = {bv.x,bv.y,bv.z,bv.w};
      #pragma unroll
      for (int i=0;i<2;i++)
        #pragma unroll
        for (int j=0;j<4;j++) acc[i*4+j] += av[i]*bb[j];
    }
    #pragma unroll
    for (int i=0;i<2;i++)
      #pragma unroll
      for (int j=0;j<4;j++) sZ[(r0+i)*65+f0+j] = acc[i*4+j];
  }
  __syncthreads();

  // softmax: 8 threads per row, 8 features each
  {
    int r = tid >> 3, q8 = tid & 7, fb = q8*8;
    float mx=-1e30f, mn=1e30f;
    #pragma unroll
    for (int f=fb; f<fb+8; ++f) { float z=sZ[r*65+f]; mx=fmaxf(mx,z); mn=fminf(mn,z); }
    mx = fmaxf(mx, __shfl_xor_sync(0xffffffffu, mx, 1, 8));
    mx = fmaxf(mx, __shfl_xor_sync(0xffffffffu, mx, 2, 8));
    mx = fmaxf(mx, __shfl_xor_sync(0xffffffffu, mx, 4, 8));
    mn = fminf(mn, __shfl_xor_sync(0xffffffffu, mn, 1, 8));
    mn = fminf(mn, __shfl_xor_sync(0xffffffffu, mn, 2, 8));
    mn = fminf(mn, __shfl_xor_sync(0xffffffffu, mn, 4, 8));
    float sp=0.f, sn=0.f;
    #pragma unroll
    for (int f=fb; f<fb+8; ++f) {
      float z=sZ[r*65+f];
      float ep=__expf(z-mx), en=__expf(mn-z);
      sF[r*129+f]=ep; sF[r*129+FD+f]=en;
      sp+=ep; sn+=en;
    }
    sp += __shfl_xor_sync(0xffffffffu, sp, 1, 8);
    sp += __shfl_xor_sync(0xffffffffu, sp, 2, 8);
    sp += __shfl_xor_sync(0xffffffffu, sp, 4, 8);
    sn += __shfl_xor_sync(0xffffffffu, sn, 1, 8);
    sn += __shfl_xor_sync(0xffffffffu, sn, 2, 8);
    sn += __shfl_xor_sync(0xffffffffu, sn, 4, 8);
    float rp=1.f/sp, rn=1.f/sn;
    #pragma unroll
    for (int f=fb; f<fb+8; ++f) {
      sF[r*129+f]    = fmaxf(sF[r*129+f]*rp, EPSF);
      sF[r*129+FD+f] = fmaxf(sF[r*129+FD+f]*rn, EPSF);
    }
  }
  __syncthreads();

  for (int i = tid; i < 64*HS; i += 512) {
    int t=i>>7, f=i&127;
    g_fq[((size_t)h*TT + tile*64 + t)*HS + f] = sF[t*129+f];
  }
}

// ---------------------------------------------------------------------------
// Kernel 2: FUSED feature map for K + block state. 512 thr.
// ---------------------------------------------------------------------------
__global__ void __launch_bounds__(512,2) fkstate_kernel(
    const float* __restrict__ key, const float* __restrict__ value,
    const float* __restrict__ w)
{
  extern __shared__ float sm[];
  float* sW  = sm;             // [128][68]; later sV [64][132]
  float* sXT = sW + 128*PA;    // [128][68] k transposed; later f_k [64][132]
  float* sZ  = sXT + 128*PA;   // [64][65]
  float* sFK = sXT;
  float* sV  = sW;

  int b = blockIdx.x, h = blockIdx.y;
  int tid = threadIdx.x;
  int kvh = h >> 2;
  const float* wh = w + (size_t)h * HS * FD;

  for (int i = tid; i < HS*FD; i += 512) {
    int d = i / FD, f = i % FD;
    sW[d*PA+f] = wh[i];
  }
  for (int i = tid; i < 64*HS; i += 512) {
    int t = i >> 7, d = i & 127;
    sXT[d*PA+t] = key[(size_t)(b*64+t)*(NKV*HS) + kvh*HS + d];
  }
  __syncthreads();

  {
    int r0 = (tid >> 4) * 2, f0 = (tid & 15) * 4;
    float acc[8];
    #pragma unroll
    for (int i=0;i<8;i++) acc[i]=0.f;
    #pragma unroll 4
    for (int d=0; d<HS; ++d) {
      float2 a  = *(const float2*)&sXT[d*PA+r0];
      float4 bv = *(const float4*)&sW [d*PA+f0];
      float av[2] = {a.x,a.y};
      float bb[4] = {bv.x,bv.y,bv.z,bv.w};
      #pragma unroll
      for (int i=0;i<2;i++)
        #pragma unroll
        for (int j=0;j<4;j++) acc[i*4+j] += av[i]*bb[j];
    }
    #pragma unroll
    for (int i=0;i<2;i++)
      #pragma unroll
      for (int j=0;j<4;j++) sZ[(r0+i)*65+f0+j] = acc[i*4+j];
  }
  __syncthreads();   // sW, sXT dead after this point

  // softmax (8 thr/row) writes f_k row-major [64][132]; V load same interval
  {
    int r = tid >> 3, q8 = tid & 7, fb = q8*8;
    float mx=-1e30f, mn=1e30f;
    #pragma unroll
    for (int f=fb; f<fb+8; ++f) { float z=sZ[r*65+f]; mx=fmaxf(mx,z); mn=fminf(mn,z); }
    mx = fmaxf(mx, __shfl_xor_sync(0xffffffffu, mx, 1, 8));
    mx = fmaxf(mx, __shfl_xor_sync(0xffffffffu, mx, 2, 8));
    mx = fmaxf(mx, __shfl_xor_sync(0xffffffffu, mx, 4, 8));
    mn = fminf(mn, __shfl_xor_sync(0xffffffffu, mn, 1, 8));
    mn = fminf(mn, __shfl_xor_sync(0xffffffffu, mn, 2, 8));
    mn = fminf(mn, __shfl_xor_sync(0xffffffffu, mn, 4, 8));
    float sp=0.f, sn=0.f;
    #pragma unroll
    for (int f=fb; f<fb+8; ++f) {
      float z=sZ[r*65+f];
      float ep=__expf(z-mx), en=__expf(mn-z);
      sFK[r*PBV+f]=ep; sFK[r*PBV+FD+f]=en;
      sp+=ep; sn+=en;
    }
    sp += __shfl_xor_sync(0xffffffffu, sp, 1, 8);
    sp += __shfl_xor_sync(0xffffffffu, sp, 2, 8);
    sp += __shfl_xor_sync(0xffffffffu, sp, 4, 8);
    sn += __shfl_xor_sync(0xffffffffu, sn, 1, 8);
    sn += __shfl_xor_sync(0xffffffffu, sn, 2, 8);
    sn += __shfl_xor_sync(0xffffffffu, sn, 4, 8);
    float rp=1.f/sp, rn=1.f/sn;
    #pragma unroll
    for (int f=fb; f<fb+8; ++f) {
      sFK[r*PBV+f]    = fmaxf(sFK[r*PBV+f]*rp, EPSF);
      sFK[r*PBV+FD+f] = fmaxf(sFK[r*PBV+FD+f]*rn, EPSF);
    }
  }
  for (int i = tid; i < 64*32; i += 512) {
    int t = i >> 5, dg = (i & 31) * 4;
    float4 vv = *(const float4*)&value[(size_t)(b*64+t)*(NKV*HS) + kvh*HS + dg];
    *(float4*)&sV[t*PBV+dg] = vv;
  }
  __syncthreads();

  // S_b[f][d] = sum_t f_k[t][f] * V[t][d]   (4x8 per-thread tile, 512 thr)
  {
    int f0 = (tid >> 4) * 4, d0 = (tid & 15) * 8;
    float acc[32];
    #pragma unroll
    for (int i=0;i<32;i++) acc[i]=0.f;
    #pragma unroll 4
    for (int t=0;t<64;++t) {
      float4 fv4 = *(const float4*)&sFK[t*PBV+f0];
      float4 v0v = *(const float4*)&sV [t*PBV+d0];
      float4 v1v = *(const float4*)&sV [t*PBV+d0+4];
      float fv[4] = {fv4.x,fv4.y,fv4.z,fv4.w};
      float vv[8] = {v0v.x,v0v.y,v0v.z,v0v.w,v1v.x,v1v.y,v1v.z,v1v.w};
      #pragma unroll
      for (int i=0;i<4;i++)
        #pragma unroll
        for (int j=0;j<8;j++) acc[i*8+j]+=fv[i]*vv[j];
    }
    float* Sout = g_S + ((size_t)h*NB + b)*HS*HS;
    #pragma unroll
    for (int i=0;i<4;i++) {
      float4 o0 = make_float4(acc[i*8+0],acc[i*8+1],acc[i*8+2],acc[i*8+3]);
      float4 o1 = make_float4(acc[i*8+4],acc[i*8+5],acc[i*8+6],acc[i*8+7]);
      *(float4*)&Sout[(f0+i)*HS + d0]     = o0;
      *(float4*)&Sout[(f0+i)*HS + d0 + 4] = o1;
    }
  }
  if (tid < HS) {
    float z=0.f;
    #pragma unroll 4
    for (int t=0;t<64;++t) z += sFK[t*PBV+tid];
    g_z[((size_t)h*NB+b)*HS + tid] = z;
  }
}

// ---------------------------------------------------------------------------
// Kernel 3: per-block prefix states  g_P[h][b] = sum_{j<=b-2} S_j  (b=2..31)
// ---------------------------------------------------------------------------
__global__ void __launch_bounds__(256) prefix_kernel()
{
  int h = blockIdx.y;
  int e = blockIdx.x*256 + threadIdx.x;  // 0..16383
  float acc = 0.f;
  for (int j = 0; j <= NB-3; ++j) {
    acc += g_S[((size_t)h*NB + j)*HS*HS + e];
    g_P[((size_t)h*NB + j+2)*HS*HS + e] = acc;
  }
  if (blockIdx.x == 0 && threadIdx.x < HS) {
    float az = 0.f;
    for (int j = 0; j <= NB-3; ++j) {
      az += g_z[((size_t)h*NB + j)*HS + threadIdx.x];
      g_zp[((size_t)h*NB + j+2)*HS + threadIdx.x] = az;
    }
  }
}

// ---------------------------------------------------------------------------
// Kernel 4: main attention, K-split halves. grid (32,32)=1024 CTAs, 512 thr,
// smem 69632 B -> 3 CTAs/SM = 48 warps.
// FIX vs R8: K^T half0 load (L1) and score GEMM G1 are UNCONDITIONAL —
// for b==0 the cols<64 are zero-filled (same pattern as L2); the softmax
// mask discards them. R8 skipped G1 entirely for b==0, losing the d<64
// half of block-0's own scores.
// ---------------------------------------------------------------------------
__global__ void __launch_bounds__(512,3) attn_kernel(
    const float* __restrict__ query, const float* __restrict__ key,
    const float* __restrict__ value, const float* __restrict__ wfraw,
    float* __restrict__ out)
{
  extern __shared__ float sm[];
  float* sA    = sm;              // [128][68]  Q^T -> probs^T -> fq^T
  float* sB    = sA + 128*PA;     // [64][132]  K^T half / V half / P half
  float* sZp   = sB + 64*PB;      // [128]
  float* sSums = sZp + 128;       // [128]  sum_sm | sum_ln

  int b = blockIdx.x, h = blockIdx.y;
  int tid = threadIdx.x;
  int kvh = h >> 2;
  float wf = 1.f / (1.f + __expf(-wfraw[h]));

  int ty = tid >> 5, tx = tid & 31;
  int r0 = ty*4, c0 = tx*4;

  float r16[16];
  #pragma unroll
  for (int i=0;i<16;i++) r16[i]=0.f;
  if (tid < 64) sSums[64+tid] = 0.f;   // default sum_ln (b<2)

  // ---- L1: Q^T full; K^T half0 (cols 0..63=block b-1, 64..127=block b; d 0..63)
  for (int i=tid;i<64*HS;i+=512) {
    int r=i>>7, d=i&127;
    sA[d*PA+r]=query[(size_t)(b*64+r)*(NH*HS) + h*HS + d];
  }
  for (int i=tid;i<64*HS;i+=512) {
    int dl=i&63, col=i>>6;
    float kv;
    if (col<64) kv = (b==0)?0.f : key[(size_t)((b-1)*64+col)*(NKV*HS)+kvh*HS+dl];
    else        kv = key[(size_t)(b*64+(col-64))*(NKV*HS)+kvh*HS+dl];
    sB[dl*PB+col]=kv;
  }
  __syncthreads();

  // ---- G1: scores, d 0..63 (unconditional)
  #pragma unroll 4
  for (int dl=0; dl<64; ++dl) {
    float4 a  = *(const float4*)&sA[dl*PA+r0];
    float4 k4 = *(const float4*)&sB[dl*PB+c0];
    float av[4]={a.x,a.y,a.z,a.w}, kv[4]={k4.x,k4.y,k4.z,k4.w};
    #pragma unroll
    for (int i=0;i<4;i++)
      #pragma unroll
      for (int j=0;j<4;j++) r16[i*4+j]+=av[i]*kv[j];
  }
  __syncthreads();

  // ---- L2: K^T half1 (d 64..127); for b==0 cols<64 are zero
  for (int i=tid;i<64*HS;i+=512) {
    int dl=i&63, col=i>>6;
    float kv;
    if (col<64) kv = (b==0)?0.f : key[(size_t)((b-1)*64+col)*(NKV*HS)+kvh*HS+64+dl];
    else        kv = key[(size_t)(b*64+(col-64))*(NKV*HS)+kvh*HS+64+dl];
    sB[dl*PB+col]=kv;
  }
  __syncthreads();

  // ---- G2: scores, d 64..127
  #pragma unroll 4
  for (int dl=0; dl<64; ++dl) {
    float4 a  = *(const float4*)&sA[(64+dl)*PA+r0];
    float4 k4 = *(const float4*)&sB[dl*PB+c0];
    float av[4]={a.x,a.y,a.z,a.w}, kv[4]={k4.x,k4.y,k4.z,k4.w};
    #pragma unroll
    for (int i=0;i<4;i++)
      #pragma unroll
      for (int j=0;j<4;j++) r16[i*4+j]+=av[i]*kv[j];
  }
  __syncthreads();   // Q^T consumed; sA reusable

  // ---- softmax: row r fully within warp ty (width-32 shuffles)
  #pragma unroll
  for (int i=0;i<4;i++) {
    int r = r0 + i;
    float mx = -1e30f;
    #pragma unroll
    for (int j=0;j<4;j++) {
      int col = c0 + j;
      bool ok = (col < 64) ? (b > 0) : ((col - 64) <= r);
      float s = r16[i*4+j]*SCALE;
      r16[i*4+j] = s;
      if (ok) mx = fmaxf(mx, s);
    }
    #pragma unroll
    for (int m=16;m>=1;m>>=1) mx = fmaxf(mx, __shfl_xor_sync(0xffffffffu, mx, m));
    float sum = 0.f;
    #pragma unroll
    for (int j=0;j<4;j++) {
      int col = c0 + j;
      bool ok = (col < 64) ? (b > 0) : ((col - 64) <= r);
      float p = ok ? wf*__expf(r16[i*4+j]-mx) : 0.f;
      r16[i*4+j] = p;
      sum += p;
    }
    #pragma unroll
    for (int m=16;m>=1;m>>=1) sum += __shfl_xor_sync(0xffffffffu, sum, m);
    if (tx == 0) sSums[r] = sum;
  }

  // ---- L3: probs^T -> sA [k][r]; V half0 -> sB (block b-1)
  #pragma unroll
  for (int i=0;i<4;i++)
    #pragma unroll
    for (int j=0;j<4;j++) sA[(c0+j)*PA + r0+i] = r16[i*4+j];
  if (b > 0) {
    for (int i=tid;i<64*32;i+=512) {
      int t=i>>5, dg=(i&31)*4;
      float4 vv = *(const float4*)&value[(size_t)((b-1)*64+t)*(NKV*HS)+kvh*HS+dg];
      *(float4*)&sB[t*PB+dg]=vv;
    }
  }
  __syncthreads();

  // r16 becomes the y accumulator
  #pragma unroll
  for (int i=0;i<16;i++) r16[i]=0.f;

  // ---- G3: y += probs(k 0..63) @ V(block b-1)  (probs are 0 when b==0)
  if (b > 0) {
    #pragma unroll 4
    for (int k=0;k<64;++k) {
      float4 p4 = *(const float4*)&sA[k*PA+r0];
      float4 v4 = *(const float4*)&sB[k*PB+c0];
      float pv[4]={p4.x,p4.y,p4.z,p4.w}, vv[4]={v4.x,v4.y,v4.z,v4.w};
      #pragma unroll
      for (int i=0;i<4;i++)
        #pragma unroll
        for (int j=0;j<4;j++) r16[i*4+j]+=pv[i]*vv[j];
    }
  }
  __syncthreads();

  // ---- L4: V half1 (block b)
  for (int i=tid;i<64*32;i+=512) {
    int t=i>>5, dg=(i&31)*4;
    float4 vv = *(const float4*)&value[(size_t)(b*64+t)*(NKV*HS)+kvh*HS+dg];
    *(float4*)&sB[t*PB+dg]=vv;
  }
  __syncthreads();

  // ---- G4: y += probs(k 64..127) @ V(block b)
  #pragma unroll 4
  for (int k=0;k<64;++k) {
    float4 p4 = *(const float4*)&sA[(64+k)*PA+r0];
    float4 v4 = *(const float4*)&sB[k*PB+c0];
    float pv[4]={p4.x,p4.y,p4.z,p4.w}, vv[4]={v4.x,v4.y,v4.z,v4.w};
    #pragma unroll
    for (int i=0;i<4;i++)
      #pragma unroll
      for (int j=0;j<4;j++) r16[i*4+j]+=pv[i]*vv[j];
  }

  // ---- linear prefix: y += f_q @ P_b ; sum_ln = f_q . zp_b
  if (b >= 2) {
    __syncthreads();   // probs^T consumed
    const float* P = g_P + ((size_t)h*NB + b)*HS*HS;
    // L5: fq^T full + P half0 (f 0..63) + zp
    for (int i=tid;i<64*HS;i+=512) {
      int r=i>>7, f=i&127;
      sA[f*PA+r] = g_fq[((size_t)h*TT + b*64)*HS + i];
    }
    for (int i=tid;i<64*32;i+=512) {
      int fl=i>>5, dg=(i&31)*4;
      *(float4*)&sB[fl*PB+dg] = *(const float4*)&P[fl*HS+dg];
    }
    if (tid < HS) sZp[tid] = g_zp[((size_t)h*NB + b)*HS + tid];
    __syncthreads();

    // G5: y += fq(f 0..63) @ P half0 ; sum_ln
    #pragma unroll 4
    for (int f=0; f<64; ++f) {
      float4 a  = *(const float4*)&sA[f*PA+r0];
      float4 p4 = *(const float4*)&sB[f*PB+c0];
      float av[4]={a.x,a.y,a.z,a.w}, pv[4]={p4.x,p4.y,p4.z,p4.w};
      #pragma unroll
      for (int i=0;i<4;i++)
        #pragma unroll
        for (int j=0;j<4;j++) r16[i*4+j]+=av[i]*pv[j];
    }
    if (tid < 64) {
      float s=0.f;
      #pragma unroll 4
      for (int f=0;f<HS;++f) s += sA[f*PA+tid]*sZp[f];
      sSums[64+tid]=s;
    }
    __syncthreads();

    // L6: P half1 (f 64..127)
    for (int i=tid;i<64*32;i+=512) {
      int fl=i>>5, dg=(i&31)*4;
      *(float4*)&sB[fl*PB+dg] = *(const float4*)&P[(64+fl)*HS+dg];
    }
    __syncthreads();

    // G6: y += fq(f 64..127) @ P half1
    #pragma unroll 4
    for (int f=0; f<64; ++f) {
      float4 a  = *(const float4*)&sA[(64+f)*PA+r0];
      float4 p4 = *(const float4*)&sB[f*PB+c0];
      float av[4]={a.x,a.y,a.z,a.w}, pv[4]={p4.x,p4.y,p4.z,p4.w};
      #pragma unroll
      for (int i=0;i<4;i++)
        #pragma unroll
        for (int j=0;j<4;j++) r16[i*4+j]+=av[i]*pv[j];
    }
  } else {
    __syncthreads();   // make sSums[64+] (written pre-L1) and sum_sm visible
  }

  // ---- epilogue ----
  #pragma unroll
  for (int i=0;i<4;i++) {
    int r=r0+i;
    float inv = 1.f/(sSums[r]+sSums[64+r]);
    float4 o = make_float4(r16[i*4+0]*inv,r16[i*4+1]*inv,r16[i*4+2]*inv,r16[i*4+3]*inv);
    *(float4*)&out[((size_t)h*TT + b*64 + r)*HS + c0] = o;
  }
}

// ---------------------------------------------------------------------------
extern "C" void kernel_launch(void* const* d_in, const int* in_sizes, int n_in,
                              void* d_out, int out_size)
{
  const float* q   = (const float*)d_in[0];
  const float* k   = (const float*)d_in[1];
  const float* v   = (const float*)d_in[2];
  const float* fqw = (const float*)d_in[3];
  const float* fkw = (const float*)d_in[4];
  const float* wfr = (const float*)d_in[5];
  float* out = (float*)d_out;

  // smem: featmap/fkstate = (128*68 + 128*68 + 64*65)*4 = 86272 B
  // attn = (128*68 + 64*132 + 256)*4 = 69632 B -> 3 CTAs/SM
  cudaFuncSetAttribute(featmap_q_kernel, cudaFuncAttributeMaxDynamicSharedMemorySize, 86272);
  cudaFuncSetAttribute(fkstate_kernel,   cudaFuncAttributeMaxDynamicSharedMemorySize, 86272);
  cudaFuncSetAttribute(attn_kernel,      cudaFuncAttributeMaxDynamicSharedMemorySize, 69632);

  featmap_q_kernel<<<dim3(32,32),512,86272>>>(q, fqw);
  fkstate_kernel  <<<dim3(32,32),512,86272>>>(k, v, fkw);
  prefix_kernel   <<<dim3(64,32),256>>>();
  attn_kernel     <<<dim3(32,32),512,69632>>>(q, k, v, wfr, out);
}

// round 12
// speedup vs baseline: 2.3630x; 1.1249x over previous
#include <cuda_runtime.h>
#include <math.h>

#define TT   2048
#define NH   32
#define NKV  8
#define HS   128
#define FD   64
#define NB   32          // 64-token blocks
#define EPSF 1e-12f
#define SCALE 0.08838834764831845f  // 1/sqrt(128)

#define PA 68    // pad for transposed A tiles [128][68]
#define PF 132   // pad for feature tiles [64][132]
#define PB 132   // pad for attn B half tiles [64][132]

// scratch (device globals: no runtime allocation allowed)
__device__ float g_fq[NH*TT*HS];          // 33.5 MB
__device__ float g_S [NH*NB*HS*HS];       // 67 MB  per-block KV states
__device__ float g_z [NH*NB*HS];          // 0.5 MB per-block key sums
__device__ float g_P [NH*NB*HS*HS];       // 67 MB  per-block prefix states
__device__ float g_zp[NH*NB*HS];          // 0.5 MB per-block prefix key sums

// ---------------------------------------------------------------------------
// Register softmax helper: thread holds z[4] = Z[row][f0..f0+3]; the row's 64
// values live in 16 consecutive lanes (width-16 shuffle domain). Produces the
// clipped feature values for the positive half (p[4]) and negative half (n[4]).
// ---------------------------------------------------------------------------
__device__ __forceinline__ void rowsoftmax16(const float z[4], float p[4], float n[4])
{
  float mx = fmaxf(fmaxf(z[0],z[1]), fmaxf(z[2],z[3]));
  float mn = fminf(fminf(z[0],z[1]), fminf(z[2],z[3]));
  #pragma unroll
  for (int m=1;m<16;m<<=1) {
    mx = fmaxf(mx, __shfl_xor_sync(0xffffffffu, mx, m, 16));
    mn = fminf(mn, __shfl_xor_sync(0xffffffffu, mn, m, 16));
  }
  float sp=0.f, sn=0.f;
  #pragma unroll
  for (int j=0;j<4;j++) {
    p[j]=__expf(z[j]-mx); n[j]=__expf(mn-z[j]);
    sp+=p[j]; sn+=n[j];
  }
  #pragma unroll
  for (int m=1;m<16;m<<=1) {
    sp += __shfl_xor_sync(0xffffffffu, sp, m, 16);
    sn += __shfl_xor_sync(0xffffffffu, sn, m, 16);
  }
  float rp=1.f/sp, rn=1.f/sn;
  #pragma unroll
  for (int j=0;j<4;j++) {
    p[j]=fmaxf(p[j]*rp, EPSF);
    n[j]=fmaxf(n[j]*rn, EPSF);
  }
}

// ---------------------------------------------------------------------------
// Kernel 1: feature map for Q. grid (32 tiles, 32 heads), 512 thr, 3 CTAs/SM.
// Z kept in registers; softmax via width-16 shuffles; no sZ tile.
// ---------------------------------------------------------------------------
__global__ void __launch_bounds__(512,3) featmap_q_kernel(
    const float* __restrict__ x, const float* __restrict__ w)
{
  extern __shared__ float sm[];
  float* sW  = sm;             // [128][68]
  float* sXT = sW + 128*PA;    // [128][68] x transposed; later sF [64][132]
  float* sF  = sXT;

  int tile = blockIdx.x, h = blockIdx.y;
  int tid = threadIdx.x;
  const float* wh = w + (size_t)h * HS * FD;

  for (int i = tid; i < HS*FD; i += 512) {
    int d = i / FD, f = i % FD;
    sW[d*PA+f] = wh[i];
  }
  for (int i = tid; i < 64*HS; i += 512) {
    int t = i >> 7, d = i & 127;
    sXT[d*PA+t] = x[(size_t)(tile*64+t)*(NH*HS) + h*HS + d];
  }
  __syncthreads();

  // GEMM Z = X W : 64x64 output, 2 rows x 4 cols per thread (in registers)
  int r0 = (tid >> 4) * 2, f0 = (tid & 15) * 4;
  float acc[8];
  #pragma unroll
  for (int i=0;i<8;i++) acc[i]=0.f;
  #pragma unroll 4
  for (int d=0; d<HS; ++d) {
    float2 a  = *(const float2*)&sXT[d*PA+r0];
    float4 bv = *(const float4*)&sW [d*PA+f0];
    float av[2] = {a.x,a.y};
    float bb[4] = {bv.x,bv.y,bv.z,bv.w};
    #pragma unroll
    for (int i=0;i<2;i++)
      #pragma unroll
      for (int j=0;j<4;j++) acc[i*4+j] += av[i]*bb[j];
  }
  __syncthreads();   // sXT dead; sF overlays it

  #pragma unroll
  for (int i=0;i<2;i++) {
    float p[4], n[4];
    rowsoftmax16(&acc[i*4], p, n);
    *(float4*)&sF[(r0+i)*PF + f0]      = make_float4(p[0],p[1],p[2],p[3]);
    *(float4*)&sF[(r0+i)*PF + FD + f0] = make_float4(n[0],n[1],n[2],n[3]);
  }
  __syncthreads();

  for (int i = tid; i < 64*32; i += 512) {
    int e = i*4;
    int t = e>>7, f = e&127;
    *(float4*)&g_fq[((size_t)h*TT + tile*64 + t)*HS + f] = *(const float4*)&sF[t*PF+f];
  }
}

// ---------------------------------------------------------------------------
// Kernel 2: FUSED feature map for K + block state. 512 thr, 3 CTAs/SM.
// Register softmax; state GEMM in two 4x4 d-half passes (reg-cap friendly).
// ---------------------------------------------------------------------------
__global__ void __launch_bounds__(512,3) fkstate_kernel(
    const float* __restrict__ key, const float* __restrict__ value,
    const float* __restrict__ w)
{
  extern __shared__ float sm[];
  float* sW  = sm;             // [128][68]; later sV [64][132]
  float* sXT = sW + 128*PA;    // [128][68] k transposed; later sFK [64][132]
  float* sFK = sXT;
  float* sV  = sW;

  int b = blockIdx.x, h = blockIdx.y;
  int tid = threadIdx.x;
  int kvh = h >> 2;
  const float* wh = w + (size_t)h * HS * FD;

  for (int i = tid; i < HS*FD; i += 512) {
    int d = i / FD, f = i % FD;
    sW[d*PA+f] = wh[i];
  }
  for (int i = tid; i < 64*HS; i += 512) {
    int t = i >> 7, d = i & 127;
    sXT[d*PA+t] = key[(size_t)(b*64+t)*(NKV*HS) + kvh*HS + d];
  }
  __syncthreads();

  int r0 = (tid >> 4) * 2, f0q = (tid & 15) * 4;
  {
    float acc[8];
    #pragma unroll
    for (int i=0;i<8;i++) acc[i]=0.f;
    #pragma unroll 4
    for (int d=0; d<HS; ++d) {
      float2 a  = *(const float2*)&sXT[d*PA+r0];
      float4 bv = *(const float4*)&sW [d*PA+f0q];
      float av[2] = {a.x,a.y};
      float bb[4] = {bv.x,bv.y,bv.z,bv.w};
      #pragma unroll
      for (int i=0;i<2;i++)
        #pragma unroll
        for (int j=0;j<4;j++) acc[i*4+j] += av[i]*bb[j];
    }
    __syncthreads();   // sW, sXT dead

    #pragma unroll
    for (int i=0;i<2;i++) {
      float p[4], n[4];
      rowsoftmax16(&acc[i*4], p, n);
      *(float4*)&sFK[(r0+i)*PF + f0q]      = make_float4(p[0],p[1],p[2],p[3]);
      *(float4*)&sFK[(r0+i)*PF + FD + f0q] = make_float4(n[0],n[1],n[2],n[3]);
    }
  }
  // V load into sV (overlays sW) — same barrier interval as softmax writes
  for (int i = tid; i < 64*32; i += 512) {
    int t = i >> 5, dg = (i & 31) * 4;
    float4 vv = *(const float4*)&value[(size_t)(b*64+t)*(NKV*HS) + kvh*HS + dg];
    *(float4*)&sV[t*PF+dg] = vv;
  }
  __syncthreads();

  // S_b[f][d] = sum_t f_k[t][f] * V[t][d]; two passes of 4x4 per thread
  {
    int f0 = (tid >> 4) * 4, d0 = (tid & 15) * 4;
    float* Sout = g_S + ((size_t)h*NB + b)*HS*HS;
    #pragma unroll
    for (int pass=0; pass<2; ++pass) {
      int dp = d0 + pass*64;
      float acc[16];
      #pragma unroll
      for (int i=0;i<16;i++) acc[i]=0.f;
      #pragma unroll 4
      for (int t=0;t<64;++t) {
        float4 a4 = *(const float4*)&sFK[t*PF+f0];
        float4 b4 = *(const float4*)&sV [t*PF+dp];
        float fv[4] = {a4.x,a4.y,a4.z,a4.w};
        float vv[4] = {b4.x,b4.y,b4.z,b4.w};
        #pragma unroll
        for (int i=0;i<4;i++)
          #pragma unroll
          for (int j=0;j<4;j++) acc[i*4+j]+=fv[i]*vv[j];
      }
      #pragma unroll
      for (int i=0;i<4;i++)
        *(float4*)&Sout[(f0+i)*HS + dp] =
          make_float4(acc[i*4+0],acc[i*4+1],acc[i*4+2],acc[i*4+3]);
    }
  }
  if (tid < HS) {
    float z=0.f;
    #pragma unroll 4
    for (int t=0;t<64;++t) z += sFK[t*PF+tid];
    g_z[((size_t)h*NB+b)*HS + tid] = z;
  }
}

// ---------------------------------------------------------------------------
// Kernel 3: per-block prefix states  g_P[h][b] = sum_{j<=b-2} S_j  (b=2..31)
// ---------------------------------------------------------------------------
__global__ void __launch_bounds__(256) prefix_kernel()
{
  int h = blockIdx.y;
  int e = blockIdx.x*256 + threadIdx.x;  // 0..16383
  float acc = 0.f;
  for (int j = 0; j <= NB-3; ++j) {
    acc += g_S[((size_t)h*NB + j)*HS*HS + e];
    g_P[((size_t)h*NB + j+2)*HS*HS + e] = acc;
  }
  if (blockIdx.x == 0 && threadIdx.x < HS) {
    float az = 0.f;
    for (int j = 0; j <= NB-3; ++j) {
      az += g_z[((size_t)h*NB + j)*HS + threadIdx.x];
      g_zp[((size_t)h*NB + j+2)*HS + threadIdx.x] = az;
    }
  }
}

// ---------------------------------------------------------------------------
// Kernel 4: main attention, K-split halves. grid (32,32)=1024 CTAs, 512 thr,
// smem 69632 B -> 3 CTAs/SM = 48 warps.  (unchanged from R10 passing version)
// ---------------------------------------------------------------------------
__global__ void __launch_bounds__(512,3) attn_kernel(
    const float* __restrict__ query, const float* __restrict__ key,
    const float* __restrict__ value, const float* __restrict__ wfraw,
    float* __restrict__ out)
{
  extern __shared__ float sm[];
  float* sA    = sm;              // [128][68]  Q^T -> probs^T -> fq^T
  float* sB    = sA + 128*PA;     // [64][132]  K^T half / V half / P half
  float* sZp   = sB + 64*PB;      // [128]
  float* sSums = sZp + 128;       // [128]  sum_sm | sum_ln

  int b = blockIdx.x, h = blockIdx.y;
  int tid = threadIdx.x;
  int kvh = h >> 2;
  float wf = 1.f / (1.f + __expf(-wfraw[h]));

  int ty = tid >> 5, tx = tid & 31;
  int r0 = ty*4, c0 = tx*4;

  float r16[16];
  #pragma unroll
  for (int i=0;i<16;i++) r16[i]=0.f;
  if (tid < 64) sSums[64+tid] = 0.f;   // default sum_ln (b<2)

  // ---- L1: Q^T full; K^T half0 (cols 0..63=block b-1, 64..127=block b; d 0..63)
  for (int i=tid;i<64*HS;i+=512) {
    int r=i>>7, d=i&127;
    sA[d*PA+r]=query[(size_t)(b*64+r)*(NH*HS) + h*HS + d];
  }
  for (int i=tid;i<64*HS;i+=512) {
    int dl=i&63, col=i>>6;
    float kv;
    if (col<64) kv = (b==0)?0.f : key[(size_t)((b-1)*64+col)*(NKV*HS)+kvh*HS+dl];
    else        kv = key[(size_t)(b*64+(col-64))*(NKV*HS)+kvh*HS+dl];
    sB[dl*PB+col]=kv;
  }
  __syncthreads();

  // ---- G1: scores, d 0..63
  #pragma unroll 4
  for (int dl=0; dl<64; ++dl) {
    float4 a  = *(const float4*)&sA[dl*PA+r0];
    float4 k4 = *(const float4*)&sB[dl*PB+c0];
    float av[4]={a.x,a.y,a.z,a.w}, kv[4]={k4.x,k4.y,k4.z,k4.w};
    #pragma unroll
    for (int i=0;i<4;i++)
      #pragma unroll
      for (int j=0;j<4;j++) r16[i*4+j]+=av[i]*kv[j];
  }
  __syncthreads();

  // ---- L2: K^T half1 (d 64..127); for b==0 cols<64 are zero
  for (int i=tid;i<64*HS;i+=512) {
    int dl=i&63, col=i>>6;
    float kv;
    if (col<64) kv = (b==0)?0.f : key[(size_t)((b-1)*64+col)*(NKV*HS)+kvh*HS+64+dl];
    else        kv = key[(size_t)(b*64+(col-64))*(NKV*HS)+kvh*HS+64+dl];
    sB[dl*PB+col]=kv;
  }
  __syncthreads();

  // ---- G2: scores, d 64..127
  #pragma unroll 4
  for (int dl=0; dl<64; ++dl) {
    float4 a  = *(const float4*)&sA[(64+dl)*PA+r0];
    float4 k4 = *(const float4*)&sB[dl*PB+c0];
    float av[4]={a.x,a.y,a.z,a.w}, kv[4]={k4.x,k4.y,k4.z,k4.w};
    #pragma unroll
    for (int i=0;i<4;i++)
      #pragma unroll
      for (int j=0;j<4;j++) r16[i*4+j]+=av[i]*kv[j];
  }
  __syncthreads();   // Q^T consumed; sA reusable

  // ---- softmax: row r fully within warp ty (width-32 shuffles)
  #pragma unroll
  for (int i=0;i<4;i++) {
    int r = r0 + i;
    float mx = -1e30f;
    #pragma unroll
    for (int j=0;j<4;j++) {
      int col = c0 + j;
      bool ok = (col < 64) ? (b > 0) : ((col - 64) <= r);
      float s = r16[i*4+j]*SCALE;
      r16[i*4+j] = s;
      if (ok) mx = fmaxf(mx, s);
    }
    #pragma unroll
    for (int m=16;m>=1;m>>=1) mx = fmaxf(mx, __shfl_xor_sync(0xffffffffu, mx, m));
    float sum = 0.f;
    #pragma unroll
    for (int j=0;j<4;j++) {
      int col = c0 + j;
      bool ok = (col < 64) ? (b > 0) : ((col - 64) <= r);
      float p = ok ? wf*__expf(r16[i*4+j]-mx) : 0.f;
      r16[i*4+j] = p;
      sum += p;
    }
    #pragma unroll
    for (int m=16;m>=1;m>>=1) sum += __shfl_xor_sync(0xffffffffu, sum, m);
    if (tx == 0) sSums[r] = sum;
  }

  // ---- L3: probs^T -> sA [k][r]; V half0 -> sB (block b-1)
  #pragma unroll
  for (int i=0;i<4;i++)
    #pragma unroll
    for (int j=0;j<4;j++) sA[(c0+j)*PA + r0+i] = r16[i*4+j];
  if (b > 0) {
    for (int i=tid;i<64*32;i+=512) {
      int t=i>>5, dg=(i&31)*4;
      float4 vv = *(const float4*)&value[(size_t)((b-1)*64+t)*(NKV*HS)+kvh*HS+dg];
      *(float4*)&sB[t*PB+dg]=vv;
    }
  }
  __syncthreads();

  // r16 becomes the y accumulator
  #pragma unroll
  for (int i=0;i<16;i++) r16[i]=0.f;

  // ---- G3: y += probs(k 0..63) @ V(block b-1)
  if (b > 0) {
    #pragma unroll 4
    for (int k=0;k<64;++k) {
      float4 p4 = *(const float4*)&sA[k*PA+r0];
      float4 v4 = *(const float4*)&sB[k*PB+c0];
      float pv[4]={p4.x,p4.y,p4.z,p4.w}, vv[4]={v4.x,v4.y,v4.z,v4.w};
      #pragma unroll
      for (int i=0;i<4;i++)
        #pragma unroll
        for (int j=0;j<4;j++) r16[i*4+j]+=pv[i]*vv[j];
    }
  }
  __syncthreads();

  // ---- L4: V half1 (block b)
  for (int i=tid;i<64*32;i+=512) {
    int t=i>>5, dg=(i&31)*4;
    float4 vv = *(const float4*)&value[(size_t)(b*64+t)*(NKV*HS)+kvh*HS+dg];
    *(float4*)&sB[t*PB+dg]=vv;
  }
  __syncthreads();

  // ---- G4: y += probs(k 64..127) @ V(block b)
  #pragma unroll 4
  for (int k=0;k<64;++k) {
    float4 p4 = *(const float4*)&sA[(64+k)*PA+r0];
    float4 v4 = *(const float4*)&sB[k*PB+c0];
    float pv[4]={p4.x,p4.y,p4.z,p4.w}, vv[4]={v4.x,v4.y,v4.z,v4.w};
    #pragma unroll
    for (int i=0;i<4;i++)
      #pragma unroll
      for (int j=0;j<4;j++) r16[i*4+j]+=pv[i]*vv[j];
  }

  // ---- linear prefix: y += f_q @ P_b ; sum_ln = f_q . zp_b
  if (b >= 2) {
    __syncthreads();   // probs^T consumed
    const float* P = g_P + ((size_t)h*NB + b)*HS*HS;
    for (int i=tid;i<64*HS;i+=512) {
      int r=i>>7, f=i&127;
      sA[f*PA+r] = g_fq[((size_t)h*TT + b*64)*HS + i];
    }
    for (int i=tid;i<64*32;i+=512) {
      int fl=i>>5, dg=(i&31)*4;
      *(float4*)&sB[fl*PB+dg] = *(const float4*)&P[fl*HS+dg];
    }
    if (tid < HS) sZp[tid] = g_zp[((size_t)h*NB + b)*HS + tid];
    __syncthreads();

    #pragma unroll 4
    for (int f=0; f<64; ++f) {
      float4 a  = *(const float4*)&sA[f*PA+r0];
      float4 p4 = *(const float4*)&sB[f*PB+c0];
      float av[4]={a.x,a.y,a.z,a.w}, pv[4]={p4.x,p4.y,p4.z,p4.w};
      #pragma unroll
      for (int i=0;i<4;i++)
        #pragma unroll
        for (int j=0;j<4;j++) r16[i*4+j]+=av[i]*pv[j];
    }
    if (tid < 64) {
      float s=0.f;
      #pragma unroll 4
      for (int f=0;f<HS;++f) s += sA[f*PA+tid]*sZp[f];
      sSums[64+tid]=s;
    }
    __syncthreads();

    for (int i=tid;i<64*32;i+=512) {
      int fl=i>>5, dg=(i&31)*4;
      *(float4*)&sB[fl*PB+dg] = *(const float4*)&P[(64+fl)*HS+dg];
    }
    __syncthreads();

    #pragma unroll 4
    for (int f=0; f<64; ++f) {
      float4 a  = *(const float4*)&sA[(64+f)*PA+r0];
      float4 p4 = *(const float4*)&sB[f*PB+c0];
      float av[4]={a.x,a.y,a.z,a.w}, pv[4]={p4.x,p4.y,p4.z,p4.w};
      #pragma unroll
      for (int i=0;i<4;i++)
        #pragma unroll
        for (int j=0;j<4;j++) r16[i*4+j]+=av[i]*pv[j];
    }
  } else {
    __syncthreads();
  }

  // ---- epilogue ----
  #pragma unroll
  for (int i=0;i<4;i++) {
    int r=r0+i;
    float inv = 1.f/(sSums[r]+sSums[64+r]);
    float4 o = make_float4(r16[i*4+0]*inv,r16[i*4+1]*inv,r16[i*4+2]*inv,r16[i*4+3]*inv);
    *(float4*)&out[((size_t)h*TT + b*64 + r)*HS + c0] = o;
  }
}

// ---------------------------------------------------------------------------
extern "C" void kernel_launch(void* const* d_in, const int* in_sizes, int n_in,
                              void* d_out, int out_size)
{
  const float* q   = (const float*)d_in[0];
  const float* k   = (const float*)d_in[1];
  const float* v   = (const float*)d_in[2];
  const float* fqw = (const float*)d_in[3];
  const float* fkw = (const float*)d_in[4];
  const float* wfr = (const float*)d_in[5];
  float* out = (float*)d_out;

  // smem: featmap/fkstate = 2*128*68*4 = 69632 B -> 3 CTAs/SM
  // attn = (128*68 + 64*132 + 256)*4 = 69632 B -> 3 CTAs/SM
  cudaFuncSetAttribute(featmap_q_kernel, cudaFuncAttributeMaxDynamicSharedMemorySize, 69632);
  cudaFuncSetAttribute(fkstate_kernel,   cudaFuncAttributeMaxDynamicSharedMemorySize, 69632);
  cudaFuncSetAttribute(attn_kernel,      cudaFuncAttributeMaxDynamicSharedMemorySize, 69632);

  featmap_q_kernel<<<dim3(32,32),512,69632>>>(q, fqw);
  fkstate_kernel  <<<dim3(32,32),512,69632>>>(k, v, fkw);
  prefix_kernel   <<<dim3(64,32),256>>>();
  attn_kernel     <<<dim3(32,32),512,69632>>>(q, k, v, wfr, out);
}

// round 13
// speedup vs baseline: 2.3744x; 1.0048x over previous
#include <cuda_runtime.h>
#include <math.h>

#define TT   2048
#define NH   32
#define NKV  8
#define HS   128
#define FD   64
#define NB   32          // 64-token blocks
#define EPSF 1e-12f
#define SCALE 0.08838834764831845f  // 1/sqrt(128)

#define PA 68    // pad for transposed A tiles [128][68]
#define PF 132   // pad for feature tiles [64][132]
#define PB 132   // pad for attn B half tiles [64][132]

// scratch (device globals: no runtime allocation allowed)
__device__ float g_fq[NH*TT*HS];          // 33.5 MB
__device__ float g_S [NH*NB*HS*HS];       // 67 MB  per-block KV states
__device__ float g_z [NH*NB*HS];          // 0.5 MB per-block key sums
__device__ float g_P [NH*NB*HS*HS];       // 67 MB  per-block prefix states
__device__ float g_zp[NH*NB*HS];          // 0.5 MB per-block prefix key sums

// ---------------------------------------------------------------------------
// Register softmax helper: thread holds z[4] = Z[row][f0..f0+3]; the row's 64
// values live in 16 consecutive lanes (width-16 shuffle domain). Produces the
// clipped feature values for the positive half (p[4]) and negative half (n[4]).
// ---------------------------------------------------------------------------
__device__ __forceinline__ void rowsoftmax16(const float z[4], float p[4], float n[4])
{
  float mx = fmaxf(fmaxf(z[0],z[1]), fmaxf(z[2],z[3]));
  float mn = fminf(fminf(z[0],z[1]), fminf(z[2],z[3]));
  #pragma unroll
  for (int m=1;m<16;m<<=1) {
    mx = fmaxf(mx, __shfl_xor_sync(0xffffffffu, mx, m, 16));
    mn = fminf(mn, __shfl_xor_sync(0xffffffffu, mn, m, 16));
  }
  float sp=0.f, sn=0.f;
  #pragma unroll
  for (int j=0;j<4;j++) {
    p[j]=__expf(z[j]-mx); n[j]=__expf(mn-z[j]);
    sp+=p[j]; sn+=n[j];
  }
  #pragma unroll
  for (int m=1;m<16;m<<=1) {
    sp += __shfl_xor_sync(0xffffffffu, sp, m, 16);
    sn += __shfl_xor_sync(0xffffffffu, sn, m, 16);
  }
  float rp=1.f/sp, rn=1.f/sn;
  #pragma unroll
  for (int j=0;j<4;j++) {
    p[j]=fmaxf(p[j]*rp, EPSF);
    n[j]=fmaxf(n[j]*rn, EPSF);
  }
}

// ---------------------------------------------------------------------------
// Kernel 1: feature map for Q. grid (32 tiles, 32 heads), 512 thr, 3 CTAs/SM.
// Z kept in registers; softmax via width-16 shuffles; no sZ tile.
// ---------------------------------------------------------------------------
__global__ void __launch_bounds__(512,3) featmap_q_kernel(
    const float* __restrict__ x, const float* __restrict__ w)
{
  extern __shared__ float sm[];
  float* sW  = sm;             // [128][68]
  float* sXT = sW + 128*PA;    // [128][68] x transposed; later sF [64][132]
  float* sF  = sXT;

  int tile = blockIdx.x, h = blockIdx.y;
  int tid = threadIdx.x;
  const float* wh = w + (size_t)h * HS * FD;

  for (int i = tid; i < HS*FD; i += 512) {
    int d = i / FD, f = i % FD;
    sW[d*PA+f] = wh[i];
  }
  for (int i = tid; i < 64*HS; i += 512) {
    int t = i >> 7, d = i & 127;
    sXT[d*PA+t] = x[(size_t)(tile*64+t)*(NH*HS) + h*HS + d];
  }
  __syncthreads();

  // GEMM Z = X W : 64x64 output, 2 rows x 4 cols per thread (in registers)
  int r0 = (tid >> 4) * 2, f0 = (tid & 15) * 4;
  float acc[8];
  #pragma unroll
  for (int i=0;i<8;i++) acc[i]=0.f;
  #pragma unroll 4
  for (int d=0; d<HS; ++d) {
    float2 a  = *(const float2*)&sXT[d*PA+r0];
    float4 bv = *(const float4*)&sW [d*PA+f0];
    float av[2] = {a.x,a.y};
    float bb[4] = {bv.x,bv.y,bv.z,bv.w};
    #pragma unroll
    for (int i=0;i<2;i++)
      #pragma unroll
      for (int j=0;j<4;j++) acc[i*4+j] += av[i]*bb[j];
  }
  __syncthreads();   // sXT dead; sF overlays it

  #pragma unroll
  for (int i=0;i<2;i++) {
    float p[4], n[4];
    rowsoftmax16(&acc[i*4], p, n);
    *(float4*)&sF[(r0+i)*PF + f0]      = make_float4(p[0],p[1],p[2],p[3]);
    *(float4*)&sF[(r0+i)*PF + FD + f0] = make_float4(n[0],n[1],n[2],n[3]);
  }
  __syncthreads();

  for (int i = tid; i < 64*32; i += 512) {
    int e = i*4;
    int t = e>>7, f = e&127;
    *(float4*)&g_fq[((size_t)h*TT + tile*64 + t)*HS + f] = *(const float4*)&sF[t*PF+f];
  }
}

// ---------------------------------------------------------------------------
// Kernel 2: FUSED feature map for K + block state. 512 thr, 3 CTAs/SM.
// Register softmax; state GEMM in two 4x4 d-half passes (reg-cap friendly).
// ---------------------------------------------------------------------------
__global__ void __launch_bounds__(512,3) fkstate_kernel(
    const float* __restrict__ key, const float* __restrict__ value,
    const float* __restrict__ w)
{
  extern __shared__ float sm[];
  float* sW  = sm;             // [128][68]; later sV [64][132]
  float* sXT = sW + 128*PA;    // [128][68] k transposed; later sFK [64][132]
  float* sFK = sXT;
  float* sV  = sW;

  int b = blockIdx.x, h = blockIdx.y;
  int tid = threadIdx.x;
  int kvh = h >> 2;
  const float* wh = w + (size_t)h * HS * FD;

  for (int i = tid; i < HS*FD; i += 512) {
    int d = i / FD, f = i % FD;
    sW[d*PA+f] = wh[i];
  }
  for (int i = tid; i < 64*HS; i += 512) {
    int t = i >> 7, d = i & 127;
    sXT[d*PA+t] = key[(size_t)(b*64+t)*(NKV*HS) + kvh*HS + d];
  }
  __syncthreads();

  int r0 = (tid >> 4) * 2, f0q = (tid & 15) * 4;
  {
    float acc[8];
    #pragma unroll
    for (int i=0;i<8;i++) acc[i]=0.f;
    #pragma unroll 4
    for (int d=0; d<HS; ++d) {
      float2 a  = *(const float2*)&sXT[d*PA+r0];
      float4 bv = *(const float4*)&sW [d*PA+f0q];
      float av[2] = {a.x,a.y};
      float bb[4] = {bv.x,bv.y,bv.z,bv.w};
      #pragma unroll
      for (int i=0;i<2;i++)
        #pragma unroll
        for (int j=0;j<4;j++) acc[i*4+j] += av[i]*bb[j];
    }
    __syncthreads();   // sW, sXT dead

    #pragma unroll
    for (int i=0;i<2;i++) {
      float p[4], n[4];
      rowsoftmax16(&acc[i*4], p, n);
      *(float4*)&sFK[(r0+i)*PF + f0q]      = make_float4(p[0],p[1],p[2],p[3]);
      *(float4*)&sFK[(r0+i)*PF + FD + f0q] = make_float4(n[0],n[1],n[2],n[3]);
    }
  }
  // V load into sV (overlays sW) — same barrier interval as softmax writes
  for (int i = tid; i < 64*32; i += 512) {
    int t = i >> 5, dg = (i & 31) * 4;
    float4 vv = *(const float4*)&value[(size_t)(b*64+t)*(NKV*HS) + kvh*HS + dg];
    *(float4*)&sV[t*PF+dg] = vv;
  }
  __syncthreads();

  // S_b[f][d] = sum_t f_k[t][f] * V[t][d]; two passes of 4x4 per thread
  {
    int f0 = (tid >> 4) * 4, d0 = (tid & 15) * 4;
    float* Sout = g_S + ((size_t)h*NB + b)*HS*HS;
    #pragma unroll
    for (int pass=0; pass<2; ++pass) {
      int dp = d0 + pass*64;
      float acc[16];
      #pragma unroll
      for (int i=0;i<16;i++) acc[i]=0.f;
      #pragma unroll 4
      for (int t=0;t<64;++t) {
        float4 a4 = *(const float4*)&sFK[t*PF+f0];
        float4 b4 = *(const float4*)&sV [t*PF+dp];
        float fv[4] = {a4.x,a4.y,a4.z,a4.w};
        float vv[4] = {b4.x,b4.y,b4.z,b4.w};
        #pragma unroll
        for (int i=0;i<4;i++)
          #pragma unroll
          for (int j=0;j<4;j++) acc[i*4+j]+=fv[i]*vv[j];
      }
      #pragma unroll
      for (int i=0;i<4;i++)
        *(float4*)&Sout[(f0+i)*HS + dp] =
          make_float4(acc[i*4+0],acc[i*4+1],acc[i*4+2],acc[i*4+3]);
    }
  }
  if (tid < HS) {
    float z=0.f;
    #pragma unroll 4
    for (int t=0;t<64;++t) z += sFK[t*PF+tid];
    g_z[((size_t)h*NB+b)*HS + tid] = z;
  }
}

// ---------------------------------------------------------------------------
// Kernel 3: per-block prefix states  g_P[h][b] = sum_{j<=b-2} S_j  (b=2..31)
// ---------------------------------------------------------------------------
__global__ void __launch_bounds__(256) prefix_kernel()
{
  int h = blockIdx.y;
  int e = blockIdx.x*256 + threadIdx.x;  // 0..16383
  float acc = 0.f;
  for (int j = 0; j <= NB-3; ++j) {
    acc += g_S[((size_t)h*NB + j)*HS*HS + e];
    g_P[((size_t)h*NB + j+2)*HS*HS + e] = acc;
  }
  if (blockIdx.x == 0 && threadIdx.x < HS) {
    float az = 0.f;
    for (int j = 0; j <= NB-3; ++j) {
      az += g_z[((size_t)h*NB + j)*HS + threadIdx.x];
      g_zp[((size_t)h*NB + j+2)*HS + threadIdx.x] = az;
    }
  }
}

// ---------------------------------------------------------------------------
// Kernel 4: main attention, K-split halves. grid (32,32)=1024 CTAs, 512 thr,
// smem 69632 B -> 3 CTAs/SM = 48 warps.  (unchanged from R10 passing version)
// ---------------------------------------------------------------------------
__global__ void __launch_bounds__(512,3) attn_kernel(
    const float* __restrict__ query, const float* __restrict__ key,
    const float* __restrict__ value, const float* __restrict__ wfraw,
    float* __restrict__ out)
{
  extern __shared__ float sm[];
  float* sA    = sm;              // [128][68]  Q^T -> probs^T -> fq^T
  float* sB    = sA + 128*PA;     // [64][132]  K^T half / V half / P half
  float* sZp   = sB + 64*PB;      // [128]
  float* sSums = sZp + 128;       // [128]  sum_sm | sum_ln

  int b = blockIdx.x, h = blockIdx.y;
  int tid = threadIdx.x;
  int kvh = h >> 2;
  float wf = 1.f / (1.f + __expf(-wfraw[h]));

  int ty = tid >> 5, tx = tid & 31;
  int r0 = ty*4, c0 = tx*4;

  float r16[16];
  #pragma unroll
  for (int i=0;i<16;i++) r16[i]=0.f;
  if (tid < 64) sSums[64+tid] = 0.f;   // default sum_ln (b<2)

  // ---- L1: Q^T full; K^T half0 (cols 0..63=block b-1, 64..127=block b; d 0..63)
  for (int i=tid;i<64*HS;i+=512) {
    int r=i>>7, d=i&127;
    sA[d*PA+r]=query[(size_t)(b*64+r)*(NH*HS) + h*HS + d];
  }
  for (int i=tid;i<64*HS;i+=512) {
    int dl=i&63, col=i>>6;
    float kv;
    if (col<64) kv = (b==0)?0.f : key[(size_t)((b-1)*64+col)*(NKV*HS)+kvh*HS+dl];
    else        kv = key[(size_t)(b*64+(col-64))*(NKV*HS)+kvh*HS+dl];
    sB[dl*PB+col]=kv;
  }
  __syncthreads();

  // ---- G1: scores, d 0..63
  #pragma unroll 4
  for (int dl=0; dl<64; ++dl) {
    float4 a  = *(const float4*)&sA[dl*PA+r0];
    float4 k4 = *(const float4*)&sB[dl*PB+c0];
    float av[4]={a.x,a.y,a.z,a.w}, kv[4]={k4.x,k4.y,k4.z,k4.w};
    #pragma unroll
    for (int i=0;i<4;i++)
      #pragma unroll
      for (int j=0;j<4;j++) r16[i*4+j]+=av[i]*kv[j];
  }
  __syncthreads();

  // ---- L2: K^T half1 (d 64..127); for b==0 cols<64 are zero
  for (int i=tid;i<64*HS;i+=512) {
    int dl=i&63, col=i>>6;
    float kv;
    if (col<64) kv = (b==0)?0.f : key[(size_t)((b-1)*64+col)*(NKV*HS)+kvh*HS+64+dl];
    else        kv = key[(size_t)(b*64+(col-64))*(NKV*HS)+kvh*HS+64+dl];
    sB[dl*PB+col]=kv;
  }
  __syncthreads();

  // ---- G2: scores, d 64..127
  #pragma unroll 4
  for (int dl=0; dl<64; ++dl) {
    float4 a  = *(const float4*)&sA[(64+dl)*PA+r0];
    float4 k4 = *(const float4*)&sB[dl*PB+c0];
    float av[4]={a.x,a.y,a.z,a.w}, kv[4]={k4.x,k4.y,k4.z,k4.w};
    #pragma unroll
    for (int i=0;i<4;i++)
      #pragma unroll
      for (int j=0;j<4;j++) r16[i*4+j]+=av[i]*kv[j];
  }
  __syncthreads();   // Q^T consumed; sA reusable

  // ---- softmax: row r fully within warp ty (width-32 shuffles)
  #pragma unroll
  for (int i=0;i<4;i++) {
    int r = r0 + i;
    float mx = -1e30f;
    #pragma unroll
    for (int j=0;j<4;j++) {
      int col = c0 + j;
      bool ok = (col < 64) ? (b > 0) : ((col - 64) <= r);
      float s = r16[i*4+j]*SCALE;
      r16[i*4+j] = s;
      if (ok) mx = fmaxf(mx, s);
    }
    #pragma unroll
    for (int m=16;m>=1;m>>=1) mx = fmaxf(mx, __shfl_xor_sync(0xffffffffu, mx, m));
    float sum = 0.f;
    #pragma unroll
    for (int j=0;j<4;j++) {
      int col = c0 + j;
      bool ok = (col < 64) ? (b > 0) : ((col - 64) <= r);
      float p = ok ? wf*__expf(r16[i*4+j]-mx) : 0.f;
      r16[i*4+j] = p;
      sum += p;
    }
    #pragma unroll
    for (int m=16;m>=1;m>>=1) sum += __shfl_xor_sync(0xffffffffu, sum, m);
    if (tx == 0) sSums[r] = sum;
  }

  // ---- L3: probs^T -> sA [k][r]; V half0 -> sB (block b-1)
  #pragma unroll
  for (int i=0;i<4;i++)
    #pragma unroll
    for (int j=0;j<4;j++) sA[(c0+j)*PA + r0+i] = r16[i*4+j];
  if (b > 0) {
    for (int i=tid;i<64*32;i+=512) {
      int t=i>>5, dg=(i&31)*4;
      float4 vv = *(const float4*)&value[(size_t)((b-1)*64+t)*(NKV*HS)+kvh*HS+dg];
      *(float4*)&sB[t*PB+dg]=vv;
    }
  }
  __syncthreads();

  // r16 becomes the y accumulator
  #pragma unroll
  for (int i=0;i<16;i++) r16[i]=0.f;

  // ---- G3: y += probs(k 0..63) @ V(block b-1)
  if (b > 0) {
    #pragma unroll 4
    for (int k=0;k<64;++k) {
      float4 p4 = *(const float4*)&sA[k*PA+r0];
      float4 v4 = *(const float4*)&sB[k*PB+c0];
      float pv[4]={p4.x,p4.y,p4.z,p4.w}, vv[4]={v4.x,v4.y,v4.z,v4.w};
      #pragma unroll
      for (int i=0;i<4;i++)
        #pragma unroll
        for (int j=0;j<4;j++) r16[i*4+j]+=pv[i]*vv[j];
    }
  }
  __syncthreads();

  // ---- L4: V half1 (block b)
  for (int i=tid;i<64*32;i+=512) {
    int t=i>>5, dg=(i&31)*4;
    float4 vv = *(const float4*)&value[(size_t)(b*64+t)*(NKV*HS)+kvh*HS+dg];
    *(float4*)&sB[t*PB+dg]=vv;
  }
  __syncthreads();

  // ---- G4: y += probs(k 64..127) @ V(block b)
  #pragma unroll 4
  for (int k=0;k<64;++k) {
    float4 p4 = *(const float4*)&sA[(64+k)*PA+r0];
    float4 v4 = *(const float4*)&sB[k*PB+c0];
    float pv[4]={p4.x,p4.y,p4.z,p4.w}, vv[4]={v4.x,v4.y,v4.z,v4.w};
    #pragma unroll
    for (int i=0;i<4;i++)
      #pragma unroll
      for (int j=0;j<4;j++) r16[i*4+j]+=pv[i]*vv[j];
  }

  // ---- linear prefix: y += f_q @ P_b ; sum_ln = f_q . zp_b
  if (b >= 2) {
    __syncthreads();   // probs^T consumed
    const float* P = g_P + ((size_t)h*NB + b)*HS*HS;
    for (int i=tid;i<64*HS;i+=512) {
      int r=i>>7, f=i&127;
      sA[f*PA+r] = g_fq[((size_t)h*TT + b*64)*HS + i];
    }
    for (int i=tid;i<64*32;i+=512) {
      int fl=i>>5, dg=(i&31)*4;
      *(float4*)&sB[fl*PB+dg] = *(const float4*)&P[fl*HS+dg];
    }
    if (tid < HS) sZp[tid] = g_zp[((size_t)h*NB + b)*HS + tid];
    __syncthreads();

    #pragma unroll 4
    for (int f=0; f<64; ++f) {
      float4 a  = *(const float4*)&sA[f*PA+r0];
      float4 p4 = *(const float4*)&sB[f*PB+c0];
      float av[4]={a.x,a.y,a.z,a.w}, pv[4]={p4.x,p4.y,p4.z,p4.w};
      #pragma unroll
      for (int i=0;i<4;i++)
        #pragma unroll
        for (int j=0;j<4;j++) r16[i*4+j]+=av[i]*pv[j];
    }
    if (tid < 64) {
      float s=0.f;
      #pragma unroll 4
      for (int f=0;f<HS;++f) s += sA[f*PA+tid]*sZp[f];
      sSums[64+tid]=s;
    }
    __syncthreads();

    for (int i=tid;i<64*32;i+=512) {
      int fl=i>>5, dg=(i&31)*4;
      *(float4*)&sB[fl*PB+dg] = *(const float4*)&P[(64+fl)*HS+dg];
    }
    __syncthreads();

    #pragma unroll 4
    for (int f=0; f<64; ++f) {
      float4 a  = *(const float4*)&sA[(64+f)*PA+r0];
      float4 p4 = *(const float4*)&sB[f*PB+c0];
      float av[4]={a.x,a.y,a.z,a.w}, pv[4]={p4.x,p4.y,p4.z,p4.w};
      #pragma unroll
      for (int i=0;i<4;i++)
        #pragma unroll
        for (int j=0;j<4;j++) r16[i*4+j]+=av[i]*pv[j];
    }
  } else {
    __syncthreads();
  }

  // ---- epilogue ----
  #pragma unroll
  for (int i=0;i<4;i++) {
    int r=r0+i;
    float inv = 1.f/(sSums[r]+sSums[64+r]);
    float4 o = make_float4(r16[i*4+0]*inv,r16[i*4+1]*inv,r16[i*4+2]*inv,r16[i*4+3]*inv);
    *(float4*)&out[((size_t)h*TT + b*64 + r)*HS + c0] = o;
  }
}

// ---------------------------------------------------------------------------
extern "C" void kernel_launch(void* const* d_in, const int* in_sizes, int n_in,
                              void* d_out, int out_size)
{
  const float* q   = (const float*)d_in[0];
  const float* k   = (const float*)d_in[1];
  const float* v   = (const float*)d_in[2];
  const float* fqw = (const float*)d_in[3];
  const float* fkw = (const float*)d_in[4];
  const float* wfr = (const float*)d_in[5];
  float* out = (float*)d_out;

  // smem: featmap/fkstate = 2*128*68*4 = 69632 B -> 3 CTAs/SM
  // attn = (128*68 + 64*132 + 256)*4 = 69632 B -> 3 CTAs/SM
  cudaFuncSetAttribute(featmap_q_kernel, cudaFuncAttributeMaxDynamicSharedMemorySize, 69632);
  cudaFuncSetAttribute(fkstate_kernel,   cudaFuncAttributeMaxDynamicSharedMemorySize, 69632);
  cudaFuncSetAttribute(attn_kernel,      cudaFuncAttributeMaxDynamicSharedMemorySize, 69632);

  featmap_q_kernel<<<dim3(32,32),512,69632>>>(q, fqw);
  fkstate_kernel  <<<dim3(32,32),512,69632>>>(k, v, fkw);
  prefix_kernel   <<<dim3(64,32),256>>>();
  attn_kernel     <<<dim3(32,32),512,69632>>>(q, k, v, wfr, out);
}

// round 14
// speedup vs baseline: 2.8894x; 1.2169x over previous
#include <cuda_runtime.h>
#include <math.h>
#include <stdint.h>

#define TT   2048
#define NH   32
#define NKV  8
#define HS   128
#define FD   64
#define NB   32          // 64-token blocks
#define EPSF 1e-12f
#define SCALE 0.08838834764831845f  // 1/sqrt(128)

#define PA 68    // pad for transposed A tiles [128][68] (featmap/fkstate)
#define PF 132   // pad for feature tiles [64][132]
#define PRA 132  // attn A tiles [64][132] row-major
#define PRB 132  // attn B tiles, n-major ([n][k])
#define PRV 136  // attn V tile, k-major ([k][n]) — 136%32=8 -> conflict-free frags

// scratch (device globals: no runtime allocation allowed)
__device__ float g_fq[NH*TT*HS];          // 33.5 MB
__device__ float g_S [NH*NB*HS*HS];       // 67 MB  per-block KV states, stored S^T [d][f]
__device__ float g_z [NH*NB*HS];          // 0.5 MB per-block key sums
__device__ float g_P [NH*NB*HS*HS];       // 67 MB  prefix states, stored P^T [d][f]
__device__ float g_zp[NH*NB*HS];          // 0.5 MB per-block prefix key sums

// ---------------------------------------------------------------------------
__device__ __forceinline__ float to_tf32(float x){
  uint32_t u; asm("cvt.rna.tf32.f32 %0, %1;" : "=r"(u) : "f"(x));
  return __uint_as_float(u);
}
__device__ __forceinline__ void st_tf32_4(float* dst, float4 v){
  dst[0]=to_tf32(v.x); dst[1]=to_tf32(v.y); dst[2]=to_tf32(v.z); dst[3]=to_tf32(v.w);
}
__device__ __forceinline__ void mma_tf32(float c[4],
    uint32_t a0,uint32_t a1,uint32_t a2,uint32_t a3, uint32_t b0,uint32_t b1){
  asm volatile("mma.sync.aligned.m16n8k8.row.col.f32.tf32.tf32.f32 "
      "{%0,%1,%2,%3}, {%4,%5,%6,%7}, {%8,%9}, {%0,%1,%2,%3};"
      : "+f"(c[0]),"+f"(c[1]),"+f"(c[2]),"+f"(c[3])
      : "r"(a0),"r"(a1),"r"(a2),"r"(a3),"r"(b0),"r"(b1));
}

// ---------------------------------------------------------------------------
// Register softmax helper for feature maps (width-16 shuffle domain).
// ---------------------------------------------------------------------------
__device__ __forceinline__ void rowsoftmax16(const float z[4], float p[4], float n[4])
{
  float mx = fmaxf(fmaxf(z[0],z[1]), fmaxf(z[2],z[3]));
  float mn = fminf(fminf(z[0],z[1]), fminf(z[2],z[3]));
  #pragma unroll
  for (int m=1;m<16;m<<=1) {
    mx = fmaxf(mx, __shfl_xor_sync(0xffffffffu, mx, m, 16));
    mn = fminf(mn, __shfl_xor_sync(0xffffffffu, mn, m, 16));
  }
  float sp=0.f, sn=0.f;
  #pragma unroll
  for (int j=0;j<4;j++) {
    p[j]=__expf(z[j]-mx); n[j]=__expf(mn-z[j]);
    sp+=p[j]; sn+=n[j];
  }
  #pragma unroll
  for (int m=1;m<16;m<<=1) {
    sp += __shfl_xor_sync(0xffffffffu, sp, m, 16);
    sn += __shfl_xor_sync(0xffffffffu, sn, m, 16);
  }
  float rp=1.f/sp, rn=1.f/sn;
  #pragma unroll
  for (int j=0;j<4;j++) {
    p[j]=fmaxf(p[j]*rp, EPSF);
    n[j]=fmaxf(n[j]*rn, EPSF);
  }
}

// ---------------------------------------------------------------------------
// Kernel 1: feature map for Q. grid (32 tiles, 32 heads), 512 thr, 3 CTAs/SM.
// ---------------------------------------------------------------------------
__global__ void __launch_bounds__(512,3) featmap_q_kernel(
    const float* __restrict__ x, const float* __restrict__ w)
{
  extern __shared__ float sm[];
  float* sW  = sm;             // [128][68]
  float* sXT = sW + 128*PA;    // [128][68] x transposed; later sF [64][132]
  float* sF  = sXT;

  int tile = blockIdx.x, h = blockIdx.y;
  int tid = threadIdx.x;
  const float* wh = w + (size_t)h * HS * FD;

  for (int i = tid; i < HS*FD; i += 512) {
    int d = i / FD, f = i % FD;
    sW[d*PA+f] = wh[i];
  }
  for (int i = tid; i < 64*HS; i += 512) {
    int t = i >> 7, d = i & 127;
    sXT[d*PA+t] = x[(size_t)(tile*64+t)*(NH*HS) + h*HS + d];
  }
  __syncthreads();

  int r0 = (tid >> 4) * 2, f0 = (tid & 15) * 4;
  float acc[8];
  #pragma unroll
  for (int i=0;i<8;i++) acc[i]=0.f;
  #pragma unroll 4
  for (int d=0; d<HS; ++d) {
    float2 a  = *(const float2*)&sXT[d*PA+r0];
    float4 bv = *(const float4*)&sW [d*PA+f0];
    float av[2] = {a.x,a.y};
    float bb[4] = {bv.x,bv.y,bv.z,bv.w};
    #pragma unroll
    for (int i=0;i<2;i++)
      #pragma unroll
      for (int j=0;j<4;j++) acc[i*4+j] += av[i]*bb[j];
  }
  __syncthreads();   // sXT dead; sF overlays it

  #pragma unroll
  for (int i=0;i<2;i++) {
    float p[4], n[4];
    rowsoftmax16(&acc[i*4], p, n);
    *(float4*)&sF[(r0+i)*PF + f0]      = make_float4(p[0],p[1],p[2],p[3]);
    *(float4*)&sF[(r0+i)*PF + FD + f0] = make_float4(n[0],n[1],n[2],n[3]);
  }
  __syncthreads();

  for (int i = tid; i < 64*32; i += 512) {
    int e = i*4;
    int t = e>>7, f = e&127;
    *(float4*)&g_fq[((size_t)h*TT + tile*64 + t)*HS + f] = *(const float4*)&sF[t*PF+f];
  }
}

// ---------------------------------------------------------------------------
// Kernel 2: FUSED feature map for K + block state. 512 thr, 3 CTAs/SM.
// NOTE: stores S TRANSPOSED: g_S holds S^T[d][f] = sum_t V[t][d] f_k[t][f].
// ---------------------------------------------------------------------------
__global__ void __launch_bounds__(512,3) fkstate_kernel(
    const float* __restrict__ key, const float* __restrict__ value,
    const float* __restrict__ w)
{
  extern __shared__ float sm[];
  float* sW  = sm;             // [128][68]; later sV [64][132]
  float* sXT = sW + 128*PA;    // [128][68] k transposed; later sFK [64][132]
  float* sFK = sXT;
  float* sV  = sW;

  int b = blockIdx.x, h = blockIdx.y;
  int tid = threadIdx.x;
  int kvh = h >> 2;
  const float* wh = w + (size_t)h * HS * FD;

  for (int i = tid; i < HS*FD; i += 512) {
    int d = i / FD, f = i % FD;
    sW[d*PA+f] = wh[i];
  }
  for (int i = tid; i < 64*HS; i += 512) {
    int t = i >> 7, d = i & 127;
    sXT[d*PA+t] = key[(size_t)(b*64+t)*(NKV*HS) + kvh*HS + d];
  }
  __syncthreads();

  int r0 = (tid >> 4) * 2, f0q = (tid & 15) * 4;
  {
    float acc[8];
    #pragma unroll
    for (int i=0;i<8;i++) acc[i]=0.f;
    #pragma unroll 4
    for (int d=0; d<HS; ++d) {
      float2 a  = *(const float2*)&sXT[d*PA+r0];
      float4 bv = *(const float4*)&sW [d*PA+f0q];
      float av[2] = {a.x,a.y};
      float bb[4] = {bv.x,bv.y,bv.z,bv.w};
      #pragma unroll
      for (int i=0;i<2;i++)
        #pragma unroll
        for (int j=0;j<4;j++) acc[i*4+j] += av[i]*bb[j];
    }
    __syncthreads();   // sW, sXT dead

    #pragma unroll
    for (int i=0;i<2;i++) {
      float p[4], n[4];
      rowsoftmax16(&acc[i*4], p, n);
      *(float4*)&sFK[(r0+i)*PF + f0q]      = make_float4(p[0],p[1],p[2],p[3]);
      *(float4*)&sFK[(r0+i)*PF + FD + f0q] = make_float4(n[0],n[1],n[2],n[3]);
    }
  }
  for (int i = tid; i < 64*32; i += 512) {
    int t = i >> 5, dg = (i & 31) * 4;
    float4 vv = *(const float4*)&value[(size_t)(b*64+t)*(NKV*HS) + kvh*HS + dg];
    *(float4*)&sV[t*PF+dg] = vv;
  }
  __syncthreads();

  // S^T[d][f] = sum_t V[t][d] * f_k[t][f]; two passes over f-halves
  {
    int d0 = (tid >> 4) * 4, f0 = (tid & 15) * 4;
    float* Sout = g_S + ((size_t)h*NB + b)*HS*HS;
    #pragma unroll
    for (int pass=0; pass<2; ++pass) {
      int fp = f0 + pass*64;
      float acc[16];
      #pragma unroll
      for (int i=0;i<16;i++) acc[i]=0.f;
      #pragma unroll 4
      for (int t=0;t<64;++t) {
        float4 a4 = *(const float4*)&sV [t*PF+d0];
        float4 b4 = *(const float4*)&sFK[t*PF+fp];
        float vv[4] = {a4.x,a4.y,a4.z,a4.w};
        float fv[4] = {b4.x,b4.y,b4.z,b4.w};
        #pragma unroll
        for (int i=0;i<4;i++)
          #pragma unroll
          for (int j=0;j<4;j++) acc[i*4+j]+=vv[i]*fv[j];
      }
      #pragma unroll
      for (int i=0;i<4;i++)
        *(float4*)&Sout[(d0+i)*HS + fp] =
          make_float4(acc[i*4+0],acc[i*4+1],acc[i*4+2],acc[i*4+3]);
    }
  }
  if (tid < HS) {
    float z=0.f;
    #pragma unroll 4
    for (int t=0;t<64;++t) z += sFK[t*PF+tid];
    g_z[((size_t)h*NB+b)*HS + tid] = z;
  }
}

// ---------------------------------------------------------------------------
// Kernel 3: prefix over S^T (elementwise, layout-agnostic).
// ---------------------------------------------------------------------------
__global__ void __launch_bounds__(256) prefix_kernel()
{
  int h = blockIdx.y;
  int e = blockIdx.x*256 + threadIdx.x;  // 0..16383
  float acc = 0.f;
  for (int j = 0; j <= NB-3; ++j) {
    acc += g_S[((size_t)h*NB + j)*HS*HS + e];
    g_P[((size_t)h*NB + j+2)*HS*HS + e] = acc;
  }
  if (blockIdx.x == 0 && threadIdx.x < HS) {
    float az = 0.f;
    for (int j = 0; j <= NB-3; ++j) {
      az += g_z[((size_t)h*NB + j)*HS + threadIdx.x];
      g_zp[((size_t)h*NB + j+2)*HS + threadIdx.x] = az;
    }
  }
}

// ---------------------------------------------------------------------------
// Kernel 4: main attention via tf32 mma.sync (m16n8k8).
// grid (32,32)=1024 CTAs, 256 thr = 8 warps, each a 32x32 output tile
// (2 m-tiles x 4 n-tiles). smem ~104 KB -> 2 CTAs/SM.
// ---------------------------------------------------------------------------
__global__ void __launch_bounds__(256,2) attn_kernel(
    const float* __restrict__ query, const float* __restrict__ key,
    const float* __restrict__ value, const float* __restrict__ wfraw,
    float* __restrict__ out)
{
  extern __shared__ float sm[];
  float* sA   = sm;                 // [64][132]  tf32 Q -> probs -> fq
  float* sB   = sA + 64*PRA;        // [128][136] tf32 K(132) -> V(136) -> P^T(132)
  float* sRed = sB + 128*PRV;       // [512]: [0..255] row-band max, [256..511] sums
  float* sZp  = sRed + 512;         // [128]
  float* sLn  = sZp + 128;          // [64] sum_ln

  int b = blockIdx.x, h = blockIdx.y;
  int tid = threadIdx.x;
  int kvh = h >> 2;
  float wf = 1.f/(1.f+__expf(-wfraw[h]));

  int w = tid >> 5, lane = tid & 31;
  int g = lane >> 2, tg = lane & 3;
  int mb = w & 1, nb = w >> 1;
  int mbase = mb*32, nbase = nb*32;

  if (tid < 64) sLn[tid] = 0.f;

  // ---- L1: tf32(Q) [64][132], tf32(K) [128 keys][132]; zp ----
  for (int i = tid; i < 64*32; i += 256) {
    int r = i >> 5, d4 = (i & 31)*4;
    float4 v = *(const float4*)&query[(size_t)(b*64+r)*(NH*HS) + h*HS + d4];
    st_tf32_4(&sA[r*PRA+d4], v);
  }
  for (int i = tid; i < 128*32; i += 256) {
    int r = i >> 5, d4 = (i & 31)*4;
    float4 v;
    if (r < 64) {
      if (b == 0) v = make_float4(0.f,0.f,0.f,0.f);
      else v = *(const float4*)&key[(size_t)((b-1)*64+r)*(NKV*HS)+kvh*HS+d4];
    } else {
      v = *(const float4*)&key[(size_t)(b*64+(r-64))*(NKV*HS)+kvh*HS+d4];
    }
    st_tf32_4(&sB[r*PRB+d4], v);
  }
  if (b >= 2 && tid < HS) sZp[tid] = g_zp[((size_t)h*NB+b)*HS+tid];
  __syncthreads();

  // ---- G1: scores = Q @ K^T ----
  float c[2][4][4];
  #pragma unroll
  for (int mt=0;mt<2;mt++)
    #pragma unroll
    for (int nt=0;nt<4;nt++)
      #pragma unroll
      for (int e=0;e<4;e++) c[mt][nt][e]=0.f;

  #pragma unroll 4
  for (int k0=0;k0<128;k0+=8) {
    uint32_t a[2][4], bb[4][2];
    #pragma unroll
    for (int mt=0;mt<2;mt++){
      int R = mbase+mt*16;
      a[mt][0]=__float_as_uint(sA[(R+g)*PRA+k0+tg]);
      a[mt][1]=__float_as_uint(sA[(R+g+8)*PRA+k0+tg]);
      a[mt][2]=__float_as_uint(sA[(R+g)*PRA+k0+tg+4]);
      a[mt][3]=__float_as_uint(sA[(R+g+8)*PRA+k0+tg+4]);
    }
    #pragma unroll
    for (int nt=0;nt<4;nt++){
      int C = nbase+nt*8;
      bb[nt][0]=__float_as_uint(sB[(C+g)*PRB+k0+tg]);
      bb[nt][1]=__float_as_uint(sB[(C+g)*PRB+k0+tg+4]);
    }
    #pragma unroll
    for (int mt=0;mt<2;mt++)
      #pragma unroll
      for (int nt=0;nt<4;nt++)
        mma_tf32(c[mt][nt], a[mt][0],a[mt][1],a[mt][2],a[mt][3], bb[nt][0],bb[nt][1]);
  }

  // ---- softmax: local masked max per row-band, reduce over tg (width-4) ----
  #pragma unroll
  for (int mt=0;mt<2;mt++)
   #pragma unroll
   for (int half=0;half<2;half++) {
    int r = mbase+mt*16+half*8+g;
    float mx = -1e30f;
    #pragma unroll
    for (int nt=0;nt<4;nt++)
      #pragma unroll
      for (int e=0;e<2;e++) {
        int col = nbase+nt*8+2*tg+e;
        float s = c[mt][nt][half*2+e]*SCALE;
        c[mt][nt][half*2+e]=s;
        bool ok = (col<64) ? (b>0) : ((col-64)<=r);
        if (ok) mx = fmaxf(mx, s);
      }
    mx = fmaxf(mx, __shfl_xor_sync(0xffffffffu, mx, 1, 4));
    mx = fmaxf(mx, __shfl_xor_sync(0xffffffffu, mx, 2, 4));
    if (tg==0) sRed[r*4+nb]=mx;
   }
  __syncthreads();   // scores read done; band maxes visible; sA/sB free

  // ---- exp + band sums; probs (tf32) -> sA; tf32(V) -> sB ----
  #pragma unroll
  for (int mt=0;mt<2;mt++)
   #pragma unroll
   for (int half=0;half<2;half++) {
    int r = mbase+mt*16+half*8+g;
    float gm = fmaxf(fmaxf(sRed[r*4+0],sRed[r*4+1]),fmaxf(sRed[r*4+2],sRed[r*4+3]));
    float sum=0.f;
    #pragma unroll
    for (int nt=0;nt<4;nt++){
      int col0 = nbase+nt*8+2*tg;
      bool ok0 = (col0  <64) ? (b>0) : ((col0  -64)<=r);
      bool ok1 = (col0+1<64) ? (b>0) : ((col0+1-64)<=r);
      float p0 = ok0 ? to_tf32(wf*__expf(c[mt][nt][half*2+0]-gm)) : 0.f;
      float p1 = ok1 ? to_tf32(wf*__expf(c[mt][nt][half*2+1]-gm)) : 0.f;
      sum += p0+p1;
      *(float2*)&sA[r*PRA + col0] = make_float2(p0,p1);
    }
    sum += __shfl_xor_sync(0xffffffffu,sum,1,4);
    sum += __shfl_xor_sync(0xffffffffu,sum,2,4);
    if (tg==0) sRed[256 + r*4+nb]=sum;
   }
  for (int i = tid; i < 128*32; i += 256) {
    int r = i >> 5, d4 = (i & 31)*4;
    float4 v;
    if (r < 64) {
      if (b == 0) v = make_float4(0.f,0.f,0.f,0.f);
      else v = *(const float4*)&value[(size_t)((b-1)*64+r)*(NKV*HS)+kvh*HS+d4];
    } else {
      v = *(const float4*)&value[(size_t)(b*64+(r-64))*(NKV*HS)+kvh*HS+d4];
    }
    st_tf32_4(&sB[r*PRV+d4], v);
  }
  // reset accumulators for y
  #pragma unroll
  for (int mt=0;mt<2;mt++)
    #pragma unroll
    for (int nt=0;nt<4;nt++)
      #pragma unroll
      for (int e=0;e<4;e++) c[mt][nt][e]=0.f;
  __syncthreads();

  // ---- G2: y = P @ V  (A: probs [m][key] pad132; B: V k-major pad136) ----
  #pragma unroll 4
  for (int k0=0;k0<128;k0+=8) {
    uint32_t a[2][4], bb[4][2];
    #pragma unroll
    for (int mt=0;mt<2;mt++){
      int R = mbase+mt*16;
      a[mt][0]=__float_as_uint(sA[(R+g)*PRA+k0+tg]);
      a[mt][1]=__float_as_uint(sA[(R+g+8)*PRA+k0+tg]);
      a[mt][2]=__float_as_uint(sA[(R+g)*PRA+k0+tg+4]);
      a[mt][3]=__float_as_uint(sA[(R+g+8)*PRA+k0+tg+4]);
    }
    #pragma unroll
    for (int nt=0;nt<4;nt++){
      int C = nbase+nt*8;
      bb[nt][0]=__float_as_uint(sB[(k0+tg  )*PRV + C+g]);
      bb[nt][1]=__float_as_uint(sB[(k0+tg+4)*PRV + C+g]);
    }
    #pragma unroll
    for (int mt=0;mt<2;mt++)
      #pragma unroll
      for (int nt=0;nt<4;nt++)
        mma_tf32(c[mt][nt], a[mt][0],a[mt][1],a[mt][2],a[mt][3], bb[nt][0],bb[nt][1]);
  }

  // ---- prefix: y += fq @ P ; sum_ln = fq . zp ----
  if (b >= 2) {
    __syncthreads();   // G2 reads done
    for (int i = tid; i < 64*32; i += 256) {
      int r = i >> 5, d4 = (i & 31)*4;
      float4 v = *(const float4*)&g_fq[((size_t)h*TT + b*64 + r)*HS + d4];
      st_tf32_4(&sA[r*PRA+d4], v);
    }
    const float* PT = g_P + ((size_t)h*NB + b)*HS*HS;   // P^T [d][f]
    for (int i = tid; i < 128*32; i += 256) {
      int r = i >> 5, f4 = (i & 31)*4;
      float4 v = *(const float4*)&PT[r*HS + f4];
      st_tf32_4(&sB[r*PRB+f4], v);
    }
    __syncthreads();

    #pragma unroll 4
    for (int k0=0;k0<128;k0+=8) {
      uint32_t a[2][4], bb[4][2];
      #pragma unroll
      for (int mt=0;mt<2;mt++){
        int R = mbase+mt*16;
        a[mt][0]=__float_as_uint(sA[(R+g)*PRA+k0+tg]);
        a[mt][1]=__float_as_uint(sA[(R+g+8)*PRA+k0+tg]);
        a[mt][2]=__float_as_uint(sA[(R+g)*PRA+k0+tg+4]);
        a[mt][3]=__float_as_uint(sA[(R+g+8)*PRA+k0+tg+4]);
      }
      #pragma unroll
      for (int nt=0;nt<4;nt++){
        int C = nbase+nt*8;
        bb[nt][0]=__float_as_uint(sB[(C+g)*PRB+k0+tg]);
        bb[nt][1]=__float_as_uint(sB[(C+g)*PRB+k0+tg+4]);
      }
      #pragma unroll
      for (int mt=0;mt<2;mt++)
        #pragma unroll
        for (int nt=0;nt<4;nt++)
          mma_tf32(c[mt][nt], a[mt][0],a[mt][1],a[mt][2],a[mt][3], bb[nt][0],bb[nt][1]);
    }
    if (tid < 64) {
      float s=0.f;
      #pragma unroll 4
      for (int f=0; f<HS; ++f) s += sA[tid*PRA+f]*sZp[f];
      sLn[tid]=s;
    }
  }
  __syncthreads();   // sums + sLn visible

  // ---- epilogue ----
  #pragma unroll
  for (int mt=0;mt<2;mt++)
   #pragma unroll
   for (int half=0;half<2;half++) {
    int r = mbase+mt*16+half*8+g;
    float ssm = sRed[256+r*4+0]+sRed[256+r*4+1]+sRed[256+r*4+2]+sRed[256+r*4+3];
    float inv = 1.f/(ssm + sLn[r]);
    #pragma unroll
    for (int nt=0;nt<4;nt++){
      int col0 = nbase+nt*8+2*tg;
      *(float2*)&out[((size_t)h*TT + b*64 + r)*HS + col0] =
        make_float2(c[mt][nt][half*2+0]*inv, c[mt][nt][half*2+1]*inv);
    }
   }
}

// ---------------------------------------------------------------------------
extern "C" void kernel_launch(void* const* d_in, const int* in_sizes, int n_in,
                              void* d_out, int out_size)
{
  const float* q   = (const float*)d_in[0];
  const float* k   = (const float*)d_in[1];
  const float* v   = (const float*)d_in[2];
  const float* fqw = (const float*)d_in[3];
  const float* fkw = (const float*)d_in[4];
  const float* wfr = (const float*)d_in[5];
  float* out = (float*)d_out;

  // smem: featmap/fkstate = 2*128*68*4 = 69632 B -> 3 CTAs/SM
  // attn = (64*132 + 128*136 + 512 + 128 + 64)*4 = 106240 B -> 2 CTAs/SM
  cudaFuncSetAttribute(featmap_q_kernel, cudaFuncAttributeMaxDynamicSharedMemorySize, 69632);
  cudaFuncSetAttribute(fkstate_kernel,   cudaFuncAttributeMaxDynamicSharedMemorySize, 69632);
  cudaFuncSetAttribute(attn_kernel,      cudaFuncAttributeMaxDynamicSharedMemorySize, 106240);

  featmap_q_kernel<<<dim3(32,32),512,69632>>>(q, fqw);
  fkstate_kernel  <<<dim3(32,32),512,69632>>>(k, v, fkw);
  prefix_kernel   <<<dim3(64,32),256>>>();
  attn_kernel     <<<dim3(32,32),256,106240>>>(q, k, v, wfr, out);
}

// round 15
// speedup vs baseline: 3.7695x; 1.3046x over previous
#include <cuda_runtime.h>
#include <math.h>
#include <stdint.h>

#define TT   2048
#define NH   32
#define NKV  8
#define HS   128
#define FD   64
#define NB   32          // 64-token blocks
#define EPSF 1e-12f
#define SCALE 0.08838834764831845f  // 1/sqrt(128)

#define PRA 132  // row-major A tiles [64][132]
#define PRB 132  // n-major B tiles ([n][k])
#define PRV 136  // k-major B tiles ([k][n]); 136%32=8 -> conflict-free frags
#define PW  72   // k-major W tile [128][72]; 72%32=8 -> conflict-free frags
#define PT  68   // f_k^T tile [128][68]; 68%32=4 -> conflict-free A frags

// scratch (device globals: no runtime allocation allowed)
__device__ float g_fq[NH*TT*HS];          // 33.5 MB
__device__ float g_S [NH*NB*HS*HS];       // 67 MB  per-block KV states, S[f][d]
__device__ float g_z [NH*NB*HS];          // 0.5 MB per-block key sums
__device__ float g_P [NH*NB*HS*HS];       // 67 MB  prefix states, P[f][d]
__device__ float g_zp[NH*NB*HS];          // 0.5 MB per-block prefix key sums

// ---------------------------------------------------------------------------
__device__ __forceinline__ float to_tf32(float x){
  uint32_t u; asm("cvt.rna.tf32.f32 %0, %1;" : "=r"(u) : "f"(x));
  return __uint_as_float(u);
}
__device__ __forceinline__ void st_tf32_4(float* dst, float4 v){
  dst[0]=to_tf32(v.x); dst[1]=to_tf32(v.y); dst[2]=to_tf32(v.z); dst[3]=to_tf32(v.w);
}
__device__ __forceinline__ void mma_tf32(float c[4],
    uint32_t a0,uint32_t a1,uint32_t a2,uint32_t a3, uint32_t b0,uint32_t b1){
  asm volatile("mma.sync.aligned.m16n8k8.row.col.f32.tf32.tf32.f32 "
      "{%0,%1,%2,%3}, {%4,%5,%6,%7}, {%8,%9}, {%0,%1,%2,%3};"
      : "+f"(c[0]),"+f"(c[1]),"+f"(c[2]),"+f"(c[3])
      : "r"(a0),"r"(a1),"r"(a2),"r"(a3),"r"(b0),"r"(b1));
}

// ---------------------------------------------------------------------------
// Kernel 1: feature map for Q via tf32 MMA. grid (32,32), 256 thr, 3 CTAs/SM.
// Z = X @ W (64x64x128), softmax in fragment registers, f -> g_fq (fp32).
// ---------------------------------------------------------------------------
__global__ void __launch_bounds__(256,3) featmap_q_kernel(
    const float* __restrict__ x, const float* __restrict__ w)
{
  extern __shared__ float sm[];
  float* sX   = sm;              // [64][132] tf32 X; later sF fp32 [64][132]
  float* sW   = sX + 64*PRA;     // [128][72] tf32 W (k-major: [d][f])
  float* sRed = sW + 128*PW;     // [512]: mx | mn | sp | sn  (r*2+nb)

  int tile = blockIdx.x, h = blockIdx.y;
  int tid = threadIdx.x;

  for (int i=tid; i<64*32; i+=256){
    int r=i>>5, d4=(i&31)*4;
    float4 v = *(const float4*)&x[(size_t)(tile*64+r)*(NH*HS)+h*HS+d4];
    st_tf32_4(&sX[r*PRA+d4], v);
  }
  for (int i=tid; i<128*16; i+=256){
    int d=i>>4, f4=(i&15)*4;
    float4 v = *(const float4*)&w[(size_t)h*HS*FD + d*FD + f4];
    st_tf32_4(&sW[d*PW+f4], v);
  }
  __syncthreads();

  int wd=tid>>5, lane=tid&31, g=lane>>2, tg=lane&3;
  int mb=wd&3, nb=wd>>2;
  int mbase=mb*16, nbase=nb*32;

  float c[4][4];
  #pragma unroll
  for (int nt=0;nt<4;nt++)
    #pragma unroll
    for (int e=0;e<4;e++) c[nt][e]=0.f;

  #pragma unroll 4
  for (int k0=0;k0<128;k0+=8){
    uint32_t a[4], bb[4][2];
    a[0]=__float_as_uint(sX[(mbase+g)*PRA+k0+tg]);
    a[1]=__float_as_uint(sX[(mbase+g+8)*PRA+k0+tg]);
    a[2]=__float_as_uint(sX[(mbase+g)*PRA+k0+tg+4]);
    a[3]=__float_as_uint(sX[(mbase+g+8)*PRA+k0+tg+4]);
    #pragma unroll
    for (int nt=0;nt<4;nt++){
      int C=nbase+nt*8;
      bb[nt][0]=__float_as_uint(sW[(k0+tg)*PW+C+g]);
      bb[nt][1]=__float_as_uint(sW[(k0+tg+4)*PW+C+g]);
    }
    #pragma unroll
    for (int nt=0;nt<4;nt++)
      mma_tf32(c[nt], a[0],a[1],a[2],a[3], bb[nt][0],bb[nt][1]);
  }

  // ---- band max/min ----
  #pragma unroll
  for (int half=0;half<2;half++){
    int r = mbase + half*8 + g;
    float mx=-1e30f, mn=1e30f;
    #pragma unroll
    for (int nt=0;nt<4;nt++)
      #pragma unroll
      for (int e=0;e<2;e++){
        float z = c[nt][half*2+e];
        mx=fmaxf(mx,z); mn=fminf(mn,z);
      }
    mx=fmaxf(mx,__shfl_xor_sync(0xffffffffu,mx,1,4));
    mx=fmaxf(mx,__shfl_xor_sync(0xffffffffu,mx,2,4));
    mn=fminf(mn,__shfl_xor_sync(0xffffffffu,mn,1,4));
    mn=fminf(mn,__shfl_xor_sync(0xffffffffu,mn,2,4));
    if (tg==0){ sRed[r*2+nb]=mx; sRed[128+r*2+nb]=mn; }
  }
  __syncthreads();   // maxes visible; sX reads (GEMM) all done

  // ---- exps + band sums (p kept in c, n in nn) ----
  float nn[4][4];
  #pragma unroll
  for (int half=0;half<2;half++){
    int r = mbase + half*8 + g;
    float gm = fmaxf(sRed[r*2+0],sRed[r*2+1]);
    float gn = fminf(sRed[128+r*2+0],sRed[128+r*2+1]);
    float sp=0.f, sn=0.f;
    #pragma unroll
    for (int nt=0;nt<4;nt++)
      #pragma unroll
      for (int e=0;e<2;e++){
        float z = c[nt][half*2+e];
        float p=__expf(z-gm), q=__expf(gn-z);
        c[nt][half*2+e]=p; nn[nt][half*2+e]=q;
        sp+=p; sn+=q;
      }
    sp+=__shfl_xor_sync(0xffffffffu,sp,1,4);
    sp+=__shfl_xor_sync(0xffffffffu,sp,2,4);
    sn+=__shfl_xor_sync(0xffffffffu,sn,1,4);
    sn+=__shfl_xor_sync(0xffffffffu,sn,2,4);
    if (tg==0){ sRed[256+r*2+nb]=sp; sRed[384+r*2+nb]=sn; }
  }
  __syncthreads();

  // ---- normalize + clip + write sF (overlay sX) ----
  #pragma unroll
  for (int half=0;half<2;half++){
    int r = mbase + half*8 + g;
    float rp = 1.f/(sRed[256+r*2+0]+sRed[256+r*2+1]);
    float rn = 1.f/(sRed[384+r*2+0]+sRed[384+r*2+1]);
    #pragma unroll
    for (int nt=0;nt<4;nt++){
      int f = nbase+nt*8+2*tg;
      float p0=fmaxf(c[nt][half*2+0]*rp,EPSF), p1=fmaxf(c[nt][half*2+1]*rp,EPSF);
      float q0=fmaxf(nn[nt][half*2+0]*rn,EPSF), q1=fmaxf(nn[nt][half*2+1]*rn,EPSF);
      *(float2*)&sX[r*PRA+f]      = make_float2(p0,p1);
      *(float2*)&sX[r*PRA+FD+f]   = make_float2(q0,q1);
    }
  }
  __syncthreads();

  for (int i=tid; i<64*32; i+=256){
    int t=i>>5, f4=(i&31)*4;
    *(float4*)&g_fq[((size_t)h*TT + tile*64 + t)*HS + f4] = *(const float4*)&sX[t*PRA+f4];
  }
}

// ---------------------------------------------------------------------------
// Kernel 2: FUSED feature map for K + block state via tf32 MMA. 256 thr.
// f_k^T stored [f][t] (tf32); S[f][d] = f_k^T @ V via MMA (V natural k-major).
// ---------------------------------------------------------------------------
__global__ void __launch_bounds__(256,3) fkstate_kernel(
    const float* __restrict__ key, const float* __restrict__ value,
    const float* __restrict__ w)
{
  extern __shared__ float sm[];
  float* sX   = sm;              // [64][132] tf32 K-tile; later sFT [128][68]
  float* sFT  = sm;
  float* sW   = sm + 8704;       // [128][72] tf32 W; later sV [64][136]
  float* sV   = sm + 8704;
  float* sRed = sm + 8704 + 9216; // [512]

  int b = blockIdx.x, h = blockIdx.y;
  int tid = threadIdx.x;
  int kvh = h >> 2;

  for (int i=tid; i<64*32; i+=256){
    int r=i>>5, d4=(i&31)*4;
    float4 v = *(const float4*)&key[(size_t)(b*64+r)*(NKV*HS)+kvh*HS+d4];
    st_tf32_4(&sX[r*PRA+d4], v);
  }
  for (int i=tid; i<128*16; i+=256){
    int d=i>>4, f4=(i&15)*4;
    float4 v = *(const float4*)&w[(size_t)h*HS*FD + d*FD + f4];
    st_tf32_4(&sW[d*PW+f4], v);
  }
  __syncthreads();

  int wd=tid>>5, lane=tid&31, g=lane>>2, tg=lane&3;
  int mb=wd&3, nb=wd>>2;
  int mbase=mb*16, nbase=nb*32;

  float c[4][4];
  #pragma unroll
  for (int nt=0;nt<4;nt++)
    #pragma unroll
    for (int e=0;e<4;e++) c[nt][e]=0.f;

  #pragma unroll 4
  for (int k0=0;k0<128;k0+=8){
    uint32_t a[4], bb[4][2];
    a[0]=__float_as_uint(sX[(mbase+g)*PRA+k0+tg]);
    a[1]=__float_as_uint(sX[(mbase+g+8)*PRA+k0+tg]);
    a[2]=__float_as_uint(sX[(mbase+g)*PRA+k0+tg+4]);
    a[3]=__float_as_uint(sX[(mbase+g+8)*PRA+k0+tg+4]);
    #pragma unroll
    for (int nt=0;nt<4;nt++){
      int C=nbase+nt*8;
      bb[nt][0]=__float_as_uint(sW[(k0+tg)*PW+C+g]);
      bb[nt][1]=__float_as_uint(sW[(k0+tg+4)*PW+C+g]);
    }
    #pragma unroll
    for (int nt=0;nt<4;nt++)
      mma_tf32(c[nt], a[0],a[1],a[2],a[3], bb[nt][0],bb[nt][1]);
  }

  #pragma unroll
  for (int half=0;half<2;half++){
    int r = mbase + half*8 + g;
    float mx=-1e30f, mn=1e30f;
    #pragma unroll
    for (int nt=0;nt<4;nt++)
      #pragma unroll
      for (int e=0;e<2;e++){
        float z = c[nt][half*2+e];
        mx=fmaxf(mx,z); mn=fminf(mn,z);
      }
    mx=fmaxf(mx,__shfl_xor_sync(0xffffffffu,mx,1,4));
    mx=fmaxf(mx,__shfl_xor_sync(0xffffffffu,mx,2,4));
    mn=fminf(mn,__shfl_xor_sync(0xffffffffu,mn,1,4));
    mn=fminf(mn,__shfl_xor_sync(0xffffffffu,mn,2,4));
    if (tg==0){ sRed[r*2+nb]=mx; sRed[128+r*2+nb]=mn; }
  }
  __syncthreads();   // sW reads (GEMM) done -> sV overlay legal below

  float nn[4][4];
  #pragma unroll
  for (int half=0;half<2;half++){
    int r = mbase + half*8 + g;
    float gm = fmaxf(sRed[r*2+0],sRed[r*2+1]);
    float gn = fminf(sRed[128+r*2+0],sRed[128+r*2+1]);
    float sp=0.f, sn=0.f;
    #pragma unroll
    for (int nt=0;nt<4;nt++)
      #pragma unroll
      for (int e=0;e<2;e++){
        float z = c[nt][half*2+e];
        float p=__expf(z-gm), q=__expf(gn-z);
        c[nt][half*2+e]=p; nn[nt][half*2+e]=q;
        sp+=p; sn+=q;
      }
    sp+=__shfl_xor_sync(0xffffffffu,sp,1,4);
    sp+=__shfl_xor_sync(0xffffffffu,sp,2,4);
    sn+=__shfl_xor_sync(0xffffffffu,sn,1,4);
    sn+=__shfl_xor_sync(0xffffffffu,sn,2,4);
    if (tg==0){ sRed[256+r*2+nb]=sp; sRed[384+r*2+nb]=sn; }
  }
  // V load (overlay sW, dead since GEMM) — natural [t][d], tf32, pad 136
  for (int i=tid; i<64*32; i+=256){
    int t=i>>5, d4=(i&31)*4;
    float4 v = *(const float4*)&value[(size_t)(b*64+t)*(NKV*HS)+kvh*HS+d4];
    st_tf32_4(&sV[t*PRV+d4], v);
  }
  __syncthreads();

  // normalize + clip + write f_k^T (tf32) into sFT [f][t]  (overlay sX, dead)
  #pragma unroll
  for (int half=0;half<2;half++){
    int r = mbase + half*8 + g;
    float rp = 1.f/(sRed[256+r*2+0]+sRed[256+r*2+1]);
    float rn = 1.f/(sRed[384+r*2+0]+sRed[384+r*2+1]);
    #pragma unroll
    for (int nt=0;nt<4;nt++)
      #pragma unroll
      for (int e=0;e<2;e++){
        int f = nbase+nt*8+2*tg+e;
        sFT[f*PT + r]      = to_tf32(fmaxf(c[nt][half*2+e]*rp,EPSF));
        sFT[(FD+f)*PT + r] = to_tf32(fmaxf(nn[nt][half*2+e]*rn,EPSF));
      }
  }
  __syncthreads();

  // ---- S[f][d] = f_k^T @ V : output 128x128, 8 warps x (32x64), 2 n-passes
  {
    float* Sout = g_S + ((size_t)h*NB + b)*HS*HS;
    #pragma unroll
    for (int pass=0; pass<2; ++pass){
      int nbase2 = nb*64 + pass*32;
      float cc[2][4][4];
      #pragma unroll
      for (int mt=0;mt<2;mt++)
        #pragma unroll
        for (int nt=0;nt<4;nt++)
          #pragma unroll
          for (int e=0;e<4;e++) cc[mt][nt][e]=0.f;
      #pragma unroll
      for (int k0=0;k0<64;k0+=8){
        uint32_t a[2][4], bb[4][2];
        #pragma unroll
        for (int mt=0;mt<2;mt++){
          int R = mb*32 + mt*16;
          a[mt][0]=__float_as_uint(sFT[(R+g)*PT+k0+tg]);
          a[mt][1]=__float_as_uint(sFT[(R+g+8)*PT+k0+tg]);
          a[mt][2]=__float_as_uint(sFT[(R+g)*PT+k0+tg+4]);
          a[mt][3]=__float_as_uint(sFT[(R+g+8)*PT+k0+tg+4]);
        }
        #pragma unroll
        for (int nt=0;nt<4;nt++){
          int C = nbase2+nt*8;
          bb[nt][0]=__float_as_uint(sV[(k0+tg)*PRV + C+g]);
          bb[nt][1]=__float_as_uint(sV[(k0+tg+4)*PRV + C+g]);
        }
        #pragma unroll
        for (int mt=0;mt<2;mt++)
          #pragma unroll
          for (int nt=0;nt<4;nt++)
            mma_tf32(cc[mt][nt], a[mt][0],a[mt][1],a[mt][2],a[mt][3], bb[nt][0],bb[nt][1]);
      }
      #pragma unroll
      for (int mt=0;mt<2;mt++)
        #pragma unroll
        for (int half=0;half<2;half++){
          int f = mb*32 + mt*16 + half*8 + g;
          #pragma unroll
          for (int nt=0;nt<4;nt++){
            int d = nbase2+nt*8+2*tg;
            *(float2*)&Sout[f*HS + d] =
              make_float2(cc[mt][nt][half*2+0], cc[mt][nt][half*2+1]);
          }
        }
    }
  }
  // z_b[f] = sum_t f_k[t][f]  (row sums of sFT)
  if (tid < HS){
    float z=0.f;
    #pragma unroll 4
    for (int t=0;t<64;++t) z += sFT[tid*PT+t];
    g_z[((size_t)h*NB+b)*HS + tid] = z;
  }
}

// ---------------------------------------------------------------------------
// Kernel 3: prefix over S (elementwise, layout-agnostic).
// ---------------------------------------------------------------------------
__global__ void __launch_bounds__(256) prefix_kernel()
{
  int h = blockIdx.y;
  int e = blockIdx.x*256 + threadIdx.x;  // 0..16383
  float acc = 0.f;
  for (int j = 0; j <= NB-3; ++j) {
    acc += g_S[((size_t)h*NB + j)*HS*HS + e];
    g_P[((size_t)h*NB + j+2)*HS*HS + e] = acc;
  }
  if (blockIdx.x == 0 && threadIdx.x < HS) {
    float az = 0.f;
    for (int j = 0; j <= NB-3; ++j) {
      az += g_z[((size_t)h*NB + j)*HS + threadIdx.x];
      g_zp[((size_t)h*NB + j+2)*HS + threadIdx.x] = az;
    }
  }
}

// ---------------------------------------------------------------------------
// Kernel 4: main attention via tf32 mma.sync (m16n8k8).  (R13, with prefix
// B-operand switched to k-major load of P[f][d].)
// ---------------------------------------------------------------------------
__global__ void __launch_bounds__(256,2) attn_kernel(
    const float* __restrict__ query, const float* __restrict__ key,
    const float* __restrict__ value, const float* __restrict__ wfraw,
    float* __restrict__ out)
{
  extern __shared__ float sm[];
  float* sA   = sm;                 // [64][132]  tf32 Q -> probs -> fq
  float* sB   = sA + 64*PRA;        // [128][136] tf32 K(132) -> V(136) -> P(136)
  float* sRed = sB + 128*PRV;       // [512]
  float* sZp  = sRed + 512;         // [128]
  float* sLn  = sZp + 128;          // [64]

  int b = blockIdx.x, h = blockIdx.y;
  int tid = threadIdx.x;
  int kvh = h >> 2;
  float wf = 1.f/(1.f+__expf(-wfraw[h]));

  int w = tid >> 5, lane = tid & 31;
  int g = lane >> 2, tg = lane & 3;
  int mb = w & 1, nb = w >> 1;
  int mbase = mb*32, nbase = nb*32;

  if (tid < 64) sLn[tid] = 0.f;

  // ---- L1: tf32(Q), tf32(K) n-major; zp ----
  for (int i = tid; i < 64*32; i += 256) {
    int r = i >> 5, d4 = (i & 31)*4;
    float4 v = *(const float4*)&query[(size_t)(b*64+r)*(NH*HS) + h*HS + d4];
    st_tf32_4(&sA[r*PRA+d4], v);
  }
  for (int i = tid; i < 128*32; i += 256) {
    int r = i >> 5, d4 = (i & 31)*4;
    float4 v;
    if (r < 64) {
      if (b == 0) v = make_float4(0.f,0.f,0.f,0.f);
      else v = *(const float4*)&key[(size_t)((b-1)*64+r)*(NKV*HS)+kvh*HS+d4];
    } else {
      v = *(const float4*)&key[(size_t)(b*64+(r-64))*(NKV*HS)+kvh*HS+d4];
    }
    st_tf32_4(&sB[r*PRB+d4], v);
  }
  if (b >= 2 && tid < HS) sZp[tid] = g_zp[((size_t)h*NB+b)*HS+tid];
  __syncthreads();

  // ---- G1: scores = Q @ K^T ----
  float c[2][4][4];
  #pragma unroll
  for (int mt=0;mt<2;mt++)
    #pragma unroll
    for (int nt=0;nt<4;nt++)
      #pragma unroll
      for (int e=0;e<4;e++) c[mt][nt][e]=0.f;

  #pragma unroll 4
  for (int k0=0;k0<128;k0+=8) {
    uint32_t a[2][4], bb[4][2];
    #pragma unroll
    for (int mt=0;mt<2;mt++){
      int R = mbase+mt*16;
      a[mt][0]=__float_as_uint(sA[(R+g)*PRA+k0+tg]);
      a[mt][1]=__float_as_uint(sA[(R+g+8)*PRA+k0+tg]);
      a[mt][2]=__float_as_uint(sA[(R+g)*PRA+k0+tg+4]);
      a[mt][3]=__float_as_uint(sA[(R+g+8)*PRA+k0+tg+4]);
    }
    #pragma unroll
    for (int nt=0;nt<4;nt++){
      int C = nbase+nt*8;
      bb[nt][0]=__float_as_uint(sB[(C+g)*PRB+k0+tg]);
      bb[nt][1]=__float_as_uint(sB[(C+g)*PRB+k0+tg+4]);
    }
    #pragma unroll
    for (int mt=0;mt<2;mt++)
      #pragma unroll
      for (int nt=0;nt<4;nt++)
        mma_tf32(c[mt][nt], a[mt][0],a[mt][1],a[mt][2],a[mt][3], bb[nt][0],bb[nt][1]);
  }

  // ---- softmax: band max ----
  #pragma unroll
  for (int mt=0;mt<2;mt++)
   #pragma unroll
   for (int half=0;half<2;half++) {
    int r = mbase+mt*16+half*8+g;
    float mx = -1e30f;
    #pragma unroll
    for (int nt=0;nt<4;nt++)
      #pragma unroll
      for (int e=0;e<2;e++) {
        int col = nbase+nt*8+2*tg+e;
        float s = c[mt][nt][half*2+e]*SCALE;
        c[mt][nt][half*2+e]=s;
        bool ok = (col<64) ? (b>0) : ((col-64)<=r);
        if (ok) mx = fmaxf(mx, s);
      }
    mx = fmaxf(mx, __shfl_xor_sync(0xffffffffu, mx, 1, 4));
    mx = fmaxf(mx, __shfl_xor_sync(0xffffffffu, mx, 2, 4));
    if (tg==0) sRed[r*4+nb]=mx;
   }
  __syncthreads();

  // ---- exp + band sums; probs (tf32) -> sA; tf32(V) -> sB ----
  #pragma unroll
  for (int mt=0;mt<2;mt++)
   #pragma unroll
   for (int half=0;half<2;half++) {
    int r = mbase+mt*16+half*8+g;
    float gm = fmaxf(fmaxf(sRed[r*4+0],sRed[r*4+1]),fmaxf(sRed[r*4+2],sRed[r*4+3]));
    float sum=0.f;
    #pragma unroll
    for (int nt=0;nt<4;nt++){
      int col0 = nbase+nt*8+2*tg;
      bool ok0 = (col0  <64) ? (b>0) : ((col0  -64)<=r);
      bool ok1 = (col0+1<64) ? (b>0) : ((col0+1-64)<=r);
      float p0 = ok0 ? to_tf32(wf*__expf(c[mt][nt][half*2+0]-gm)) : 0.f;
      float p1 = ok1 ? to_tf32(wf*__expf(c[mt][nt][half*2+1]-gm)) : 0.f;
      sum += p0+p1;
      *(float2*)&sA[r*PRA + col0] = make_float2(p0,p1);
    }
    sum += __shfl_xor_sync(0xffffffffu,sum,1,4);
    sum += __shfl_xor_sync(0xffffffffu,sum,2,4);
    if (tg==0) sRed[256 + r*4+nb]=sum;
   }
  for (int i = tid; i < 128*32; i += 256) {
    int r = i >> 5, d4 = (i & 31)*4;
    float4 v;
    if (r < 64) {
      if (b == 0) v = make_float4(0.f,0.f,0.f,0.f);
      else v = *(const float4*)&value[(size_t)((b-1)*64+r)*(NKV*HS)+kvh*HS+d4];
    } else {
      v = *(const float4*)&value[(size_t)(b*64+(r-64))*(NKV*HS)+kvh*HS+d4];
    }
    st_tf32_4(&sB[r*PRV+d4], v);
  }
  #pragma unroll
  for (int mt=0;mt<2;mt++)
    #pragma unroll
    for (int nt=0;nt<4;nt++)
      #pragma unroll
      for (int e=0;e<4;e++) c[mt][nt][e]=0.f;
  __syncthreads();

  // ---- G2: y = P @ V ----
  #pragma unroll 4
  for (int k0=0;k0<128;k0+=8) {
    uint32_t a[2][4], bb[4][2];
    #pragma unroll
    for (int mt=0;mt<2;mt++){
      int R = mbase+mt*16;
      a[mt][0]=__float_as_uint(sA[(R+g)*PRA+k0+tg]);
      a[mt][1]=__float_as_uint(sA[(R+g+8)*PRA+k0+tg]);
      a[mt][2]=__float_as_uint(sA[(R+g)*PRA+k0+tg+4]);
      a[mt][3]=__float_as_uint(sA[(R+g+8)*PRA+k0+tg+4]);
    }
    #pragma unroll
    for (int nt=0;nt<4;nt++){
      int C = nbase+nt*8;
      bb[nt][0]=__float_as_uint(sB[(k0+tg  )*PRV + C+g]);
      bb[nt][1]=__float_as_uint(sB[(k0+tg+4)*PRV + C+g]);
    }
    #pragma unroll
    for (int mt=0;mt<2;mt++)
      #pragma unroll
      for (int nt=0;nt<4;nt++)
        mma_tf32(c[mt][nt], a[mt][0],a[mt][1],a[mt][2],a[mt][3], bb[nt][0],bb[nt][1]);
  }

  // ---- prefix: y += fq @ P ; sum_ln = fq . zp ----
  if (b >= 2) {
    __syncthreads();
    for (int i = tid; i < 64*32; i += 256) {
      int r = i >> 5, d4 = (i & 31)*4;
      float4 v = *(const float4*)&g_fq[((size_t)h*TT + b*64 + r)*HS + d4];
      st_tf32_4(&sA[r*PRA+d4], v);
    }
    const float* P = g_P + ((size_t)h*NB + b)*HS*HS;   // P[f][d], k-major B
    for (int i = tid; i < 128*32; i += 256) {
      int r = i >> 5, d4 = (i & 31)*4;
      float4 v = *(const float4*)&P[r*HS + d4];
      st_tf32_4(&sB[r*PRV+d4], v);
    }
    __syncthreads();

    #pragma unroll 4
    for (int k0=0;k0<128;k0+=8) {
      uint32_t a[2][4], bb[4][2];
      #pragma unroll
      for (int mt=0;mt<2;mt++){
        int R = mbase+mt*16;
        a[mt][0]=__float_as_uint(sA[(R+g)*PRA+k0+tg]);
        a[mt][1]=__float_as_uint(sA[(R+g+8)*PRA+k0+tg]);
        a[mt][2]=__float_as_uint(sA[(R+g)*PRA+k0+tg+4]);
        a[mt][3]=__float_as_uint(sA[(R+g+8)*PRA+k0+tg+4]);
      }
      #pragma unroll
      for (int nt=0;nt<4;nt++){
        int C = nbase+nt*8;
        bb[nt][0]=__float_as_uint(sB[(k0+tg  )*PRV + C+g]);
        bb[nt][1]=__float_as_uint(sB[(k0+tg+4)*PRV + C+g]);
      }
      #pragma unroll
      for (int mt=0;mt<2;mt++)
        #pragma unroll
        for (int nt=0;nt<4;nt++)
          mma_tf32(c[mt][nt], a[mt][0],a[mt][1],a[mt][2],a[mt][3], bb[nt][0],bb[nt][1]);
    }
    if (tid < 64) {
      float s=0.f;
      #pragma unroll 4
      for (int f=0; f<HS; ++f) s += sA[tid*PRA+f]*sZp[f];
      sLn[tid]=s;
    }
  }
  __syncthreads();

  // ---- epilogue ----
  #pragma unroll
  for (int mt=0;mt<2;mt++)
   #pragma unroll
   for (int half=0;half<2;half++) {
    int r = mbase+mt*16+half*8+g;
    float ssm = sRed[256+r*4+0]+sRed[256+r*4+1]+sRed[256+r*4+2]+sRed[256+r*4+3];
    float inv = 1.f/(ssm + sLn[r]);
    #pragma unroll
    for (int nt=0;nt<4;nt++){
      int col0 = nbase+nt*8+2*tg;
      *(float2*)&out[((size_t)h*TT + b*64 + r)*HS + col0] =
        make_float2(c[mt][nt][half*2+0]*inv, c[mt][nt][half*2+1]*inv);
    }
   }
}

// ---------------------------------------------------------------------------
extern "C" void kernel_launch(void* const* d_in, const int* in_sizes, int n_in,
                              void* d_out, int out_size)
{
  const float* q   = (const float*)d_in[0];
  const float* k   = (const float*)d_in[1];
  const float* v   = (const float*)d_in[2];
  const float* fqw = (const float*)d_in[3];
  const float* fkw = (const float*)d_in[4];
  const float* wfr = (const float*)d_in[5];
  float* out = (float*)d_out;

  // smem: featmap_q = (64*132 + 128*72 + 512)*4 = 72704 B -> 3 CTAs/SM
  // fkstate = (8704 + 9216 + 512)*4 = 73728 B -> 3 CTAs/SM
  // attn = (64*132 + 128*136 + 512 + 128 + 64)*4 = 106240 B -> 2 CTAs/SM
  cudaFuncSetAttribute(featmap_q_kernel, cudaFuncAttributeMaxDynamicSharedMemorySize, 72704);
  cudaFuncSetAttribute(fkstate_kernel,   cudaFuncAttributeMaxDynamicSharedMemorySize, 73728);
  cudaFuncSetAttribute(attn_kernel,      cudaFuncAttributeMaxDynamicSharedMemorySize, 106240);

  featmap_q_kernel<<<dim3(32,32),256,72704>>>(q, fqw);
  fkstate_kernel  <<<dim3(32,32),256,73728>>>(k, v, fkw);
  prefix_kernel   <<<dim3(64,32),256>>>();
  attn_kernel     <<<dim3(32,32),256,106240>>>(q, k, v, wfr, out);
}

// round 16
// speedup vs baseline: 4.3825x; 1.1626x over previous
#include <cuda_runtime.h>
#include <math.h>
#include <stdint.h>

#define TT   2048
#define NH   32
#define NKV  8
#define HS   128
#define FD   64
#define NB   32          // 64-token blocks
#define EPSF 1e-12f
#define SCALE 0.08838834764831845f  // 1/sqrt(128)

#define PRA 132  // row-major A tiles [64][132]
#define PRB 132  // n-major B tiles ([n][k])
#define PRV 136  // k-major B tiles ([k][n]); 136%32=8 -> conflict-free frags
#define PW  72   // k-major W tile [128][72]; 72%32=8 -> conflict-free frags
#define PT  68   // f_k^T tile [128][68]; 68%32=4 -> conflict-free A frags

// scratch (device globals: no runtime allocation allowed)
__device__ float g_fq[NH*TT*HS];          // 33.5 MB
__device__ float g_S [NH*NB*HS*HS];       // 67 MB  per-block KV states, S[f][d]
__device__ float g_z [NH*NB*HS];          // 0.5 MB per-block key sums
__device__ float g_P [NH*NB*HS*HS];       // 67 MB  prefix states, P[f][d]
__device__ float g_zp[NH*NB*HS];          // 0.5 MB per-block prefix key sums

// ---------------------------------------------------------------------------
__device__ __forceinline__ float to_tf32(float x){
  uint32_t u; asm("cvt.rna.tf32.f32 %0, %1;" : "=r"(u) : "f"(x));
  return __uint_as_float(u);
}
__device__ __forceinline__ void st_tf32_4(float* dst, float4 v){
  dst[0]=to_tf32(v.x); dst[1]=to_tf32(v.y); dst[2]=to_tf32(v.z); dst[3]=to_tf32(v.w);
}
__device__ __forceinline__ void mma_tf32(float c[4],
    uint32_t a0,uint32_t a1,uint32_t a2,uint32_t a3, uint32_t b0,uint32_t b1){
  asm volatile("mma.sync.aligned.m16n8k8.row.col.f32.tf32.tf32.f32 "
      "{%0,%1,%2,%3}, {%4,%5,%6,%7}, {%8,%9}, {%0,%1,%2,%3};"
      : "+f"(c[0]),"+f"(c[1]),"+f"(c[2]),"+f"(c[3])
      : "r"(a0),"r"(a1),"r"(a2),"r"(a3),"r"(b0),"r"(b1));
}

// ---------------------------------------------------------------------------
// Kernel 1: feature map for Q via tf32 MMA. grid (32,32), 256 thr, 3 CTAs/SM.
// ---------------------------------------------------------------------------
__global__ void __launch_bounds__(256,3) featmap_q_kernel(
    const float* __restrict__ x, const float* __restrict__ w)
{
  extern __shared__ float sm[];
  float* sX   = sm;              // [64][132] tf32 X; later sF fp32 [64][132]
  float* sW   = sX + 64*PRA;     // [128][72] tf32 W (k-major: [d][f])
  float* sRed = sW + 128*PW;     // [512]: mx | mn | sp | sn  (r*2+nb)

  int tile = blockIdx.x, h = blockIdx.y;
  int tid = threadIdx.x;

  for (int i=tid; i<64*32; i+=256){
    int r=i>>5, d4=(i&31)*4;
    float4 v = *(const float4*)&x[(size_t)(tile*64+r)*(NH*HS)+h*HS+d4];
    st_tf32_4(&sX[r*PRA+d4], v);
  }
  for (int i=tid; i<128*16; i+=256){
    int d=i>>4, f4=(i&15)*4;
    float4 v = *(const float4*)&w[(size_t)h*HS*FD + d*FD + f4];
    st_tf32_4(&sW[d*PW+f4], v);
  }
  __syncthreads();

  int wd=tid>>5, lane=tid&31, g=lane>>2, tg=lane&3;
  int mb=wd&3, nb=wd>>2;
  int mbase=mb*16, nbase=nb*32;

  float c[4][4];
  #pragma unroll
  for (int nt=0;nt<4;nt++)
    #pragma unroll
    for (int e=0;e<4;e++) c[nt][e]=0.f;

  #pragma unroll 4
  for (int k0=0;k0<128;k0+=8){
    uint32_t a[4], bb[4][2];
    a[0]=__float_as_uint(sX[(mbase+g)*PRA+k0+tg]);
    a[1]=__float_as_uint(sX[(mbase+g+8)*PRA+k0+tg]);
    a[2]=__float_as_uint(sX[(mbase+g)*PRA+k0+tg+4]);
    a[3]=__float_as_uint(sX[(mbase+g+8)*PRA+k0+tg+4]);
    #pragma unroll
    for (int nt=0;nt<4;nt++){
      int C=nbase+nt*8;
      bb[nt][0]=__float_as_uint(sW[(k0+tg)*PW+C+g]);
      bb[nt][1]=__float_as_uint(sW[(k0+tg+4)*PW+C+g]);
    }
    #pragma unroll
    for (int nt=0;nt<4;nt++)
      mma_tf32(c[nt], a[0],a[1],a[2],a[3], bb[nt][0],bb[nt][1]);
  }

  // ---- band max/min ----
  #pragma unroll
  for (int half=0;half<2;half++){
    int r = mbase + half*8 + g;
    float mx=-1e30f, mn=1e30f;
    #pragma unroll
    for (int nt=0;nt<4;nt++)
      #pragma unroll
      for (int e=0;e<2;e++){
        float z = c[nt][half*2+e];
        mx=fmaxf(mx,z); mn=fminf(mn,z);
      }
    mx=fmaxf(mx,__shfl_xor_sync(0xffffffffu,mx,1,4));
    mx=fmaxf(mx,__shfl_xor_sync(0xffffffffu,mx,2,4));
    mn=fminf(mn,__shfl_xor_sync(0xffffffffu,mn,1,4));
    mn=fminf(mn,__shfl_xor_sync(0xffffffffu,mn,2,4));
    if (tg==0){ sRed[r*2+nb]=mx; sRed[128+r*2+nb]=mn; }
  }
  __syncthreads();

  // ---- exps + band sums ----
  float nn[4][4];
  #pragma unroll
  for (int half=0;half<2;half++){
    int r = mbase + half*8 + g;
    float gm = fmaxf(sRed[r*2+0],sRed[r*2+1]);
    float gn = fminf(sRed[128+r*2+0],sRed[128+r*2+1]);
    float sp=0.f, sn=0.f;
    #pragma unroll
    for (int nt=0;nt<4;nt++)
      #pragma unroll
      for (int e=0;e<2;e++){
        float z = c[nt][half*2+e];
        float p=__expf(z-gm), q=__expf(gn-z);
        c[nt][half*2+e]=p; nn[nt][half*2+e]=q;
        sp+=p; sn+=q;
      }
    sp+=__shfl_xor_sync(0xffffffffu,sp,1,4);
    sp+=__shfl_xor_sync(0xffffffffu,sp,2,4);
    sn+=__shfl_xor_sync(0xffffffffu,sn,1,4);
    sn+=__shfl_xor_sync(0xffffffffu,sn,2,4);
    if (tg==0){ sRed[256+r*2+nb]=sp; sRed[384+r*2+nb]=sn; }
  }
  __syncthreads();

  // ---- normalize + clip + write sF (overlay sX) ----
  #pragma unroll
  for (int half=0;half<2;half++){
    int r = mbase + half*8 + g;
    float rp = 1.f/(sRed[256+r*2+0]+sRed[256+r*2+1]);
    float rn = 1.f/(sRed[384+r*2+0]+sRed[384+r*2+1]);
    #pragma unroll
    for (int nt=0;nt<4;nt++){
      int f = nbase+nt*8+2*tg;
      float p0=fmaxf(c[nt][half*2+0]*rp,EPSF), p1=fmaxf(c[nt][half*2+1]*rp,EPSF);
      float q0=fmaxf(nn[nt][half*2+0]*rn,EPSF), q1=fmaxf(nn[nt][half*2+1]*rn,EPSF);
      *(float2*)&sX[r*PRA+f]      = make_float2(p0,p1);
      *(float2*)&sX[r*PRA+FD+f]   = make_float2(q0,q1);
    }
  }
  __syncthreads();

  for (int i=tid; i<64*32; i+=256){
    int t=i>>5, f4=(i&31)*4;
    *(float4*)&g_fq[((size_t)h*TT + tile*64 + t)*HS + f4] = *(const float4*)&sX[t*PRA+f4];
  }
}

// ---------------------------------------------------------------------------
// Kernel 2: FUSED feature map for K + block state via tf32 MMA. 256 thr.
// ---------------------------------------------------------------------------
__global__ void __launch_bounds__(256,3) fkstate_kernel(
    const float* __restrict__ key, const float* __restrict__ value,
    const float* __restrict__ w)
{
  extern __shared__ float sm[];
  float* sX   = sm;              // [64][132] tf32 K-tile; later sFT [128][68]
  float* sFT  = sm;
  float* sW   = sm + 8704;       // [128][72] tf32 W; later sV [64][136]
  float* sV   = sm + 8704;
  float* sRed = sm + 8704 + 9216; // [512]

  int b = blockIdx.x, h = blockIdx.y;
  int tid = threadIdx.x;
  int kvh = h >> 2;

  for (int i=tid; i<64*32; i+=256){
    int r=i>>5, d4=(i&31)*4;
    float4 v = *(const float4*)&key[(size_t)(b*64+r)*(NKV*HS)+kvh*HS+d4];
    st_tf32_4(&sX[r*PRA+d4], v);
  }
  for (int i=tid; i<128*16; i+=256){
    int d=i>>4, f4=(i&15)*4;
    float4 v = *(const float4*)&w[(size_t)h*HS*FD + d*FD + f4];
    st_tf32_4(&sW[d*PW+f4], v);
  }
  __syncthreads();

  int wd=tid>>5, lane=tid&31, g=lane>>2, tg=lane&3;
  int mb=wd&3, nb=wd>>2;
  int mbase=mb*16, nbase=nb*32;

  float c[4][4];
  #pragma unroll
  for (int nt=0;nt<4;nt++)
    #pragma unroll
    for (int e=0;e<4;e++) c[nt][e]=0.f;

  #pragma unroll 4
  for (int k0=0;k0<128;k0+=8){
    uint32_t a[4], bb[4][2];
    a[0]=__float_as_uint(sX[(mbase+g)*PRA+k0+tg]);
    a[1]=__float_as_uint(sX[(mbase+g+8)*PRA+k0+tg]);
    a[2]=__float_as_uint(sX[(mbase+g)*PRA+k0+tg+4]);
    a[3]=__float_as_uint(sX[(mbase+g+8)*PRA+k0+tg+4]);
    #pragma unroll
    for (int nt=0;nt<4;nt++){
      int C=nbase+nt*8;
      bb[nt][0]=__float_as_uint(sW[(k0+tg)*PW+C+g]);
      bb[nt][1]=__float_as_uint(sW[(k0+tg+4)*PW+C+g]);
    }
    #pragma unroll
    for (int nt=0;nt<4;nt++)
      mma_tf32(c[nt], a[0],a[1],a[2],a[3], bb[nt][0],bb[nt][1]);
  }

  #pragma unroll
  for (int half=0;half<2;half++){
    int r = mbase + half*8 + g;
    float mx=-1e30f, mn=1e30f;
    #pragma unroll
    for (int nt=0;nt<4;nt++)
      #pragma unroll
      for (int e=0;e<2;e++){
        float z = c[nt][half*2+e];
        mx=fmaxf(mx,z); mn=fminf(mn,z);
      }
    mx=fmaxf(mx,__shfl_xor_sync(0xffffffffu,mx,1,4));
    mx=fmaxf(mx,__shfl_xor_sync(0xffffffffu,mx,2,4));
    mn=fminf(mn,__shfl_xor_sync(0xffffffffu,mn,1,4));
    mn=fminf(mn,__shfl_xor_sync(0xffffffffu,mn,2,4));
    if (tg==0){ sRed[r*2+nb]=mx; sRed[128+r*2+nb]=mn; }
  }
  __syncthreads();   // sW reads (GEMM) done -> sV overlay legal below

  float nn[4][4];
  #pragma unroll
  for (int half=0;half<2;half++){
    int r = mbase + half*8 + g;
    float gm = fmaxf(sRed[r*2+0],sRed[r*2+1]);
    float gn = fminf(sRed[128+r*2+0],sRed[128+r*2+1]);
    float sp=0.f, sn=0.f;
    #pragma unroll
    for (int nt=0;nt<4;nt++)
      #pragma unroll
      for (int e=0;e<2;e++){
        float z = c[nt][half*2+e];
        float p=__expf(z-gm), q=__expf(gn-z);
        c[nt][half*2+e]=p; nn[nt][half*2+e]=q;
        sp+=p; sn+=q;
      }
    sp+=__shfl_xor_sync(0xffffffffu,sp,1,4);
    sp+=__shfl_xor_sync(0xffffffffu,sp,2,4);
    sn+=__shfl_xor_sync(0xffffffffu,sn,1,4);
    sn+=__shfl_xor_sync(0xffffffffu,sn,2,4);
    if (tg==0){ sRed[256+r*2+nb]=sp; sRed[384+r*2+nb]=sn; }
  }
  for (int i=tid; i<64*32; i+=256){
    int t=i>>5, d4=(i&31)*4;
    float4 v = *(const float4*)&value[(size_t)(b*64+t)*(NKV*HS)+kvh*HS+d4];
    st_tf32_4(&sV[t*PRV+d4], v);
  }
  __syncthreads();

  #pragma unroll
  for (int half=0;half<2;half++){
    int r = mbase + half*8 + g;
    float rp = 1.f/(sRed[256+r*2+0]+sRed[256+r*2+1]);
    float rn = 1.f/(sRed[384+r*2+0]+sRed[384+r*2+1]);
    #pragma unroll
    for (int nt=0;nt<4;nt++)
      #pragma unroll
      for (int e=0;e<2;e++){
        int f = nbase+nt*8+2*tg+e;
        sFT[f*PT + r]      = to_tf32(fmaxf(c[nt][half*2+e]*rp,EPSF));
        sFT[(FD+f)*PT + r] = to_tf32(fmaxf(nn[nt][half*2+e]*rn,EPSF));
      }
  }
  __syncthreads();

  // ---- S[f][d] = f_k^T @ V : output 128x128, 8 warps x (32x64), 2 n-passes
  {
    float* Sout = g_S + ((size_t)h*NB + b)*HS*HS;
    #pragma unroll
    for (int pass=0; pass<2; ++pass){
      int nbase2 = nb*64 + pass*32;
      float cc[2][4][4];
      #pragma unroll
      for (int mt=0;mt<2;mt++)
        #pragma unroll
        for (int nt=0;nt<4;nt++)
          #pragma unroll
          for (int e=0;e<4;e++) cc[mt][nt][e]=0.f;
      #pragma unroll
      for (int k0=0;k0<64;k0+=8){
        uint32_t a[2][4], bb[4][2];
        #pragma unroll
        for (int mt=0;mt<2;mt++){
          int R = mb*32 + mt*16;
          a[mt][0]=__float_as_uint(sFT[(R+g)*PT+k0+tg]);
          a[mt][1]=__float_as_uint(sFT[(R+g+8)*PT+k0+tg]);
          a[mt][2]=__float_as_uint(sFT[(R+g)*PT+k0+tg+4]);
          a[mt][3]=__float_as_uint(sFT[(R+g+8)*PT+k0+tg+4]);
        }
        #pragma unroll
        for (int nt=0;nt<4;nt++){
          int C = nbase2+nt*8;
          bb[nt][0]=__float_as_uint(sV[(k0+tg)*PRV + C+g]);
          bb[nt][1]=__float_as_uint(sV[(k0+tg+4)*PRV + C+g]);
        }
        #pragma unroll
        for (int mt=0;mt<2;mt++)
          #pragma unroll
          for (int nt=0;nt<4;nt++)
            mma_tf32(cc[mt][nt], a[mt][0],a[mt][1],a[mt][2],a[mt][3], bb[nt][0],bb[nt][1]);
      }
      #pragma unroll
      for (int mt=0;mt<2;mt++)
        #pragma unroll
        for (int half=0;half<2;half++){
          int f = mb*32 + mt*16 + half*8 + g;
          #pragma unroll
          for (int nt=0;nt<4;nt++){
            int d = nbase2+nt*8+2*tg;
            *(float2*)&Sout[f*HS + d] =
              make_float2(cc[mt][nt][half*2+0], cc[mt][nt][half*2+1]);
          }
        }
    }
  }
  if (tid < HS){
    float z=0.f;
    #pragma unroll 4
    for (int t=0;t<64;++t) z += sFT[tid*PT+t];
    g_z[((size_t)h*NB+b)*HS + tid] = z;
  }
}

// ---------------------------------------------------------------------------
// Kernel 3: prefix over S (elementwise, layout-agnostic).
// ---------------------------------------------------------------------------
__global__ void __launch_bounds__(256) prefix_kernel()
{
  int h = blockIdx.y;
  int e = blockIdx.x*256 + threadIdx.x;  // 0..16383
  float acc = 0.f;
  for (int j = 0; j <= NB-3; ++j) {
    acc += g_S[((size_t)h*NB + j)*HS*HS + e];
    g_P[((size_t)h*NB + j+2)*HS*HS + e] = acc;
  }
  if (blockIdx.x == 0 && threadIdx.x < HS) {
    float az = 0.f;
    for (int j = 0; j <= NB-3; ++j) {
      az += g_z[((size_t)h*NB + j)*HS + threadIdx.x];
      g_zp[((size_t)h*NB + j+2)*HS + threadIdx.x] = az;
    }
  }
}

// ---------------------------------------------------------------------------
// Kernel 4: main attention via tf32 mma.sync (m16n8k8).
// R15: 512 thr = 16 warps, each 16x32 output tile (mb=w&3, nb=w>>2).
// Same smem (106 KB -> 2 CTAs/SM) => 32 warps/SM, 50% occ ceiling.
// ---------------------------------------------------------------------------
__global__ void __launch_bounds__(512,2) attn_kernel(
    const float* __restrict__ query, const float* __restrict__ key,
    const float* __restrict__ value, const float* __restrict__ wfraw,
    float* __restrict__ out)
{
  extern __shared__ float sm[];
  float* sA   = sm;                 // [64][132]  tf32 Q -> probs -> fq
  float* sB   = sA + 64*PRA;        // [128][136] tf32 K(132) -> V(136) -> P(136)
  float* sRed = sB + 128*PRV;       // [512]
  float* sZp  = sRed + 512;         // [128]
  float* sLn  = sZp + 128;          // [64]

  int b = blockIdx.x, h = blockIdx.y;
  int tid = threadIdx.x;
  int kvh = h >> 2;
  float wf = 1.f/(1.f+__expf(-wfraw[h]));

  int w = tid >> 5, lane = tid & 31;
  int g = lane >> 2, tg = lane & 3;
  int mb = w & 3, nb = w >> 2;
  int mbase = mb*16, nbase = nb*32;

  if (tid < 64) sLn[tid] = 0.f;

  // ---- L1: tf32(Q), tf32(K) n-major; zp ----
  for (int i = tid; i < 64*32; i += 512) {
    int r = i >> 5, d4 = (i & 31)*4;
    float4 v = *(const float4*)&query[(size_t)(b*64+r)*(NH*HS) + h*HS + d4];
    st_tf32_4(&sA[r*PRA+d4], v);
  }
  for (int i = tid; i < 128*32; i += 512) {
    int r = i >> 5, d4 = (i & 31)*4;
    float4 v;
    if (r < 64) {
      if (b == 0) v = make_float4(0.f,0.f,0.f,0.f);
      else v = *(const float4*)&key[(size_t)((b-1)*64+r)*(NKV*HS)+kvh*HS+d4];
    } else {
      v = *(const float4*)&key[(size_t)(b*64+(r-64))*(NKV*HS)+kvh*HS+d4];
    }
    st_tf32_4(&sB[r*PRB+d4], v);
  }
  if (b >= 2 && tid < HS) sZp[tid] = g_zp[((size_t)h*NB+b)*HS+tid];
  __syncthreads();

  // ---- G1: scores = Q @ K^T  (one m-tile, four n-tiles per warp) ----
  float c[4][4];
  #pragma unroll
  for (int nt=0;nt<4;nt++)
    #pragma unroll
    for (int e=0;e<4;e++) c[nt][e]=0.f;

  #pragma unroll 4
  for (int k0=0;k0<128;k0+=8) {
    uint32_t a[4], bb[4][2];
    a[0]=__float_as_uint(sA[(mbase+g)*PRA+k0+tg]);
    a[1]=__float_as_uint(sA[(mbase+g+8)*PRA+k0+tg]);
    a[2]=__float_as_uint(sA[(mbase+g)*PRA+k0+tg+4]);
    a[3]=__float_as_uint(sA[(mbase+g+8)*PRA+k0+tg+4]);
    #pragma unroll
    for (int nt=0;nt<4;nt++){
      int C = nbase+nt*8;
      bb[nt][0]=__float_as_uint(sB[(C+g)*PRB+k0+tg]);
      bb[nt][1]=__float_as_uint(sB[(C+g)*PRB+k0+tg+4]);
    }
    #pragma unroll
    for (int nt=0;nt<4;nt++)
      mma_tf32(c[nt], a[0],a[1],a[2],a[3], bb[nt][0],bb[nt][1]);
  }

  // ---- softmax: band max ----
  #pragma unroll
  for (int half=0;half<2;half++) {
    int r = mbase+half*8+g;
    float mx = -1e30f;
    #pragma unroll
    for (int nt=0;nt<4;nt++)
      #pragma unroll
      for (int e=0;e<2;e++) {
        int col = nbase+nt*8+2*tg+e;
        float s = c[nt][half*2+e]*SCALE;
        c[nt][half*2+e]=s;
        bool ok = (col<64) ? (b>0) : ((col-64)<=r);
        if (ok) mx = fmaxf(mx, s);
      }
    mx = fmaxf(mx, __shfl_xor_sync(0xffffffffu, mx, 1, 4));
    mx = fmaxf(mx, __shfl_xor_sync(0xffffffffu, mx, 2, 4));
    if (tg==0) sRed[r*4+nb]=mx;
  }
  __syncthreads();

  // ---- exp + band sums; probs (tf32) -> sA; tf32(V) -> sB ----
  #pragma unroll
  for (int half=0;half<2;half++) {
    int r = mbase+half*8+g;
    float gm = fmaxf(fmaxf(sRed[r*4+0],sRed[r*4+1]),fmaxf(sRed[r*4+2],sRed[r*4+3]));
    float sum=0.f;
    #pragma unroll
    for (int nt=0;nt<4;nt++){
      int col0 = nbase+nt*8+2*tg;
      bool ok0 = (col0  <64) ? (b>0) : ((col0  -64)<=r);
      bool ok1 = (col0+1<64) ? (b>0) : ((col0+1-64)<=r);
      float p0 = ok0 ? to_tf32(wf*__expf(c[nt][half*2+0]-gm)) : 0.f;
      float p1 = ok1 ? to_tf32(wf*__expf(c[nt][half*2+1]-gm)) : 0.f;
      sum += p0+p1;
      *(float2*)&sA[r*PRA + col0] = make_float2(p0,p1);
    }
    sum += __shfl_xor_sync(0xffffffffu,sum,1,4);
    sum += __shfl_xor_sync(0xffffffffu,sum,2,4);
    if (tg==0) sRed[256 + r*4+nb]=sum;
  }
  for (int i = tid; i < 128*32; i += 512) {
    int r = i >> 5, d4 = (i & 31)*4;
    float4 v;
    if (r < 64) {
      if (b == 0) v = make_float4(0.f,0.f,0.f,0.f);
      else v = *(const float4*)&value[(size_t)((b-1)*64+r)*(NKV*HS)+kvh*HS+d4];
    } else {
      v = *(const float4*)&value[(size_t)(b*64+(r-64))*(NKV*HS)+kvh*HS+d4];
    }
    st_tf32_4(&sB[r*PRV+d4], v);
  }
  #pragma unroll
  for (int nt=0;nt<4;nt++)
    #pragma unroll
    for (int e=0;e<4;e++) c[nt][e]=0.f;
  __syncthreads();

  // ---- G2: y = P @ V ----
  #pragma unroll 4
  for (int k0=0;k0<128;k0+=8) {
    uint32_t a[4], bb[4][2];
    a[0]=__float_as_uint(sA[(mbase+g)*PRA+k0+tg]);
    a[1]=__float_as_uint(sA[(mbase+g+8)*PRA+k0+tg]);
    a[2]=__float_as_uint(sA[(mbase+g)*PRA+k0+tg+4]);
    a[3]=__float_as_uint(sA[(mbase+g+8)*PRA+k0+tg+4]);
    #pragma unroll
    for (int nt=0;nt<4;nt++){
      int C = nbase+nt*8;
      bb[nt][0]=__float_as_uint(sB[(k0+tg  )*PRV + C+g]);
      bb[nt][1]=__float_as_uint(sB[(k0+tg+4)*PRV + C+g]);
    }
    #pragma unroll
    for (int nt=0;nt<4;nt++)
      mma_tf32(c[nt], a[0],a[1],a[2],a[3], bb[nt][0],bb[nt][1]);
  }

  // ---- prefix: y += fq @ P ; sum_ln = fq . zp ----
  if (b >= 2) {
    __syncthreads();
    for (int i = tid; i < 64*32; i += 512) {
      int r = i >> 5, d4 = (i & 31)*4;
      float4 v = *(const float4*)&g_fq[((size_t)h*TT + b*64 + r)*HS + d4];
      st_tf32_4(&sA[r*PRA+d4], v);
    }
    const float* P = g_P + ((size_t)h*NB + b)*HS*HS;   // P[f][d], k-major B
    for (int i = tid; i < 128*32; i += 512) {
      int r = i >> 5, d4 = (i & 31)*4;
      float4 v = *(const float4*)&P[r*HS + d4];
      st_tf32_4(&sB[r*PRV+d4], v);
    }
    __syncthreads();

    #pragma unroll 4
    for (int k0=0;k0<128;k0+=8) {
      uint32_t a[4], bb[4][2];
      a[0]=__float_as_uint(sA[(mbase+g)*PRA+k0+tg]);
      a[1]=__float_as_uint(sA[(mbase+g+8)*PRA+k0+tg]);
      a[2]=__float_as_uint(sA[(mbase+g)*PRA+k0+tg+4]);
      a[3]=__float_as_uint(sA[(mbase+g+8)*PRA+k0+tg+4]);
      #pragma unroll
      for (int nt=0;nt<4;nt++){
        int C = nbase+nt*8;
        bb[nt][0]=__float_as_uint(sB[(k0+tg  )*PRV + C+g]);
        bb[nt][1]=__float_as_uint(sB[(k0+tg+4)*PRV + C+g]);
      }
      #pragma unroll
      for (int nt=0;nt<4;nt++)
        mma_tf32(c[nt], a[0],a[1],a[2],a[3], bb[nt][0],bb[nt][1]);
    }
    if (tid < 64) {
      float s=0.f;
      #pragma unroll 4
      for (int f=0; f<HS; ++f) s += sA[tid*PRA+f]*sZp[f];
      sLn[tid]=s;
    }
  }
  __syncthreads();

  // ---- epilogue ----
  #pragma unroll
  for (int half=0;half<2;half++) {
    int r = mbase+half*8+g;
    float ssm = sRed[256+r*4+0]+sRed[256+r*4+1]+sRed[256+r*4+2]+sRed[256+r*4+3];
    float inv = 1.f/(ssm + sLn[r]);
    #pragma unroll
    for (int nt=0;nt<4;nt++){
      int col0 = nbase+nt*8+2*tg;
      *(float2*)&out[((size_t)h*TT + b*64 + r)*HS + col0] =
        make_float2(c[nt][half*2+0]*inv, c[nt][half*2+1]*inv);
    }
  }
}

// ---------------------------------------------------------------------------
extern "C" void kernel_launch(void* const* d_in, const int* in_sizes, int n_in,
                              void* d_out, int out_size)
{
  const float* q   = (const float*)d_in[0];
  const float* k   = (const float*)d_in[1];
  const float* v   = (const float*)d_in[2];
  const float* fqw = (const float*)d_in[3];
  const float* fkw = (const float*)d_in[4];
  const float* wfr = (const float*)d_in[5];
  float* out = (float*)d_out;

  // smem: featmap_q = 72704 B, fkstate = 73728 B (3 CTAs/SM each)
  // attn = 106240 B -> 2 CTAs/SM, 512 thr -> 32 warps/SM
  cudaFuncSetAttribute(featmap_q_kernel, cudaFuncAttributeMaxDynamicSharedMemorySize, 72704);
  cudaFuncSetAttribute(fkstate_kernel,   cudaFuncAttributeMaxDynamicSharedMemorySize, 73728);
  cudaFuncSetAttribute(attn_kernel,      cudaFuncAttributeMaxDynamicSharedMemorySize, 106240);

  featmap_q_kernel<<<dim3(32,32),256,72704>>>(q, fqw);
  fkstate_kernel  <<<dim3(32,32),256,73728>>>(k, v, fkw);
  prefix_kernel   <<<dim3(64,32),256>>>();
  attn_kernel     <<<dim3(32,32),512,106240>>>(q, k, v, wfr, out);
}